// round 4
// baseline (speedup 1.0000x reference)
#include <cuda_runtime.h>
#include <math.h>
#include <stdint.h>

// ---------------------------------------------------------------------------
// Problem constants: B=2, C=256, H=W=256, SSM=256, NH=16, HD=16, WS=8
// ---------------------------------------------------------------------------
#define PPLANE 65536
#define NBATCH 2

typedef unsigned long long u64;

__device__ float g_local[NBATCH * 256 * PPLANE];
__device__ float g_qkv  [NBATCH * 768 * PPLANE];
__device__ float g_attn [NBATCH * 256 * PPLANE];
__device__ float g_mid  [NBATCH * 256 * PPLANE];
__device__ float g_dw   [NBATCH * 256 * PPLANE];

__device__ float g_inv1[256], g_inv2[256], g_biasc[256], g_invp[256], g_biasp[256];

// ---------------------------------------------------------------------------
// Packed f32x2 helpers (Blackwell dual-width fp32 pipe)
// ---------------------------------------------------------------------------
__device__ __forceinline__ u64 dup2(float x) {
    u64 r;
    uint32_t u = __float_as_uint(x);
    asm("mov.b64 %0, {%1, %1};" : "=l"(r) : "r"(u));
    return r;
}
__device__ __forceinline__ void ffma2(u64& d, u64 a, u64 b) {
    asm("fma.rn.f32x2 %0, %1, %2, %0;" : "+l"(d) : "l"(a), "l"(b));
}
__device__ __forceinline__ u64 fadd2(u64 a, u64 b) {
    u64 d;
    asm("add.rn.f32x2 %0, %1, %2;" : "=l"(d) : "l"(a), "l"(b));
    return d;
}

// ---------------------------------------------------------------------------
// Prep: fold BN params
// ---------------------------------------------------------------------------
__global__ void prep_kernel(const float* __restrict__ g1, const float* __restrict__ b1,
                            const float* __restrict__ m1, const float* __restrict__ v1,
                            const float* __restrict__ g2, const float* __restrict__ b2,
                            const float* __restrict__ m2, const float* __restrict__ v2,
                            const float* __restrict__ gp, const float* __restrict__ bp,
                            const float* __restrict__ mp, const float* __restrict__ vp)
{
    int c = threadIdx.x;
    float i1 = g1[c] * rsqrtf(v1[c] + 1e-5f);
    float i2 = g2[c] * rsqrtf(v2[c] + 1e-5f);
    g_inv1[c] = i1;
    g_inv2[c] = i2;
    g_biasc[c] = (b1[c] - m1[c] * i1) + (b2[c] - m2[c] * i2);
    float ip = gp[c] * rsqrtf(vp[c] + 1e-5f);
    g_invp[c] = ip;
    g_biasp[c] = bp[c] - mp[c] * ip;
}

// ---------------------------------------------------------------------------
// FFMA2 SGEMM, 128x128 tile, K-step 16, register prefetch.
//   C[(b*M + m)*65536 + p] = sum_k A[m*K+k] * B[(b*K + k)*65536 + p]
// Accumulators packed along column pairs (f32x2).
// ---------------------------------------------------------------------------
__global__ __launch_bounds__(256, 2) void gemm_plain(
    const float* __restrict__ A, const float* __restrict__ Bm,
    float* extC, int M, int K, int dst)
{
    __shared__ float As[16 * 128];
    __shared__ float Bs[16 * 128];
    const float* Bsrc = Bm ? Bm : (const float*)g_dw;
    float* C = (dst == 0) ? (float*)g_qkv : extC;

    int tid = threadIdx.x;
    int pg0 = blockIdx.x * 128;
    int b   = pg0 >> 16;
    int p0  = pg0 & 65535;
    int m0  = blockIdx.y * 128;

    int ty = tid >> 4, tx = tid & 15;

    int am = tid >> 1;
    int ak = (tid & 1) * 8;
    const float* Abase = A + (size_t)(m0 + am) * K + ak;
    int bk = tid >> 4;
    int bn = (tid & 15) * 8;
    const float* Bbase = Bsrc + ((size_t)(b * K + bk) << 16) + p0 + bn;

    u64 acc[8][4];
#pragma unroll
    for (int i = 0; i < 8; ++i)
#pragma unroll
        for (int j = 0; j < 4; ++j) acc[i][j] = 0ULL;

    // prefetch first tile
    float4 a0 = *(const float4*)Abase;
    float4 a1 = *(const float4*)(Abase + 4);
    float4 b0 = *(const float4*)Bbase;
    float4 b1 = *(const float4*)(Bbase + 4);

    for (int k0 = 0; k0 < K; k0 += 16) {
        As[(ak + 0) * 128 + am] = a0.x;
        As[(ak + 1) * 128 + am] = a0.y;
        As[(ak + 2) * 128 + am] = a0.z;
        As[(ak + 3) * 128 + am] = a0.w;
        As[(ak + 4) * 128 + am] = a1.x;
        As[(ak + 5) * 128 + am] = a1.y;
        As[(ak + 6) * 128 + am] = a1.z;
        As[(ak + 7) * 128 + am] = a1.w;
        *(float4*)&Bs[bk * 128 + bn]     = b0;
        *(float4*)&Bs[bk * 128 + bn + 4] = b1;
        __syncthreads();

        if (k0 + 16 < K) {
            a0 = *(const float4*)(Abase + k0 + 16);
            a1 = *(const float4*)(Abase + k0 + 20);
            const float* bp = Bbase + ((size_t)(k0 + 16) << 16);
            b0 = *(const float4*)bp;
            b1 = *(const float4*)(bp + 4);
        }

#pragma unroll
        for (int kk = 0; kk < 16; ++kk) {
            float4 A0 = *(const float4*)&As[kk * 128 + ty * 8];
            float4 A1 = *(const float4*)&As[kk * 128 + ty * 8 + 4];
            ulonglong2 B0 = *(const ulonglong2*)&Bs[kk * 128 + tx * 8];
            ulonglong2 B1 = *(const ulonglong2*)&Bs[kk * 128 + tx * 8 + 4];
            u64 bv[4] = { B0.x, B0.y, B1.x, B1.y };
            u64 ad[8] = { dup2(A0.x), dup2(A0.y), dup2(A0.z), dup2(A0.w),
                          dup2(A1.x), dup2(A1.y), dup2(A1.z), dup2(A1.w) };
#pragma unroll
            for (int i = 0; i < 8; ++i)
#pragma unroll
                for (int j = 0; j < 4; ++j) ffma2(acc[i][j], ad[i], bv[j]);
        }
        __syncthreads();
    }
#pragma unroll
    for (int i = 0; i < 8; ++i) {
        size_t row = ((size_t)(b * M + m0 + ty * 8 + i) << 16) + p0 + tx * 8;
        *(ulonglong2*)&C[row]     = make_ulonglong2(acc[i][0], acc[i][1]);
        *(ulonglong2*)&C[row + 4] = make_ulonglong2(acc[i][2], acc[i][3]);
    }
}

// ---------------------------------------------------------------------------
// Fused local branch: BN2(conv1x1(y,w2)) + BN1(conv3x3(y,w1)) as one implicit
// GEMM, K = 2304 + 256 = 2560, FFMA2 inner product.
// ---------------------------------------------------------------------------
__global__ __launch_bounds__(256, 2) void gemm_local(
    const float* __restrict__ w1, const float* __restrict__ w2,
    const float* __restrict__ y)
{
    __shared__ float As[16 * 128];
    __shared__ float Bs[16 * 128];

    int tid = threadIdx.x;
    int pg0 = blockIdx.x * 128;
    int b   = pg0 >> 16;
    int p0  = pg0 & 65535;
    int m0  = blockIdx.y * 128;
    int h   = p0 >> 8;
    int w0  = p0 & 255;

    int ty = tid >> 4, tx = tid & 15;

    int am = tid >> 1;
    int ak = (tid & 1) * 8;
    int mg = m0 + am;
    float s1 = g_inv1[mg];
    float s2 = g_inv2[mg];

    int bk = tid >> 4;
    int bn = (tid & 15) * 8;

    u64 acc[8][4];
#pragma unroll
    for (int i = 0; i < 8; ++i)
#pragma unroll
        for (int j = 0; j < 4; ++j) acc[i][j] = 0ULL;

    float areg[8], breg[8];
    auto loadA = [&](int k0) {
        int k = k0 + ak;
        const float* ap;
        float sc;
        if (k < 2304) { ap = w1 + (size_t)mg * 2304 + k; sc = s1; }
        else          { ap = w2 + (size_t)mg * 256 + (k - 2304); sc = s2; }
        float4 t0 = *(const float4*)ap;
        float4 t1 = *(const float4*)(ap + 4);
        areg[0]=t0.x*sc; areg[1]=t0.y*sc; areg[2]=t0.z*sc; areg[3]=t0.w*sc;
        areg[4]=t1.x*sc; areg[5]=t1.y*sc; areg[6]=t1.z*sc; areg[7]=t1.w*sc;
    };
    auto loadB = [&](int k0) {
        int k = k0 + bk;
        int ci, dy, dx;
        if (k < 2304) {
            ci = k / 9;
            int tap = k - ci * 9;
            int r = tap / 3;
            dy = r - 1;
            dx = tap - r * 3 - 1;
        } else {
            ci = k - 2304; dy = 0; dx = 0;
        }
        int hh = h + dy;
        bool hok = (hh >= 0) && (hh < 256);
        const float* row = y + ((size_t)(b * 256 + ci) << 16) + hh * 256;
#pragma unroll
        for (int j = 0; j < 8; ++j) {
            int ww = w0 + bn + j + dx;
            breg[j] = (hok && ww >= 0 && ww < 256) ? row[ww] : 0.f;
        }
    };

    loadA(0);
    loadB(0);

    for (int k0 = 0; k0 < 2560; k0 += 16) {
#pragma unroll
        for (int j = 0; j < 8; ++j) As[(ak + j) * 128 + am] = areg[j];
#pragma unroll
        for (int j = 0; j < 8; ++j) Bs[bk * 128 + bn + j] = breg[j];
        __syncthreads();

        if (k0 + 16 < 2560) { loadA(k0 + 16); loadB(k0 + 16); }

#pragma unroll
        for (int kk = 0; kk < 16; ++kk) {
            float4 A0 = *(const float4*)&As[kk * 128 + ty * 8];
            float4 A1 = *(const float4*)&As[kk * 128 + ty * 8 + 4];
            ulonglong2 B0 = *(const ulonglong2*)&Bs[kk * 128 + tx * 8];
            ulonglong2 B1 = *(const ulonglong2*)&Bs[kk * 128 + tx * 8 + 4];
            u64 bv[4] = { B0.x, B0.y, B1.x, B1.y };
            u64 ad[8] = { dup2(A0.x), dup2(A0.y), dup2(A0.z), dup2(A0.w),
                          dup2(A1.x), dup2(A1.y), dup2(A1.z), dup2(A1.w) };
#pragma unroll
            for (int i = 0; i < 8; ++i)
#pragma unroll
                for (int j = 0; j < 4; ++j) ffma2(acc[i][j], ad[i], bv[j]);
        }
        __syncthreads();
    }
#pragma unroll
    for (int i = 0; i < 8; ++i) {
        int m = m0 + ty * 8 + i;
        u64 bd = dup2(g_biasc[m]);
        size_t row = ((size_t)(b * 256 + m) << 16) + p0 + tx * 8;
        *(ulonglong2*)&g_local[row] =
            make_ulonglong2(fadd2(acc[i][0], bd), fadd2(acc[i][1], bd));
        *(ulonglong2*)&g_local[row + 4] =
            make_ulonglong2(fadd2(acc[i][2], bd), fadd2(acc[i][3], bd));
    }
}

// ---------------------------------------------------------------------------
// Windowed attention, online softmax; 4 (window,head) units per block.
// ---------------------------------------------------------------------------
__global__ __launch_bounds__(256) void attn_kernel(const float* __restrict__ rpb)
{
    int win  = blockIdx.x;
    int hq   = threadIdx.y;
    int head = blockIdx.y * 4 + hq;
    int b  = win >> 10;
    int wy = (win >> 5) & 31;
    int wx = win & 31;
    int i  = threadIdx.x;
    int yi = i >> 3, xi = i & 7;
    int p  = ((wy * 8 + yi) << 8) + wx * 8 + xi;

    __shared__ float ks[4][64][16];
    __shared__ float vs[4][64][16];
    __shared__ float rpbs[4][225];

    for (int t = i; t < 225; t += 64) rpbs[hq][t] = rpb[t * 16 + head];

    size_t base = ((size_t)(b * 768 + head * 16) << 16) + p;
    float q[16];
#pragma unroll
    for (int d = 0; d < 16; ++d) {
        q[d]         = g_qkv[base + ((size_t)d << 16)] * 0.25f;
        ks[hq][i][d] = g_qkv[base + ((size_t)(256 + d) << 16)];
        vs[hq][i][d] = g_qkv[base + ((size_t)(512 + d) << 16)];
    }
    __syncthreads();

    float m_run = -1e30f, l_run = 0.f;
    float o[16];
#pragma unroll
    for (int d = 0; d < 16; ++d) o[d] = 0.f;

#pragma unroll
    for (int cchunk = 0; cchunk < 4; ++cchunk) {
        float s[16];
        float cm = -1e30f;
#pragma unroll
        for (int jj = 0; jj < 16; ++jj) {
            int j = cchunk * 16 + jj;
            const float4* kp = (const float4*)ks[hq][j];
            float4 k0 = kp[0], k1 = kp[1], k2 = kp[2], k3 = kp[3];
            float acc = q[0] * k0.x + q[1] * k0.y + q[2] * k0.z + q[3] * k0.w
                      + q[4] * k1.x + q[5] * k1.y + q[6] * k1.z + q[7] * k1.w
                      + q[8] * k2.x + q[9] * k2.y + q[10] * k2.z + q[11] * k2.w
                      + q[12] * k3.x + q[13] * k3.y + q[14] * k3.z + q[15] * k3.w;
            int yj = j >> 3, xj = j & 7;
            acc += rpbs[hq][(yi - yj + 7) * 15 + (xi - xj + 7)];
            s[jj] = acc;
            cm = fmaxf(cm, acc);
        }
        float mnew = fmaxf(m_run, cm);
        float corr = __expf(m_run - mnew);
        l_run *= corr;
#pragma unroll
        for (int d = 0; d < 16; ++d) o[d] *= corr;
#pragma unroll
        for (int jj = 0; jj < 16; ++jj) {
            int j = cchunk * 16 + jj;
            float pj = __expf(s[jj] - mnew);
            l_run += pj;
            const float4* vp = (const float4*)vs[hq][j];
            float4 v0 = vp[0], v1 = vp[1], v2 = vp[2], v3 = vp[3];
            o[0]  += pj * v0.x; o[1]  += pj * v0.y; o[2]  += pj * v0.z; o[3]  += pj * v0.w;
            o[4]  += pj * v1.x; o[5]  += pj * v1.y; o[6]  += pj * v1.z; o[7]  += pj * v1.w;
            o[8]  += pj * v2.x; o[9]  += pj * v2.y; o[10] += pj * v2.z; o[11] += pj * v2.w;
            o[12] += pj * v3.x; o[13] += pj * v3.y; o[14] += pj * v3.z; o[15] += pj * v3.w;
        }
        m_run = mnew;
    }
    float inv = 1.f / l_run;
#pragma unroll
    for (int d = 0; d < 16; ++d)
        g_attn[((size_t)(b * 256 + head * 16 + d) << 16) + p] = o[d] * inv;
}

// ---------------------------------------------------------------------------
// mid = avgpool_v(attn) + avgpool_h(attn) + local
// ---------------------------------------------------------------------------
__global__ void pool_add_kernel()
{
    int bc = blockIdx.x >> 8;
    int h  = blockIdx.x & 255;
    int w  = threadIdx.x;
    const float* plane = g_attn + ((size_t)bc << 16);

    float sx = 0.f;
#pragma unroll
    for (int t = h - 3; t <= h + 4; ++t) {
        if (t >= 0 && t <= 256) {
            int tt = (t == 256) ? 254 : t;
            sx += plane[tt * 256 + w];
        }
    }
    const float* row = plane + h * 256;
    float sy = 0.f;
#pragma unroll
    for (int t = w - 3; t <= w + 4; ++t) {
        if (t >= 0 && t <= 256) {
            int tt = (t == 256) ? 254 : t;
            sy += row[tt];
        }
    }
    size_t idx = ((size_t)bc << 16) + h * 256 + w;
    g_mid[idx] = (sx + sy) * 0.125f + g_local[idx];
}

// ---------------------------------------------------------------------------
// Depthwise 8x8 conv + BN
// ---------------------------------------------------------------------------
__global__ __launch_bounds__(256) void dwconv_kernel(const float* __restrict__ w_dw)
{
    __shared__ float tile[39 * 40];
    __shared__ float ws[64];

    int tix = blockIdx.x;
    int bc  = blockIdx.y;
    int c   = bc & 255;
    int ty0 = (tix >> 3) * 32;
    int tx0 = (tix & 7) * 32;
    int tid = threadIdx.x;

    const float* plane = g_mid + ((size_t)bc << 16);

    for (int idx = tid; idx < 39 * 39; idx += 256) {
        int r  = idx / 39;
        int cc = idx - r * 39;
        int gh = ty0 - 3 + r;
        int gw = tx0 - 3 + cc;
        float v = 0.f;
        if (gh >= 0 && gh <= 256 && gw >= 0 && gw <= 256) {
            int ih = (gh == 256) ? 254 : gh;
            int iw = (gw == 256) ? 254 : gw;
            v = plane[ih * 256 + iw];
        }
        tile[r * 40 + cc] = v;
    }
    if (tid < 64) ws[tid] = w_dw[c * 64 + tid];
    __syncthreads();

    int lw  = tid & 31;
    int lh0 = (tid >> 5) * 4;
    float acc[4] = {0.f, 0.f, 0.f, 0.f};
#pragma unroll
    for (int j = 0; j < 8; ++j) {
        float wcol[8];
#pragma unroll
        for (int i = 0; i < 8; ++i) wcol[i] = ws[i * 8 + j];
#pragma unroll
        for (int r = 0; r < 11; ++r) {
            float v = tile[(lh0 + r) * 40 + lw + j];
#pragma unroll
            for (int a = 0; a < 4; ++a) {
                int i = r - a;
                if (i >= 0 && i < 8) acc[a] += v * wcol[i];
            }
        }
    }
    float ip = g_invp[c];
    float bb = g_biasp[c];
#pragma unroll
    for (int a = 0; a < 4; ++a) {
        int h = ty0 + lh0 + a;
        g_dw[((size_t)bc << 16) + h * 256 + tx0 + lw] = acc[a] * ip + bb;
    }
}

// ---------------------------------------------------------------------------
// Launch
// ---------------------------------------------------------------------------
extern "C" void kernel_launch(void* const* d_in, const int* in_sizes, int n_in,
                              void* d_out, int out_size)
{
    const float* x    = (const float*)d_in[0];
    const float* y    = (const float*)d_in[1];
    const float* wqkv = (const float*)d_in[2];
    const float* wl1  = (const float*)d_in[3];
    const float* g1   = (const float*)d_in[4];
    const float* b1   = (const float*)d_in[5];
    const float* m1   = (const float*)d_in[6];
    const float* v1   = (const float*)d_in[7];
    const float* wl2  = (const float*)d_in[8];
    const float* g2   = (const float*)d_in[9];
    const float* b2   = (const float*)d_in[10];
    const float* m2   = (const float*)d_in[11];
    const float* v2   = (const float*)d_in[12];
    const float* wdw  = (const float*)d_in[13];
    const float* gp   = (const float*)d_in[14];
    const float* bp   = (const float*)d_in[15];
    const float* mp   = (const float*)d_in[16];
    const float* vp   = (const float*)d_in[17];
    const float* wpw  = (const float*)d_in[18];
    const float* rpb  = (const float*)d_in[19];
    float* out = (float*)d_out;

    prep_kernel<<<1, 256>>>(g1, b1, m1, v1, g2, b2, m2, v2, gp, bp, mp, vp);

    gemm_local<<<dim3(1024, 2), 256>>>(wl1, wl2, y);

    gemm_plain<<<dim3(1024, 6), 256>>>(wqkv, x, nullptr, 768, 256, 0);

    attn_kernel<<<dim3(2048, 4), dim3(64, 4)>>>(rpb);

    pool_add_kernel<<<512 * 256, 256>>>();

    dwconv_kernel<<<dim3(64, 512), 256>>>(wdw);

    gemm_plain<<<dim3(1024, 2), 256>>>(wpw, nullptr, out, 256, 256, 1);
}

// round 5
// speedup vs baseline: 1.8677x; 1.8677x over previous
#include <cuda_runtime.h>
#include <cuda_bf16.h>
#include <math.h>
#include <stdint.h>

// ---------------------------------------------------------------------------
// Problem constants: B=2, C=256, H=W=256, SSM=256, NH=16, HD=16, WS=8
// ---------------------------------------------------------------------------
#define PPLANE 65536
#define NBATCH 2

__device__ float g_local[NBATCH * 256 * PPLANE];
__device__ float g_qkv  [NBATCH * 768 * PPLANE];
__device__ float g_attn [NBATCH * 256 * PPLANE];
__device__ float g_mid  [NBATCH * 256 * PPLANE];
__device__ float g_dw   [NBATCH * 256 * PPLANE];

__device__ float g_inv1[256], g_inv2[256], g_biasc[256], g_invp[256], g_biasp[256];

// ---------------------------------------------------------------------------
// bf16 split + mma + ldmatrix helpers
// ---------------------------------------------------------------------------
__device__ __forceinline__ uint32_t smem_u32(const void* p) {
    uint32_t a;
    asm("{ .reg .u64 t; cvta.to.shared.u64 t, %1; cvt.u32.u64 %0, t; }"
        : "=r"(a) : "l"(p));
    return a;
}
__device__ __forceinline__ uint32_t pkbf(float a, float b) {
    __nv_bfloat162 t = __floats2bfloat162_rn(a, b);
    return *reinterpret_cast<uint32_t*>(&t);
}
__device__ __forceinline__ float bfh(float x) {
    return __bfloat162float(__float2bfloat16_rn(x));
}
// split 8 floats into hi/lo bf16 packs (4 u32 each)
__device__ __forceinline__ void split8(const float* v, uint4& hi, uint4& lo) {
    float h0 = bfh(v[0]), h1 = bfh(v[1]), h2 = bfh(v[2]), h3 = bfh(v[3]);
    float h4 = bfh(v[4]), h5 = bfh(v[5]), h6 = bfh(v[6]), h7 = bfh(v[7]);
    hi = make_uint4(pkbf(v[0], v[1]), pkbf(v[2], v[3]), pkbf(v[4], v[5]), pkbf(v[6], v[7]));
    lo = make_uint4(pkbf(v[0]-h0, v[1]-h1), pkbf(v[2]-h2, v[3]-h3),
                    pkbf(v[4]-h4, v[5]-h5), pkbf(v[6]-h6, v[7]-h7));
}
__device__ __forceinline__ void ldsm4(uint32_t* r, uint32_t a) {
    asm volatile("ldmatrix.sync.aligned.m8n8.x4.shared.b16 {%0,%1,%2,%3},[%4];"
                 : "=r"(r[0]), "=r"(r[1]), "=r"(r[2]), "=r"(r[3]) : "r"(a));
}
__device__ __forceinline__ void ldsm4t(uint32_t* r, uint32_t a) {
    asm volatile("ldmatrix.sync.aligned.m8n8.x4.trans.shared.b16 {%0,%1,%2,%3},[%4];"
                 : "=r"(r[0]), "=r"(r[1]), "=r"(r[2]), "=r"(r[3]) : "r"(a));
}
__device__ __forceinline__ void mma16(float* c, const uint32_t* a, const uint32_t* b) {
    asm volatile(
        "mma.sync.aligned.m16n8k16.row.col.f32.bf16.bf16.f32 "
        "{%0,%1,%2,%3},{%4,%5,%6,%7},{%8,%9},{%0,%1,%2,%3};"
        : "+f"(c[0]), "+f"(c[1]), "+f"(c[2]), "+f"(c[3])
        : "r"(a[0]), "r"(a[1]), "r"(a[2]), "r"(a[3]), "r"(b[0]), "r"(b[1]));
}

// smem strides (bytes): A rows (m) hold 16 bf16 (32B) padded to 48B.
// B rows (k) hold 128 bf16 (256B) padded to 272B.
#define ASTRIDE 48
#define BSTRIDE 272

// ---------------------------------------------------------------------------
// Prep: fold BN params
// ---------------------------------------------------------------------------
__global__ void prep_kernel(const float* __restrict__ g1, const float* __restrict__ b1,
                            const float* __restrict__ m1, const float* __restrict__ v1,
                            const float* __restrict__ g2, const float* __restrict__ b2,
                            const float* __restrict__ m2, const float* __restrict__ v2,
                            const float* __restrict__ gp, const float* __restrict__ bp,
                            const float* __restrict__ mp, const float* __restrict__ vp)
{
    int c = threadIdx.x;
    float i1 = g1[c] * rsqrtf(v1[c] + 1e-5f);
    float i2 = g2[c] * rsqrtf(v2[c] + 1e-5f);
    g_inv1[c] = i1;
    g_inv2[c] = i2;
    g_biasc[c] = (b1[c] - m1[c] * i1) + (b2[c] - m2[c] * i2);
    float ip = gp[c] * rsqrtf(vp[c] + 1e-5f);
    g_invp[c] = ip;
    g_biasp[c] = bp[c] - mp[c] * ip;
}

// ---------------------------------------------------------------------------
// Consumer: one K=16 step. A-frags via ldmatrix.x4, B-frags via ldmatrix.x4.trans.
// 3-pass split-bf16: hi*hi + hi*lo + lo*hi.
// ---------------------------------------------------------------------------
__device__ __forceinline__ void mma_step(
    uint32_t sAh, uint32_t sAl, uint32_t sBh, uint32_t sBl,
    int wm, int wn, int lane, float acc[4][4][4])
{
    int t  = lane >> 3;
    int r8 = lane & 7;
    // B addresses: row = (t>>1)*8 + r8 (k), col = wn + ng*16 + (t&1)*8 (n)
    uint32_t bh[4][2], bl[4][2];
#pragma unroll
    for (int ng = 0; ng < 2; ++ng) {
        uint32_t addr = ((t >> 1) * 8 + r8) * BSTRIDE + (wn + ng * 16 + (t & 1) * 8) * 2;
        uint32_t tb[4];
        ldsm4t(tb, sBh + addr);
        bh[ng * 2 + 0][0] = tb[0]; bh[ng * 2 + 0][1] = tb[2];
        bh[ng * 2 + 1][0] = tb[1]; bh[ng * 2 + 1][1] = tb[3];
        ldsm4t(tb, sBl + addr);
        bl[ng * 2 + 0][0] = tb[0]; bl[ng * 2 + 0][1] = tb[2];
        bl[ng * 2 + 1][0] = tb[1]; bl[ng * 2 + 1][1] = tb[3];
    }
    // A addresses: row = wm + mt*16 + (t&1)*8 + r8, kofs = (t>>1)*16B
    uint32_t abase = ((t & 1) * 8 + r8) * ASTRIDE + (t >> 1) * 16;
#pragma unroll
    for (int mt = 0; mt < 4; ++mt) {
        uint32_t arow = abase + (wm + mt * 16) * ASTRIDE;
        uint32_t ah[4], al[4];
        ldsm4(ah, sAh + arow);
#pragma unroll
        for (int j = 0; j < 4; ++j) mma16(acc[mt][j], ah, bh[j]);
#pragma unroll
        for (int j = 0; j < 4; ++j) mma16(acc[mt][j], ah, bl[j]);
        ldsm4(al, sAl + arow);
#pragma unroll
        for (int j = 0; j < 4; ++j) mma16(acc[mt][j], al, bh[j]);
    }
}

// ---------------------------------------------------------------------------
// Plain GEMM: C[(b*M+m)<<16 + p] = sum_k A[m*K+k] * B[(b*K+k)<<16 + p]
// ---------------------------------------------------------------------------
__global__ __launch_bounds__(256, 2) void gemm_bf16(
    const float* __restrict__ A, const float* __restrict__ Bm,
    float* extC, int M, int K, int dst)
{
    __shared__ __align__(16) char Ah[128 * ASTRIDE];
    __shared__ __align__(16) char Al[128 * ASTRIDE];
    __shared__ __align__(16) char Bh[16 * BSTRIDE];
    __shared__ __align__(16) char Bl[16 * BSTRIDE];

    const float* Bsrc = Bm ? Bm : (const float*)g_dw;
    float* C = (dst == 0) ? (float*)g_qkv : extC;

    int tid = threadIdx.x;
    int pg0 = blockIdx.x * 128;
    int b   = pg0 >> 16;
    int p0  = pg0 & 65535;
    int m0  = blockIdx.y * 128;
    int lane = tid & 31, warp = tid >> 5;
    int wm = (warp >> 2) * 64, wn = (warp & 3) * 32;

    uint32_t sAh = smem_u32(Ah), sAl = smem_u32(Al);
    uint32_t sBh = smem_u32(Bh), sBl = smem_u32(Bl);

    int am = tid >> 1, ak = (tid & 1) * 8;
    const float* Abase = A + (size_t)(m0 + am) * K + ak;
    int bk = tid >> 4, bn = (tid & 15) * 8;
    const float* Bbase = Bsrc + ((size_t)(b * K + bk) << 16) + p0 + bn;

    char* Aph = Ah + am * ASTRIDE + ak * 2;
    char* Apl = Al + am * ASTRIDE + ak * 2;
    char* Bph = Bh + bk * BSTRIDE + bn * 2;
    char* Bpl = Bl + bk * BSTRIDE + bn * 2;

    float acc[4][4][4];
#pragma unroll
    for (int i = 0; i < 4; ++i)
#pragma unroll
        for (int j = 0; j < 4; ++j)
#pragma unroll
            for (int r = 0; r < 4; ++r) acc[i][j][r] = 0.f;

    float ar[8], br[8];
    {
        float4 t0 = *(const float4*)Abase;
        float4 t1 = *(const float4*)(Abase + 4);
        ar[0]=t0.x; ar[1]=t0.y; ar[2]=t0.z; ar[3]=t0.w;
        ar[4]=t1.x; ar[5]=t1.y; ar[6]=t1.z; ar[7]=t1.w;
        float4 u0 = *(const float4*)Bbase;
        float4 u1 = *(const float4*)(Bbase + 4);
        br[0]=u0.x; br[1]=u0.y; br[2]=u0.z; br[3]=u0.w;
        br[4]=u1.x; br[5]=u1.y; br[6]=u1.z; br[7]=u1.w;
    }

    for (int k0 = 0; k0 < K; k0 += 16) {
        uint4 hi, lo;
        split8(ar, hi, lo);
        *(uint4*)Aph = hi;
        *(uint4*)Apl = lo;
        split8(br, hi, lo);
        *(uint4*)Bph = hi;
        *(uint4*)Bpl = lo;
        __syncthreads();

        if (k0 + 16 < K) {
            float4 t0 = *(const float4*)(Abase + k0 + 16);
            float4 t1 = *(const float4*)(Abase + k0 + 20);
            ar[0]=t0.x; ar[1]=t0.y; ar[2]=t0.z; ar[3]=t0.w;
            ar[4]=t1.x; ar[5]=t1.y; ar[6]=t1.z; ar[7]=t1.w;
            const float* bp = Bbase + ((size_t)(k0 + 16) << 16);
            float4 u0 = *(const float4*)bp;
            float4 u1 = *(const float4*)(bp + 4);
            br[0]=u0.x; br[1]=u0.y; br[2]=u0.z; br[3]=u0.w;
            br[4]=u1.x; br[5]=u1.y; br[6]=u1.z; br[7]=u1.w;
        }

        mma_step(sAh, sAl, sBh, sBl, wm, wn, lane, acc);
        __syncthreads();
    }

    int g = lane >> 2, tig = lane & 3;
#pragma unroll
    for (int mt = 0; mt < 4; ++mt) {
        int r0 = m0 + wm + mt * 16 + g;
#pragma unroll
        for (int j = 0; j < 4; ++j) {
            int col = p0 + wn + j * 8 + tig * 2;
            size_t i0 = ((size_t)(b * M + r0) << 16) + col;
            size_t i1 = ((size_t)(b * M + r0 + 8) << 16) + col;
            *(float2*)&C[i0] = make_float2(acc[mt][j][0], acc[mt][j][1]);
            *(float2*)&C[i1] = make_float2(acc[mt][j][2], acc[mt][j][3]);
        }
    }
}

// ---------------------------------------------------------------------------
// Fused local branch: BN1(conv3x3) + BN2(conv1x1) implicit GEMM, K=2560.
// ---------------------------------------------------------------------------
__global__ __launch_bounds__(256, 2) void gemm_local_bf16(
    const float* __restrict__ w1, const float* __restrict__ w2,
    const float* __restrict__ y)
{
    __shared__ __align__(16) char Ah[128 * ASTRIDE];
    __shared__ __align__(16) char Al[128 * ASTRIDE];
    __shared__ __align__(16) char Bh[16 * BSTRIDE];
    __shared__ __align__(16) char Bl[16 * BSTRIDE];

    int tid = threadIdx.x;
    int pg0 = blockIdx.x * 128;
    int b   = pg0 >> 16;
    int p0  = pg0 & 65535;
    int m0  = blockIdx.y * 128;
    int h   = p0 >> 8;
    int w0  = p0 & 255;
    int lane = tid & 31, warp = tid >> 5;
    int wm = (warp >> 2) * 64, wn = (warp & 3) * 32;

    uint32_t sAh = smem_u32(Ah), sAl = smem_u32(Al);
    uint32_t sBh = smem_u32(Bh), sBl = smem_u32(Bl);

    int am = tid >> 1, ak = (tid & 1) * 8;
    int mg = m0 + am;
    float s1 = g_inv1[mg];
    float s2 = g_inv2[mg];
    int bk = tid >> 4, bn = (tid & 15) * 8;

    char* Aph = Ah + am * ASTRIDE + ak * 2;
    char* Apl = Al + am * ASTRIDE + ak * 2;
    char* Bph = Bh + bk * BSTRIDE + bn * 2;
    char* Bpl = Bl + bk * BSTRIDE + bn * 2;

    float acc[4][4][4];
#pragma unroll
    for (int i = 0; i < 4; ++i)
#pragma unroll
        for (int j = 0; j < 4; ++j)
#pragma unroll
            for (int r = 0; r < 4; ++r) acc[i][j][r] = 0.f;

    float ar[8], br[8];
    auto loadA = [&](int k0) {
        int k = k0 + ak;
        const float* ap;
        float sc;
        if (k < 2304) { ap = w1 + (size_t)mg * 2304 + k; sc = s1; }
        else          { ap = w2 + (size_t)mg * 256 + (k - 2304); sc = s2; }
        float4 t0 = *(const float4*)ap;
        float4 t1 = *(const float4*)(ap + 4);
        ar[0]=t0.x*sc; ar[1]=t0.y*sc; ar[2]=t0.z*sc; ar[3]=t0.w*sc;
        ar[4]=t1.x*sc; ar[5]=t1.y*sc; ar[6]=t1.z*sc; ar[7]=t1.w*sc;
    };
    auto loadB = [&](int k0) {
        int k = k0 + bk;
        int ci, dy, dx;
        if (k < 2304) {
            ci = k / 9;
            int tap = k - ci * 9;
            int r = tap / 3;
            dy = r - 1;
            dx = tap - r * 3 - 1;
        } else {
            ci = k - 2304; dy = 0; dx = 0;
        }
        int hh = h + dy;
        bool hok = (hh >= 0) && (hh < 256);
        const float* row = y + ((size_t)(b * 256 + ci) << 16) + hh * 256;
#pragma unroll
        for (int j = 0; j < 8; ++j) {
            int ww = w0 + bn + j + dx;
            br[j] = (hok && ww >= 0 && ww < 256) ? row[ww] : 0.f;
        }
    };

    loadA(0);
    loadB(0);

    for (int k0 = 0; k0 < 2560; k0 += 16) {
        uint4 hi, lo;
        split8(ar, hi, lo);
        *(uint4*)Aph = hi;
        *(uint4*)Apl = lo;
        split8(br, hi, lo);
        *(uint4*)Bph = hi;
        *(uint4*)Bpl = lo;
        __syncthreads();

        if (k0 + 16 < 2560) { loadA(k0 + 16); loadB(k0 + 16); }

        mma_step(sAh, sAl, sBh, sBl, wm, wn, lane, acc);
        __syncthreads();
    }

    int g = lane >> 2, tig = lane & 3;
#pragma unroll
    for (int mt = 0; mt < 4; ++mt) {
        int r0 = m0 + wm + mt * 16 + g;
        float bi0 = g_biasc[r0];
        float bi1 = g_biasc[r0 + 8];
#pragma unroll
        for (int j = 0; j < 4; ++j) {
            int col = p0 + wn + j * 8 + tig * 2;
            size_t i0 = ((size_t)(b * 256 + r0) << 16) + col;
            size_t i1 = ((size_t)(b * 256 + r0 + 8) << 16) + col;
            *(float2*)&g_local[i0] = make_float2(acc[mt][j][0] + bi0, acc[mt][j][1] + bi0);
            *(float2*)&g_local[i1] = make_float2(acc[mt][j][2] + bi1, acc[mt][j][3] + bi1);
        }
    }
}

// ---------------------------------------------------------------------------
// Windowed attention, online softmax (round-2 config: 64-thread blocks).
// ---------------------------------------------------------------------------
__global__ __launch_bounds__(64) void attn_kernel(const float* __restrict__ rpb)
{
    int win  = blockIdx.x;
    int head = blockIdx.y;
    int b  = win >> 10;
    int wy = (win >> 5) & 31;
    int wx = win & 31;
    int i  = threadIdx.x;
    int yi = i >> 3, xi = i & 7;
    int p  = ((wy * 8 + yi) << 8) + wx * 8 + xi;

    __shared__ float ks[64][16];
    __shared__ float vs[64][16];
    __shared__ float rpbs[225];

    for (int t = i; t < 225; t += 64) rpbs[t] = rpb[t * 16 + head];

    size_t base = ((size_t)(b * 768 + head * 16) << 16) + p;
    float q[16];
#pragma unroll
    for (int d = 0; d < 16; ++d) {
        q[d]     = g_qkv[base + ((size_t)d << 16)] * 0.25f;
        ks[i][d] = g_qkv[base + ((size_t)(256 + d) << 16)];
        vs[i][d] = g_qkv[base + ((size_t)(512 + d) << 16)];
    }
    __syncthreads();

    float m_run = -1e30f, l_run = 0.f;
    float o[16];
#pragma unroll
    for (int d = 0; d < 16; ++d) o[d] = 0.f;

#pragma unroll
    for (int cchunk = 0; cchunk < 4; ++cchunk) {
        float s[16];
        float cm = -1e30f;
#pragma unroll
        for (int jj = 0; jj < 16; ++jj) {
            int j = cchunk * 16 + jj;
            const float4* kp = (const float4*)ks[j];
            float4 k0 = kp[0], k1 = kp[1], k2 = kp[2], k3 = kp[3];
            float acc = q[0] * k0.x + q[1] * k0.y + q[2] * k0.z + q[3] * k0.w
                      + q[4] * k1.x + q[5] * k1.y + q[6] * k1.z + q[7] * k1.w
                      + q[8] * k2.x + q[9] * k2.y + q[10] * k2.z + q[11] * k2.w
                      + q[12] * k3.x + q[13] * k3.y + q[14] * k3.z + q[15] * k3.w;
            int yj = j >> 3, xj = j & 7;
            acc += rpbs[(yi - yj + 7) * 15 + (xi - xj + 7)];
            s[jj] = acc;
            cm = fmaxf(cm, acc);
        }
        float mnew = fmaxf(m_run, cm);
        float corr = __expf(m_run - mnew);
        l_run *= corr;
#pragma unroll
        for (int d = 0; d < 16; ++d) o[d] *= corr;
#pragma unroll
        for (int jj = 0; jj < 16; ++jj) {
            int j = cchunk * 16 + jj;
            float pj = __expf(s[jj] - mnew);
            l_run += pj;
            const float4* vp = (const float4*)vs[j];
            float4 v0 = vp[0], v1 = vp[1], v2 = vp[2], v3 = vp[3];
            o[0]  += pj * v0.x; o[1]  += pj * v0.y; o[2]  += pj * v0.z; o[3]  += pj * v0.w;
            o[4]  += pj * v1.x; o[5]  += pj * v1.y; o[6]  += pj * v1.z; o[7]  += pj * v1.w;
            o[8]  += pj * v2.x; o[9]  += pj * v2.y; o[10] += pj * v2.z; o[11] += pj * v2.w;
            o[12] += pj * v3.x; o[13] += pj * v3.y; o[14] += pj * v3.z; o[15] += pj * v3.w;
        }
        m_run = mnew;
    }
    float inv = 1.f / l_run;
#pragma unroll
    for (int d = 0; d < 16; ++d)
        g_attn[((size_t)(b * 256 + head * 16 + d) << 16) + p] = o[d] * inv;
}

// ---------------------------------------------------------------------------
// mid = avgpool_v(attn) + avgpool_h(attn) + local
// ---------------------------------------------------------------------------
__global__ void pool_add_kernel()
{
    int bc = blockIdx.x >> 8;
    int h  = blockIdx.x & 255;
    int w  = threadIdx.x;
    const float* plane = g_attn + ((size_t)bc << 16);

    float sx = 0.f;
#pragma unroll
    for (int t = h - 3; t <= h + 4; ++t) {
        if (t >= 0 && t <= 256) {
            int tt = (t == 256) ? 254 : t;
            sx += plane[tt * 256 + w];
        }
    }
    const float* row = plane + h * 256;
    float sy = 0.f;
#pragma unroll
    for (int t = w - 3; t <= w + 4; ++t) {
        if (t >= 0 && t <= 256) {
            int tt = (t == 256) ? 254 : t;
            sy += row[tt];
        }
    }
    size_t idx = ((size_t)bc << 16) + h * 256 + w;
    g_mid[idx] = (sx + sy) * 0.125f + g_local[idx];
}

// ---------------------------------------------------------------------------
// Depthwise 8x8 conv + BN
// ---------------------------------------------------------------------------
__global__ __launch_bounds__(256) void dwconv_kernel(const float* __restrict__ w_dw)
{
    __shared__ float tile[39 * 40];
    __shared__ float ws[64];

    int tix = blockIdx.x;
    int bc  = blockIdx.y;
    int c   = bc & 255;
    int ty0 = (tix >> 3) * 32;
    int tx0 = (tix & 7) * 32;
    int tid = threadIdx.x;

    const float* plane = g_mid + ((size_t)bc << 16);

    for (int idx = tid; idx < 39 * 39; idx += 256) {
        int r  = idx / 39;
        int cc = idx - r * 39;
        int gh = ty0 - 3 + r;
        int gw = tx0 - 3 + cc;
        float v = 0.f;
        if (gh >= 0 && gh <= 256 && gw >= 0 && gw <= 256) {
            int ih = (gh == 256) ? 254 : gh;
            int iw = (gw == 256) ? 254 : gw;
            v = plane[ih * 256 + iw];
        }
        tile[r * 40 + cc] = v;
    }
    if (tid < 64) ws[tid] = w_dw[c * 64 + tid];
    __syncthreads();

    int lw  = tid & 31;
    int lh0 = (tid >> 5) * 4;
    float acc[4] = {0.f, 0.f, 0.f, 0.f};
#pragma unroll
    for (int j = 0; j < 8; ++j) {
        float wcol[8];
#pragma unroll
        for (int i = 0; i < 8; ++i) wcol[i] = ws[i * 8 + j];
#pragma unroll
        for (int r = 0; r < 11; ++r) {
            float v = tile[(lh0 + r) * 40 + lw + j];
#pragma unroll
            for (int a = 0; a < 4; ++a) {
                int i = r - a;
                if (i >= 0 && i < 8) acc[a] += v * wcol[i];
            }
        }
    }
    float ip = g_invp[c];
    float bb = g_biasp[c];
#pragma unroll
    for (int a = 0; a < 4; ++a) {
        int h = ty0 + lh0 + a;
        g_dw[((size_t)bc << 16) + h * 256 + tx0 + lw] = acc[a] * ip + bb;
    }
}

// ---------------------------------------------------------------------------
// Launch
// ---------------------------------------------------------------------------
extern "C" void kernel_launch(void* const* d_in, const int* in_sizes, int n_in,
                              void* d_out, int out_size)
{
    const float* x    = (const float*)d_in[0];
    const float* y    = (const float*)d_in[1];
    const float* wqkv = (const float*)d_in[2];
    const float* wl1  = (const float*)d_in[3];
    const float* g1   = (const float*)d_in[4];
    const float* b1   = (const float*)d_in[5];
    const float* m1   = (const float*)d_in[6];
    const float* v1   = (const float*)d_in[7];
    const float* wl2  = (const float*)d_in[8];
    const float* g2   = (const float*)d_in[9];
    const float* b2   = (const float*)d_in[10];
    const float* m2   = (const float*)d_in[11];
    const float* v2   = (const float*)d_in[12];
    const float* wdw  = (const float*)d_in[13];
    const float* gp   = (const float*)d_in[14];
    const float* bp   = (const float*)d_in[15];
    const float* mp   = (const float*)d_in[16];
    const float* vp   = (const float*)d_in[17];
    const float* wpw  = (const float*)d_in[18];
    const float* rpb  = (const float*)d_in[19];
    float* out = (float*)d_out;

    prep_kernel<<<1, 256>>>(g1, b1, m1, v1, g2, b2, m2, v2, gp, bp, mp, vp);

    gemm_local_bf16<<<dim3(1024, 2), 256>>>(wl1, wl2, y);

    gemm_bf16<<<dim3(1024, 6), 256>>>(wqkv, x, nullptr, 768, 256, 0);

    attn_kernel<<<dim3(2048, 16), 64>>>(rpb);

    pool_add_kernel<<<512 * 256, 256>>>();

    dwconv_kernel<<<dim3(64, 512), 256>>>(wdw);

    gemm_bf16<<<dim3(1024, 2), 256>>>(wpw, nullptr, out, 256, 256, 1);
}

// round 6
// speedup vs baseline: 1.9066x; 1.0208x over previous
#include <cuda_runtime.h>
#include <cuda_bf16.h>
#include <math.h>
#include <stdint.h>

// ---------------------------------------------------------------------------
// Problem constants: B=2, C=256, H=W=256, SSM=256, NH=16, HD=16, WS=8
// ---------------------------------------------------------------------------
#define PPLANE 65536
#define NBATCH 2

__device__ float g_local[NBATCH * 256 * PPLANE];
__device__ float g_qkv  [NBATCH * 768 * PPLANE];   // window-major pixel layout
__device__ float g_attn [NBATCH * 256 * PPLANE];
__device__ float g_mid  [NBATCH * 256 * PPLANE];
__device__ float g_dw   [NBATCH * 256 * PPLANE];

__device__ float g_inv1[256], g_inv2[256], g_biasc[256], g_invp[256], g_biasp[256];

// ---------------------------------------------------------------------------
// bf16 split + mma + ldmatrix helpers
// ---------------------------------------------------------------------------
__device__ __forceinline__ uint32_t smem_u32(const void* p) {
    uint32_t a;
    asm("{ .reg .u64 t; cvta.to.shared.u64 t, %1; cvt.u32.u64 %0, t; }"
        : "=r"(a) : "l"(p));
    return a;
}
__device__ __forceinline__ uint32_t pkbf(float a, float b) {
    __nv_bfloat162 t = __floats2bfloat162_rn(a, b);
    return *reinterpret_cast<uint32_t*>(&t);
}
__device__ __forceinline__ float bfh(float x) {
    return __bfloat162float(__float2bfloat16_rn(x));
}
__device__ __forceinline__ void split8(const float* v, uint4& hi, uint4& lo) {
    float h0 = bfh(v[0]), h1 = bfh(v[1]), h2 = bfh(v[2]), h3 = bfh(v[3]);
    float h4 = bfh(v[4]), h5 = bfh(v[5]), h6 = bfh(v[6]), h7 = bfh(v[7]);
    hi = make_uint4(pkbf(v[0], v[1]), pkbf(v[2], v[3]), pkbf(v[4], v[5]), pkbf(v[6], v[7]));
    lo = make_uint4(pkbf(v[0]-h0, v[1]-h1), pkbf(v[2]-h2, v[3]-h3),
                    pkbf(v[4]-h4, v[5]-h5), pkbf(v[6]-h6, v[7]-h7));
}
__device__ __forceinline__ void ldsm4(uint32_t* r, uint32_t a) {
    asm volatile("ldmatrix.sync.aligned.m8n8.x4.shared.b16 {%0,%1,%2,%3},[%4];"
                 : "=r"(r[0]), "=r"(r[1]), "=r"(r[2]), "=r"(r[3]) : "r"(a));
}
__device__ __forceinline__ void ldsm4t(uint32_t* r, uint32_t a) {
    asm volatile("ldmatrix.sync.aligned.m8n8.x4.trans.shared.b16 {%0,%1,%2,%3},[%4];"
                 : "=r"(r[0]), "=r"(r[1]), "=r"(r[2]), "=r"(r[3]) : "r"(a));
}
__device__ __forceinline__ void mma16(float* c, const uint32_t* a, const uint32_t* b) {
    asm volatile(
        "mma.sync.aligned.m16n8k16.row.col.f32.bf16.bf16.f32 "
        "{%0,%1,%2,%3},{%4,%5,%6,%7},{%8,%9},{%0,%1,%2,%3};"
        : "+f"(c[0]), "+f"(c[1]), "+f"(c[2]), "+f"(c[3])
        : "r"(a[0]), "r"(a[1]), "r"(a[2]), "r"(a[3]), "r"(b[0]), "r"(b[1]));
}

#define ASTRIDE 48
#define BSTRIDE 272
#define ABYTES (128 * ASTRIDE)
#define BBYTES (16 * BSTRIDE)

// pixel -> window-major permuted index (within one 256x256 plane)
__device__ __forceinline__ int perm_px(int p) {
    int h = p >> 8, w = p & 255;
    return (((h >> 3) * 32 + (w >> 3)) << 6) + ((h & 7) << 3) + (w & 7);
}

// ---------------------------------------------------------------------------
// Prep: fold BN params
// ---------------------------------------------------------------------------
__global__ void prep_kernel(const float* __restrict__ g1, const float* __restrict__ b1,
                            const float* __restrict__ m1, const float* __restrict__ v1,
                            const float* __restrict__ g2, const float* __restrict__ b2,
                            const float* __restrict__ m2, const float* __restrict__ v2,
                            const float* __restrict__ gp, const float* __restrict__ bp,
                            const float* __restrict__ mp, const float* __restrict__ vp)
{
    int c = threadIdx.x;
    float i1 = g1[c] * rsqrtf(v1[c] + 1e-5f);
    float i2 = g2[c] * rsqrtf(v2[c] + 1e-5f);
    g_inv1[c] = i1;
    g_inv2[c] = i2;
    g_biasc[c] = (b1[c] - m1[c] * i1) + (b2[c] - m2[c] * i2);
    float ip = gp[c] * rsqrtf(vp[c] + 1e-5f);
    g_invp[c] = ip;
    g_biasp[c] = bp[c] - mp[c] * ip;
}

// ---------------------------------------------------------------------------
// Consumer: one K=16 step (3-pass split-bf16)
// ---------------------------------------------------------------------------
__device__ __forceinline__ void mma_step(
    uint32_t sAh, uint32_t sAl, uint32_t sBh, uint32_t sBl,
    int wm, int wn, int lane, float acc[4][4][4])
{
    int t  = lane >> 3;
    int r8 = lane & 7;
    uint32_t bh[4][2], bl[4][2];
#pragma unroll
    for (int ng = 0; ng < 2; ++ng) {
        uint32_t addr = ((t >> 1) * 8 + r8) * BSTRIDE + (wn + ng * 16 + (t & 1) * 8) * 2;
        uint32_t tb[4];
        ldsm4t(tb, sBh + addr);
        bh[ng * 2 + 0][0] = tb[0]; bh[ng * 2 + 0][1] = tb[2];
        bh[ng * 2 + 1][0] = tb[1]; bh[ng * 2 + 1][1] = tb[3];
        ldsm4t(tb, sBl + addr);
        bl[ng * 2 + 0][0] = tb[0]; bl[ng * 2 + 0][1] = tb[2];
        bl[ng * 2 + 1][0] = tb[1]; bl[ng * 2 + 1][1] = tb[3];
    }
    uint32_t abase = ((t & 1) * 8 + r8) * ASTRIDE + (t >> 1) * 16;
#pragma unroll
    for (int mt = 0; mt < 4; ++mt) {
        uint32_t arow = abase + (wm + mt * 16) * ASTRIDE;
        uint32_t ah[4], al[4];
        ldsm4(ah, sAh + arow);
#pragma unroll
        for (int j = 0; j < 4; ++j) mma16(acc[mt][j], ah, bh[j]);
#pragma unroll
        for (int j = 0; j < 4; ++j) mma16(acc[mt][j], ah, bl[j]);
        ldsm4(al, sAl + arow);
#pragma unroll
        for (int j = 0; j < 4; ++j) mma16(acc[mt][j], al, bh[j]);
    }
}

// ---------------------------------------------------------------------------
// Plain GEMM (double-buffered): C = A * B
//   dst==0 -> g_qkv with window-major permuted columns
//   dst==1 -> extC, normal layout, B = g_dw
// ---------------------------------------------------------------------------
__global__ __launch_bounds__(256, 2) void gemm_bf16(
    const float* __restrict__ A, const float* __restrict__ Bm,
    float* extC, int M, int K, int dst)
{
    __shared__ __align__(16) char AhS[2][ABYTES];
    __shared__ __align__(16) char AlS[2][ABYTES];
    __shared__ __align__(16) char BhS[2][BBYTES];
    __shared__ __align__(16) char BlS[2][BBYTES];

    const float* Bsrc = Bm ? Bm : (const float*)g_dw;
    float* C = (dst == 0) ? (float*)g_qkv : extC;

    int tid = threadIdx.x;
    int pg0 = blockIdx.x * 128;
    int b   = pg0 >> 16;
    int p0  = pg0 & 65535;
    int m0  = blockIdx.y * 128;
    int lane = tid & 31, warp = tid >> 5;
    int wm = (warp >> 2) * 64, wn = (warp & 3) * 32;

    int am = tid >> 1, ak = (tid & 1) * 8;
    const float* Abase = A + (size_t)(m0 + am) * K + ak;
    int bk = tid >> 4, bn = (tid & 15) * 8;
    const float* Bbase = Bsrc + ((size_t)(b * K + bk) << 16) + p0 + bn;

    int aoff = am * ASTRIDE + ak * 2;
    int boff = bk * BSTRIDE + bn * 2;

    float acc[4][4][4];
#pragma unroll
    for (int i = 0; i < 4; ++i)
#pragma unroll
        for (int j = 0; j < 4; ++j)
#pragma unroll
            for (int r = 0; r < 4; ++r) acc[i][j][r] = 0.f;

    float ar[8], br[8];
    auto gload = [&](int k0) {
        float4 t0 = *(const float4*)(Abase + k0);
        float4 t1 = *(const float4*)(Abase + k0 + 4);
        ar[0]=t0.x; ar[1]=t0.y; ar[2]=t0.z; ar[3]=t0.w;
        ar[4]=t1.x; ar[5]=t1.y; ar[6]=t1.z; ar[7]=t1.w;
        const float* bp = Bbase + ((size_t)k0 << 16);
        float4 u0 = *(const float4*)bp;
        float4 u1 = *(const float4*)(bp + 4);
        br[0]=u0.x; br[1]=u0.y; br[2]=u0.z; br[3]=u0.w;
        br[4]=u1.x; br[5]=u1.y; br[6]=u1.z; br[7]=u1.w;
    };
    auto sstore = [&](int s) {
        uint4 hi, lo;
        split8(ar, hi, lo);
        *(uint4*)(AhS[s] + aoff) = hi;
        *(uint4*)(AlS[s] + aoff) = lo;
        split8(br, hi, lo);
        *(uint4*)(BhS[s] + boff) = hi;
        *(uint4*)(BlS[s] + boff) = lo;
    };

    int nch = K >> 4;
    gload(0);
    sstore(0);
    if (nch > 1) gload(16);
    __syncthreads();

    for (int ch = 0; ch < nch; ++ch) {
        if (ch + 1 < nch) sstore((ch + 1) & 1);       // regs hold chunk ch+1
        if (ch + 2 < nch) gload((ch + 2) << 4);       // prefetch chunk ch+2
        int s = ch & 1;
        mma_step(smem_u32(AhS[s]), smem_u32(AlS[s]),
                 smem_u32(BhS[s]), smem_u32(BlS[s]), wm, wn, lane, acc);
        __syncthreads();
    }

    int g = lane >> 2, tig = lane & 3;
#pragma unroll
    for (int mt = 0; mt < 4; ++mt) {
        int r0 = m0 + wm + mt * 16 + g;
#pragma unroll
        for (int j = 0; j < 4; ++j) {
            int col = p0 + wn + j * 8 + tig * 2;
            int pc = (dst == 0) ? perm_px(col) : col;
            size_t i0 = ((size_t)(b * M + r0) << 16) + pc;
            size_t i1 = ((size_t)(b * M + r0 + 8) << 16) + pc;
            *(float2*)&C[i0] = make_float2(acc[mt][j][0], acc[mt][j][1]);
            *(float2*)&C[i1] = make_float2(acc[mt][j][2], acc[mt][j][3]);
        }
    }
}

// ---------------------------------------------------------------------------
// Fused local branch (double-buffered): conv3x3+BN1 + conv1x1+BN2, K=2560.
// ---------------------------------------------------------------------------
__global__ __launch_bounds__(256, 2) void gemm_local_bf16(
    const float* __restrict__ w1, const float* __restrict__ w2,
    const float* __restrict__ y)
{
    __shared__ __align__(16) char AhS[2][ABYTES];
    __shared__ __align__(16) char AlS[2][ABYTES];
    __shared__ __align__(16) char BhS[2][BBYTES];
    __shared__ __align__(16) char BlS[2][BBYTES];

    int tid = threadIdx.x;
    int pg0 = blockIdx.x * 128;
    int b   = pg0 >> 16;
    int p0  = pg0 & 65535;
    int m0  = blockIdx.y * 128;
    int h   = p0 >> 8;
    int w0  = p0 & 255;
    int lane = tid & 31, warp = tid >> 5;
    int wm = (warp >> 2) * 64, wn = (warp & 3) * 32;

    int am = tid >> 1, ak = (tid & 1) * 8;
    int mg = m0 + am;
    float s1 = g_inv1[mg];
    float s2 = g_inv2[mg];
    int bk = tid >> 4, bn = (tid & 15) * 8;

    int aoff = am * ASTRIDE + ak * 2;
    int boff = bk * BSTRIDE + bn * 2;

    float acc[4][4][4];
#pragma unroll
    for (int i = 0; i < 4; ++i)
#pragma unroll
        for (int j = 0; j < 4; ++j)
#pragma unroll
            for (int r = 0; r < 4; ++r) acc[i][j][r] = 0.f;

    float ar[8], br[8];
    auto gload = [&](int k0) {
        {
            int k = k0 + ak;
            const float* ap;
            float sc;
            if (k < 2304) { ap = w1 + (size_t)mg * 2304 + k; sc = s1; }
            else          { ap = w2 + (size_t)mg * 256 + (k - 2304); sc = s2; }
            float4 t0 = *(const float4*)ap;
            float4 t1 = *(const float4*)(ap + 4);
            ar[0]=t0.x*sc; ar[1]=t0.y*sc; ar[2]=t0.z*sc; ar[3]=t0.w*sc;
            ar[4]=t1.x*sc; ar[5]=t1.y*sc; ar[6]=t1.z*sc; ar[7]=t1.w*sc;
        }
        {
            int k = k0 + bk;
            int ci, dy, dx;
            if (k < 2304) {
                ci = k / 9;
                int tap = k - ci * 9;
                int r = tap / 3;
                dy = r - 1;
                dx = tap - r * 3 - 1;
            } else { ci = k - 2304; dy = 0; dx = 0; }
            int hh = h + dy;
            bool hok = (hh >= 0) && (hh < 256);
            const float* row = y + ((size_t)(b * 256 + ci) << 16) + hh * 256;
#pragma unroll
            for (int j = 0; j < 8; ++j) {
                int ww = w0 + bn + j + dx;
                br[j] = (hok && ww >= 0 && ww < 256) ? row[ww] : 0.f;
            }
        }
    };
    auto sstore = [&](int s) {
        uint4 hi, lo;
        split8(ar, hi, lo);
        *(uint4*)(AhS[s] + aoff) = hi;
        *(uint4*)(AlS[s] + aoff) = lo;
        split8(br, hi, lo);
        *(uint4*)(BhS[s] + boff) = hi;
        *(uint4*)(BlS[s] + boff) = lo;
    };

    const int nch = 160;   // 2560 / 16
    gload(0);
    sstore(0);
    gload(16);
    __syncthreads();

    for (int ch = 0; ch < nch; ++ch) {
        if (ch + 1 < nch) sstore((ch + 1) & 1);
        if (ch + 2 < nch) gload((ch + 2) << 4);
        int s = ch & 1;
        mma_step(smem_u32(AhS[s]), smem_u32(AlS[s]),
                 smem_u32(BhS[s]), smem_u32(BlS[s]), wm, wn, lane, acc);
        __syncthreads();
    }

    int g = lane >> 2, tig = lane & 3;
#pragma unroll
    for (int mt = 0; mt < 4; ++mt) {
        int r0 = m0 + wm + mt * 16 + g;
        float bi0 = g_biasc[r0];
        float bi1 = g_biasc[r0 + 8];
#pragma unroll
        for (int j = 0; j < 4; ++j) {
            int col = p0 + wn + j * 8 + tig * 2;
            size_t i0 = ((size_t)(b * 256 + r0) << 16) + col;
            size_t i1 = ((size_t)(b * 256 + r0 + 8) << 16) + col;
            *(float2*)&g_local[i0] = make_float2(acc[mt][j][0] + bi0, acc[mt][j][1] + bi0);
            *(float2*)&g_local[i1] = make_float2(acc[mt][j][2] + bi1, acc[mt][j][3] + bi1);
        }
    }
}

// ---------------------------------------------------------------------------
// Windowed attention, online softmax. qkv is window-major -> coalesced loads.
// ---------------------------------------------------------------------------
__global__ __launch_bounds__(64) void attn_kernel(const float* __restrict__ rpb)
{
    int win  = blockIdx.x;          // 0..2047 (includes batch)
    int head = blockIdx.y;
    int b  = win >> 10;
    int wloc = win & 1023;
    int i  = threadIdx.x;
    int yi = i >> 3, xi = i & 7;
    int pp = wloc * 64 + i;         // permuted (window-major) pixel index

    __shared__ float ks[64][16];
    __shared__ float vs[64][16];
    __shared__ float rpbs[225];

    for (int t = i; t < 225; t += 64) rpbs[t] = rpb[t * 16 + head];

    size_t base = ((size_t)(b * 768 + head * 16) << 16) + pp;
    float q[16];
#pragma unroll
    for (int d = 0; d < 16; ++d) {
        q[d]     = g_qkv[base + ((size_t)d << 16)] * 0.25f;
        ks[i][d] = g_qkv[base + ((size_t)(256 + d) << 16)];
        vs[i][d] = g_qkv[base + ((size_t)(512 + d) << 16)];
    }
    __syncthreads();

    float m_run = -1e30f, l_run = 0.f;
    float o[16];
#pragma unroll
    for (int d = 0; d < 16; ++d) o[d] = 0.f;

#pragma unroll
    for (int cchunk = 0; cchunk < 4; ++cchunk) {
        float s[16];
        float cm = -1e30f;
#pragma unroll
        for (int jj = 0; jj < 16; ++jj) {
            int j = cchunk * 16 + jj;
            const float4* kp = (const float4*)ks[j];
            float4 k0 = kp[0], k1 = kp[1], k2 = kp[2], k3 = kp[3];
            float acc = q[0] * k0.x + q[1] * k0.y + q[2] * k0.z + q[3] * k0.w
                      + q[4] * k1.x + q[5] * k1.y + q[6] * k1.z + q[7] * k1.w
                      + q[8] * k2.x + q[9] * k2.y + q[10] * k2.z + q[11] * k2.w
                      + q[12] * k3.x + q[13] * k3.y + q[14] * k3.z + q[15] * k3.w;
            int yj = j >> 3, xj = j & 7;
            acc += rpbs[(yi - yj + 7) * 15 + (xi - xj + 7)];
            s[jj] = acc;
            cm = fmaxf(cm, acc);
        }
        float mnew = fmaxf(m_run, cm);
        float corr = __expf(m_run - mnew);
        l_run *= corr;
#pragma unroll
        for (int d = 0; d < 16; ++d) o[d] *= corr;
#pragma unroll
        for (int jj = 0; jj < 16; ++jj) {
            int j = cchunk * 16 + jj;
            float pj = __expf(s[jj] - mnew);
            l_run += pj;
            const float4* vp = (const float4*)vs[j];
            float4 v0 = vp[0], v1 = vp[1], v2 = vp[2], v3 = vp[3];
            o[0]  += pj * v0.x; o[1]  += pj * v0.y; o[2]  += pj * v0.z; o[3]  += pj * v0.w;
            o[4]  += pj * v1.x; o[5]  += pj * v1.y; o[6]  += pj * v1.z; o[7]  += pj * v1.w;
            o[8]  += pj * v2.x; o[9]  += pj * v2.y; o[10] += pj * v2.z; o[11] += pj * v2.w;
            o[12] += pj * v3.x; o[13] += pj * v3.y; o[14] += pj * v3.z; o[15] += pj * v3.w;
        }
        m_run = mnew;
    }
    float inv = 1.f / l_run;

    // store to normal layout for the pool stage
    int wy = wloc >> 5, wx = wloc & 31;
    int p  = ((wy * 8 + yi) << 8) + wx * 8 + xi;
#pragma unroll
    for (int d = 0; d < 16; ++d)
        g_attn[((size_t)(b * 256 + head * 16 + d) << 16) + p] = o[d] * inv;
}

// ---------------------------------------------------------------------------
// mid = avgpool_v(attn) + avgpool_h(attn) + local
// ---------------------------------------------------------------------------
__global__ void pool_add_kernel()
{
    int bc = blockIdx.x >> 8;
    int h  = blockIdx.x & 255;
    int w  = threadIdx.x;
    const float* plane = g_attn + ((size_t)bc << 16);

    float sx = 0.f;
#pragma unroll
    for (int t = h - 3; t <= h + 4; ++t) {
        if (t >= 0 && t <= 256) {
            int tt = (t == 256) ? 254 : t;
            sx += plane[tt * 256 + w];
        }
    }
    const float* row = plane + h * 256;
    float sy = 0.f;
#pragma unroll
    for (int t = w - 3; t <= w + 4; ++t) {
        if (t >= 0 && t <= 256) {
            int tt = (t == 256) ? 254 : t;
            sy += row[tt];
        }
    }
    size_t idx = ((size_t)bc << 16) + h * 256 + w;
    g_mid[idx] = (sx + sy) * 0.125f + g_local[idx];
}

// ---------------------------------------------------------------------------
// Depthwise 8x8 conv + BN
// ---------------------------------------------------------------------------
__global__ __launch_bounds__(256) void dwconv_kernel(const float* __restrict__ w_dw)
{
    __shared__ float tile[39 * 40];
    __shared__ float ws[64];

    int tix = blockIdx.x;
    int bc  = blockIdx.y;
    int c   = bc & 255;
    int ty0 = (tix >> 3) * 32;
    int tx0 = (tix & 7) * 32;
    int tid = threadIdx.x;

    const float* plane = g_mid + ((size_t)bc << 16);

    for (int idx = tid; idx < 39 * 39; idx += 256) {
        int r  = idx / 39;
        int cc = idx - r * 39;
        int gh = ty0 - 3 + r;
        int gw = tx0 - 3 + cc;
        float v = 0.f;
        if (gh >= 0 && gh <= 256 && gw >= 0 && gw <= 256) {
            int ih = (gh == 256) ? 254 : gh;
            int iw = (gw == 256) ? 254 : gw;
            v = plane[ih * 256 + iw];
        }
        tile[r * 40 + cc] = v;
    }
    if (tid < 64) ws[tid] = w_dw[c * 64 + tid];
    __syncthreads();

    int lw  = tid & 31;
    int lh0 = (tid >> 5) * 4;
    float acc[4] = {0.f, 0.f, 0.f, 0.f};
#pragma unroll
    for (int j = 0; j < 8; ++j) {
        float wcol[8];
#pragma unroll
        for (int i = 0; i < 8; ++i) wcol[i] = ws[i * 8 + j];
#pragma unroll
        for (int r = 0; r < 11; ++r) {
            float v = tile[(lh0 + r) * 40 + lw + j];
#pragma unroll
            for (int a = 0; a < 4; ++a) {
                int i = r - a;
                if (i >= 0 && i < 8) acc[a] += v * wcol[i];
            }
        }
    }
    float ip = g_invp[c];
    float bb = g_biasp[c];
#pragma unroll
    for (int a = 0; a < 4; ++a) {
        int h = ty0 + lh0 + a;
        g_dw[((size_t)bc << 16) + h * 256 + tx0 + lw] = acc[a] * ip + bb;
    }
}

// ---------------------------------------------------------------------------
// Launch
// ---------------------------------------------------------------------------
extern "C" void kernel_launch(void* const* d_in, const int* in_sizes, int n_in,
                              void* d_out, int out_size)
{
    const float* x    = (const float*)d_in[0];
    const float* y    = (const float*)d_in[1];
    const float* wqkv = (const float*)d_in[2];
    const float* wl1  = (const float*)d_in[3];
    const float* g1   = (const float*)d_in[4];
    const float* b1   = (const float*)d_in[5];
    const float* m1   = (const float*)d_in[6];
    const float* v1   = (const float*)d_in[7];
    const float* wl2  = (const float*)d_in[8];
    const float* g2   = (const float*)d_in[9];
    const float* b2   = (const float*)d_in[10];
    const float* m2   = (const float*)d_in[11];
    const float* v2   = (const float*)d_in[12];
    const float* wdw  = (const float*)d_in[13];
    const float* gp   = (const float*)d_in[14];
    const float* bp   = (const float*)d_in[15];
    const float* mp   = (const float*)d_in[16];
    const float* vp   = (const float*)d_in[17];
    const float* wpw  = (const float*)d_in[18];
    const float* rpb  = (const float*)d_in[19];
    float* out = (float*)d_out;

    prep_kernel<<<1, 256>>>(g1, b1, m1, v1, g2, b2, m2, v2, gp, bp, mp, vp);

    gemm_local_bf16<<<dim3(1024, 2), 256>>>(wl1, wl2, y);

    gemm_bf16<<<dim3(1024, 6), 256>>>(wqkv, x, nullptr, 768, 256, 0);

    attn_kernel<<<dim3(2048, 16), 64>>>(rpb);

    pool_add_kernel<<<512 * 256, 256>>>();

    dwconv_kernel<<<dim3(64, 512), 256>>>(wdw);

    gemm_bf16<<<dim3(1024, 2), 256>>>(wpw, nullptr, out, 256, 256, 1);
}

// round 8
// speedup vs baseline: 2.0085x; 1.0535x over previous
#include <cuda_runtime.h>
#include <cuda_bf16.h>
#include <math.h>
#include <stdint.h>

// ---------------------------------------------------------------------------
// Problem constants: B=2, C=256, H=W=256, SSM=256, NH=16, HD=16, WS=8
// ---------------------------------------------------------------------------
#define PPLANE 65536
#define NBATCH 2

__device__ float g_local[NBATCH * 256 * PPLANE];
__device__ float g_qkv  [NBATCH * 768 * PPLANE];   // window-major pixel layout
__device__ float g_attn [NBATCH * 256 * PPLANE];
__device__ float g_mid  [NBATCH * 256 * PPLANE];

// pre-split bf16 operands
__device__ unsigned short g_xhi [NBATCH * 256 * PPLANE];
__device__ unsigned short g_xlo [NBATCH * 256 * PPLANE];
__device__ uint32_t       g_yhl [NBATCH * 256 * PPLANE];   // (hi<<16)|lo
__device__ unsigned short g_dwhi[NBATCH * 256 * PPLANE];
__device__ unsigned short g_dwlo[NBATCH * 256 * PPLANE];
__device__ unsigned short g_wqh [768 * 256], g_wql [768 * 256];
__device__ unsigned short g_wph [256 * 256], g_wpl [256 * 256];
__device__ unsigned short g_wlh [256 * 2560], g_wll [256 * 2560];

__device__ float g_inv1[256], g_inv2[256], g_biasc[256], g_invp[256], g_biasp[256];

// ---------------------------------------------------------------------------
// helpers
// ---------------------------------------------------------------------------
__device__ __forceinline__ uint32_t smem_u32(const void* p) {
    uint32_t a;
    asm("{ .reg .u64 t; cvta.to.shared.u64 t, %1; cvt.u32.u64 %0, t; }"
        : "=r"(a) : "l"(p));
    return a;
}
__device__ __forceinline__ void splt(float v, unsigned short& h, unsigned short& l) {
    __nv_bfloat16 hb = __float2bfloat16_rn(v);
    float r = v - __bfloat162float(hb);
    __nv_bfloat16 lb = __float2bfloat16_rn(r);
    h = *reinterpret_cast<unsigned short*>(&hb);
    l = *reinterpret_cast<unsigned short*>(&lb);
}
__device__ __forceinline__ void ldsm4(uint32_t* r, uint32_t a) {
    asm volatile("ldmatrix.sync.aligned.m8n8.x4.shared.b16 {%0,%1,%2,%3},[%4];"
                 : "=r"(r[0]), "=r"(r[1]), "=r"(r[2]), "=r"(r[3]) : "r"(a));
}
__device__ __forceinline__ void ldsm4t(uint32_t* r, uint32_t a) {
    asm volatile("ldmatrix.sync.aligned.m8n8.x4.trans.shared.b16 {%0,%1,%2,%3},[%4];"
                 : "=r"(r[0]), "=r"(r[1]), "=r"(r[2]), "=r"(r[3]) : "r"(a));
}
__device__ __forceinline__ void mma16(float* c, const uint32_t* a, const uint32_t* b) {
    asm volatile(
        "mma.sync.aligned.m16n8k16.row.col.f32.bf16.bf16.f32 "
        "{%0,%1,%2,%3},{%4,%5,%6,%7},{%8,%9},{%0,%1,%2,%3};"
        : "+f"(c[0]), "+f"(c[1]), "+f"(c[2]), "+f"(c[3])
        : "r"(a[0]), "r"(a[1]), "r"(a[2]), "r"(a[3]), "r"(b[0]), "r"(b[1]));
}

#define ASTRIDE 48
#define BSTRIDE 272
#define ABYTES (128 * ASTRIDE)
#define BBYTES (16 * BSTRIDE)

__device__ __forceinline__ int perm_px(int p) {
    int h = p >> 8, w = p & 255;
    return (((h >> 3) * 32 + (w >> 3)) << 6) + ((h & 7) << 3) + (w & 7);
}

// ---------------------------------------------------------------------------
// Prep kernels
// ---------------------------------------------------------------------------
__global__ void prep_kernel(const float* __restrict__ g1, const float* __restrict__ b1,
                            const float* __restrict__ m1, const float* __restrict__ v1,
                            const float* __restrict__ g2, const float* __restrict__ b2,
                            const float* __restrict__ m2, const float* __restrict__ v2,
                            const float* __restrict__ gp, const float* __restrict__ bp,
                            const float* __restrict__ mp, const float* __restrict__ vp)
{
    int c = threadIdx.x;
    float i1 = g1[c] * rsqrtf(v1[c] + 1e-5f);
    float i2 = g2[c] * rsqrtf(v2[c] + 1e-5f);
    g_inv1[c] = i1;
    g_inv2[c] = i2;
    g_biasc[c] = (b1[c] - m1[c] * i1) + (b2[c] - m2[c] * i2);
    float ip = gp[c] * rsqrtf(vp[c] + 1e-5f);
    g_invp[c] = ip;
    g_biasp[c] = bp[c] - mp[c] * ip;
}

// split qkv weights; q rows (m<256) pre-scaled by 0.25
__global__ void split_wqkv(const float* __restrict__ w)
{
    int i = blockIdx.x * 256 + threadIdx.x;
    if (i >= 768 * 256) return;
    float sc = (i < 256 * 256) ? 0.25f : 1.0f;
    splt(w[i] * sc, g_wqh[i], g_wql[i]);
}
__global__ void split_wpw(const float* __restrict__ w)
{
    int i = blockIdx.x * 256 + threadIdx.x;
    splt(w[i], g_wph[i], g_wpl[i]);
}
__global__ void split_wlocal(const float* __restrict__ w1, const float* __restrict__ w2)
{
    int i = blockIdx.x * 256 + threadIdx.x;
    if (i >= 256 * 2560) return;
    int m = i / 2560, k = i - m * 2560;
    float v = (k < 2304) ? w1[m * 2304 + k] * g_inv1[m]
                         : w2[m * 256 + (k - 2304)] * g_inv2[m];
    splt(v, g_wlh[i], g_wll[i]);
}
__global__ void split_x(const float* __restrict__ x)
{
    size_t i4 = (size_t)blockIdx.x * 256 + threadIdx.x;
    size_t base = i4 * 4;
    float4 v = *(const float4*)(x + base);
    unsigned short h[4], l[4];
    splt(v.x, h[0], l[0]); splt(v.y, h[1], l[1]);
    splt(v.z, h[2], l[2]); splt(v.w, h[3], l[3]);
    *(uint2*)(g_xhi + base) = *(uint2*)h;
    *(uint2*)(g_xlo + base) = *(uint2*)l;
}
__global__ void split_y(const float* __restrict__ y)
{
    size_t i4 = (size_t)blockIdx.x * 256 + threadIdx.x;
    size_t base = i4 * 4;
    float4 v = *(const float4*)(y + base);
    uint32_t o[4];
    unsigned short h, l;
    splt(v.x, h, l); o[0] = ((uint32_t)h << 16) | l;
    splt(v.y, h, l); o[1] = ((uint32_t)h << 16) | l;
    splt(v.z, h, l); o[2] = ((uint32_t)h << 16) | l;
    splt(v.w, h, l); o[3] = ((uint32_t)h << 16) | l;
    *(uint4*)(g_yhl + base) = *(uint4*)o;
}

// ---------------------------------------------------------------------------
// Consumer: one K=16 step (3-pass split-bf16)
// ---------------------------------------------------------------------------
__device__ __forceinline__ void mma_step(
    uint32_t sAh, uint32_t sAl, uint32_t sBh, uint32_t sBl,
    int wm, int wn, int lane, float acc[4][4][4])
{
    int t  = lane >> 3;
    int r8 = lane & 7;
    uint32_t bh[4][2], bl[4][2];
#pragma unroll
    for (int ng = 0; ng < 2; ++ng) {
        uint32_t addr = ((t >> 1) * 8 + r8) * BSTRIDE + (wn + ng * 16 + (t & 1) * 8) * 2;
        uint32_t tb[4];
        ldsm4t(tb, sBh + addr);
        bh[ng * 2 + 0][0] = tb[0]; bh[ng * 2 + 0][1] = tb[2];
        bh[ng * 2 + 1][0] = tb[1]; bh[ng * 2 + 1][1] = tb[3];
        ldsm4t(tb, sBl + addr);
        bl[ng * 2 + 0][0] = tb[0]; bl[ng * 2 + 0][1] = tb[2];
        bl[ng * 2 + 1][0] = tb[1]; bl[ng * 2 + 1][1] = tb[3];
    }
    uint32_t abase = ((t & 1) * 8 + r8) * ASTRIDE + (t >> 1) * 16;
#pragma unroll
    for (int mt = 0; mt < 4; ++mt) {
        uint32_t arow = abase + (wm + mt * 16) * ASTRIDE;
        uint32_t ah[4], al[4];
        ldsm4(ah, sAh + arow);
#pragma unroll
        for (int j = 0; j < 4; ++j) mma16(acc[mt][j], ah, bh[j]);
#pragma unroll
        for (int j = 0; j < 4; ++j) mma16(acc[mt][j], ah, bl[j]);
        ldsm4(al, sAl + arow);
#pragma unroll
        for (int j = 0; j < 4; ++j) mma16(acc[mt][j], al, bh[j]);
    }
}

// ---------------------------------------------------------------------------
// Aligned GEMM (pre-split bf16 A and B), operands resolved DEVICE-SIDE.
//   which==0: A = wqkv (M=768,K=256), B = x,  C = g_qkv (permuted cols)
//   which==1: A = wpw  (M=256,K=256), B = dw, C = extC
// grid = (M/128, 1024)
// ---------------------------------------------------------------------------
__global__ __launch_bounds__(256, 2) void gemm_aligned(float* extC, int M, int K, int which)
{
    __shared__ __align__(16) char AhS[2][ABYTES];
    __shared__ __align__(16) char AlS[2][ABYTES];
    __shared__ __align__(16) char BhS[2][BBYTES];
    __shared__ __align__(16) char BlS[2][BBYTES];

    const unsigned short *Ah_g, *Al_g, *Bh_g, *Bl_g;
    float* C;
    if (which == 0) {
        Ah_g = g_wqh; Al_g = g_wql; Bh_g = g_xhi; Bl_g = g_xlo; C = (float*)g_qkv;
    } else {
        Ah_g = g_wph; Al_g = g_wpl; Bh_g = g_dwhi; Bl_g = g_dwlo; C = extC;
    }

    int tid = threadIdx.x;
    int m0  = blockIdx.x * 128;
    int pg0 = blockIdx.y * 128;
    int b   = pg0 >> 16;
    int p0  = pg0 & 65535;
    int lane = tid & 31, warp = tid >> 5;
    int wm = (warp >> 2) * 64, wn = (warp & 3) * 32;

    int am = tid >> 1, ak = (tid & 1) * 8;
    const unsigned short* Abh = Ah_g + (size_t)(m0 + am) * K + ak;
    const unsigned short* Abl = Al_g + (size_t)(m0 + am) * K + ak;
    int bk = tid >> 4, bn = (tid & 15) * 8;
    size_t bbase = ((size_t)(b * K + bk) << 16) + p0 + bn;

    int aoff = am * ASTRIDE + ak * 2;
    int boff = bk * BSTRIDE + bn * 2;

    float acc[4][4][4];
#pragma unroll
    for (int i = 0; i < 4; ++i)
#pragma unroll
        for (int j = 0; j < 4; ++j)
#pragma unroll
            for (int r = 0; r < 4; ++r) acc[i][j][r] = 0.f;

    uint4 rah, ral, rbh, rbl;
    auto gload = [&](int k0) {
        rah = *(const uint4*)(Abh + k0);
        ral = *(const uint4*)(Abl + k0);
        rbh = *(const uint4*)(Bh_g + bbase + ((size_t)k0 << 16));
        rbl = *(const uint4*)(Bl_g + bbase + ((size_t)k0 << 16));
    };
    auto sstore = [&](int s) {
        *(uint4*)(AhS[s] + aoff) = rah;
        *(uint4*)(AlS[s] + aoff) = ral;
        *(uint4*)(BhS[s] + boff) = rbh;
        *(uint4*)(BlS[s] + boff) = rbl;
    };

    int nch = K >> 4;
    gload(0);
    sstore(0);
    if (nch > 1) gload(16);
    __syncthreads();

    for (int ch = 0; ch < nch; ++ch) {
        if (ch + 1 < nch) sstore((ch + 1) & 1);
        if (ch + 2 < nch) gload((ch + 2) << 4);
        int s = ch & 1;
        mma_step(smem_u32(AhS[s]), smem_u32(AlS[s]),
                 smem_u32(BhS[s]), smem_u32(BlS[s]), wm, wn, lane, acc);
        __syncthreads();
    }

    int g = lane >> 2, tig = lane & 3;
#pragma unroll
    for (int mt = 0; mt < 4; ++mt) {
        int r0 = m0 + wm + mt * 16 + g;
#pragma unroll
        for (int j = 0; j < 4; ++j) {
            int col = p0 + wn + j * 8 + tig * 2;
            int pc = (which == 0) ? perm_px(col) : col;
            size_t i0 = ((size_t)(b * M + r0) << 16) + pc;
            size_t i1 = ((size_t)(b * M + r0 + 8) << 16) + pc;
            *(float2*)&C[i0] = make_float2(acc[mt][j][0], acc[mt][j][1]);
            *(float2*)&C[i1] = make_float2(acc[mt][j][2], acc[mt][j][3]);
        }
    }
}

// ---------------------------------------------------------------------------
// Fused local branch GEMM, K=2560, B gathered from interleaved g_yhl.
// grid = (2, 1024)
// ---------------------------------------------------------------------------
__global__ __launch_bounds__(256, 2) void gemm_local_bf16(void)
{
    __shared__ __align__(16) char AhS[2][ABYTES];
    __shared__ __align__(16) char AlS[2][ABYTES];
    __shared__ __align__(16) char BhS[2][BBYTES];
    __shared__ __align__(16) char BlS[2][BBYTES];

    int tid = threadIdx.x;
    int m0  = blockIdx.x * 128;
    int pg0 = blockIdx.y * 128;
    int b   = pg0 >> 16;
    int p0  = pg0 & 65535;
    int h   = p0 >> 8;
    int w0  = p0 & 255;
    int lane = tid & 31, warp = tid >> 5;
    int wm = (warp >> 2) * 64, wn = (warp & 3) * 32;

    int am = tid >> 1, ak = (tid & 1) * 8;
    int mg = m0 + am;
    int bk = tid >> 4, bn = (tid & 15) * 8;

    int aoff = am * ASTRIDE + ak * 2;
    int boff = bk * BSTRIDE + bn * 2;

    const unsigned short* Abh = g_wlh + (size_t)mg * 2560 + ak;
    const unsigned short* Abl = g_wll + (size_t)mg * 2560 + ak;

    float acc[4][4][4];
#pragma unroll
    for (int i = 0; i < 4; ++i)
#pragma unroll
        for (int j = 0; j < 4; ++j)
#pragma unroll
            for (int r = 0; r < 4; ++r) acc[i][j][r] = 0.f;

    uint4 rah, ral, rbh, rbl;
    auto gload = [&](int k0) {
        rah = *(const uint4*)(Abh + k0);
        ral = *(const uint4*)(Abl + k0);
        int k = k0 + bk;
        int ci, dy, dx;
        if (k < 2304) {
            ci = k / 9;
            int tap = k - ci * 9;
            int r = tap / 3;
            dy = r - 1;
            dx = tap - r * 3 - 1;
        } else { ci = k - 2304; dy = 0; dx = 0; }
        int hh = h + dy;
        bool hok = (hh >= 0) && (hh < 256);
        const uint32_t* row = g_yhl + ((size_t)(b * 256 + ci) << 16) + hh * 256;
        uint32_t v[8];
#pragma unroll
        for (int j = 0; j < 8; ++j) {
            int ww = w0 + bn + j + dx;
            v[j] = (hok && ww >= 0 && ww < 256) ? row[ww] : 0u;
        }
        uint32_t* ph = (uint32_t*)&rbh;
        uint32_t* pl = (uint32_t*)&rbl;
#pragma unroll
        for (int j = 0; j < 4; ++j) {
            ph[j] = __byte_perm(v[2 * j], v[2 * j + 1], 0x7632);
            pl[j] = __byte_perm(v[2 * j], v[2 * j + 1], 0x5410);
        }
    };
    auto sstore = [&](int s) {
        *(uint4*)(AhS[s] + aoff) = rah;
        *(uint4*)(AlS[s] + aoff) = ral;
        *(uint4*)(BhS[s] + boff) = rbh;
        *(uint4*)(BlS[s] + boff) = rbl;
    };

    const int nch = 160;
    gload(0);
    sstore(0);
    gload(16);
    __syncthreads();

    for (int ch = 0; ch < nch; ++ch) {
        if (ch + 1 < nch) sstore((ch + 1) & 1);
        if (ch + 2 < nch) gload((ch + 2) << 4);
        int s = ch & 1;
        mma_step(smem_u32(AhS[s]), smem_u32(AlS[s]),
                 smem_u32(BhS[s]), smem_u32(BlS[s]), wm, wn, lane, acc);
        __syncthreads();
    }

    int g = lane >> 2, tig = lane & 3;
#pragma unroll
    for (int mt = 0; mt < 4; ++mt) {
        int r0 = m0 + wm + mt * 16 + g;
        float bi0 = g_biasc[r0];
        float bi1 = g_biasc[r0 + 8];
#pragma unroll
        for (int j = 0; j < 4; ++j) {
            int col = p0 + wn + j * 8 + tig * 2;
            size_t i0 = ((size_t)(b * 256 + r0) << 16) + col;
            size_t i1 = ((size_t)(b * 256 + r0 + 8) << 16) + col;
            *(float2*)&g_local[i0] = make_float2(acc[mt][j][0] + bi0, acc[mt][j][1] + bi0);
            *(float2*)&g_local[i1] = make_float2(acc[mt][j][2] + bi1, acc[mt][j][3] + bi1);
        }
    }
}

// ---------------------------------------------------------------------------
// Windowed attention (qkv window-major; q pre-scaled in weights)
// ---------------------------------------------------------------------------
__global__ __launch_bounds__(64) void attn_kernel(const float* __restrict__ rpb)
{
    int win  = blockIdx.x;
    int head = blockIdx.y;
    int b  = win >> 10;
    int wloc = win & 1023;
    int i  = threadIdx.x;
    int yi = i >> 3, xi = i & 7;
    int pp = wloc * 64 + i;

    __shared__ float ks[64][16];
    __shared__ float vs[64][16];
    __shared__ float rpbs[225];

    for (int t = i; t < 225; t += 64) rpbs[t] = rpb[t * 16 + head];

    size_t base = ((size_t)(b * 768 + head * 16) << 16) + pp;
    float q[16];
#pragma unroll
    for (int d = 0; d < 16; ++d) {
        q[d]     = g_qkv[base + ((size_t)d << 16)];
        ks[i][d] = g_qkv[base + ((size_t)(256 + d) << 16)];
        vs[i][d] = g_qkv[base + ((size_t)(512 + d) << 16)];
    }
    __syncthreads();

    float m_run = -1e30f, l_run = 0.f;
    float o[16];
#pragma unroll
    for (int d = 0; d < 16; ++d) o[d] = 0.f;

#pragma unroll
    for (int cchunk = 0; cchunk < 4; ++cchunk) {
        float s[16];
        float cm = -1e30f;
#pragma unroll
        for (int jj = 0; jj < 16; ++jj) {
            int j = cchunk * 16 + jj;
            const float4* kp = (const float4*)ks[j];
            float4 k0 = kp[0], k1 = kp[1], k2 = kp[2], k3 = kp[3];
            float acc = q[0] * k0.x + q[1] * k0.y + q[2] * k0.z + q[3] * k0.w
                      + q[4] * k1.x + q[5] * k1.y + q[6] * k1.z + q[7] * k1.w
                      + q[8] * k2.x + q[9] * k2.y + q[10] * k2.z + q[11] * k2.w
                      + q[12] * k3.x + q[13] * k3.y + q[14] * k3.z + q[15] * k3.w;
            int yj = j >> 3, xj = j & 7;
            acc += rpbs[(yi - yj + 7) * 15 + (xi - xj + 7)];
            s[jj] = acc;
            cm = fmaxf(cm, acc);
        }
        float mnew = fmaxf(m_run, cm);
        float corr = __expf(m_run - mnew);
        l_run *= corr;
#pragma unroll
        for (int d = 0; d < 16; ++d) o[d] *= corr;
#pragma unroll
        for (int jj = 0; jj < 16; ++jj) {
            int j = cchunk * 16 + jj;
            float pj = __expf(s[jj] - mnew);
            l_run += pj;
            const float4* vp = (const float4*)vs[j];
            float4 v0 = vp[0], v1 = vp[1], v2 = vp[2], v3 = vp[3];
            o[0]  += pj * v0.x; o[1]  += pj * v0.y; o[2]  += pj * v0.z; o[3]  += pj * v0.w;
            o[4]  += pj * v1.x; o[5]  += pj * v1.y; o[6]  += pj * v1.z; o[7]  += pj * v1.w;
            o[8]  += pj * v2.x; o[9]  += pj * v2.y; o[10] += pj * v2.z; o[11] += pj * v2.w;
            o[12] += pj * v3.x; o[13] += pj * v3.y; o[14] += pj * v3.z; o[15] += pj * v3.w;
        }
        m_run = mnew;
    }
    float inv = 1.f / l_run;

    int wy = wloc >> 5, wx = wloc & 31;
    int p  = ((wy * 8 + yi) << 8) + wx * 8 + xi;
#pragma unroll
    for (int d = 0; d < 16; ++d)
        g_attn[((size_t)(b * 256 + head * 16 + d) << 16) + p] = o[d] * inv;
}

// ---------------------------------------------------------------------------
// mid = avgpool_v(attn) + avgpool_h(attn) + local
// ---------------------------------------------------------------------------
__global__ void pool_add_kernel()
{
    int bc = blockIdx.x >> 8;
    int h  = blockIdx.x & 255;
    int w  = threadIdx.x;
    const float* plane = g_attn + ((size_t)bc << 16);

    float sx = 0.f;
#pragma unroll
    for (int t = h - 3; t <= h + 4; ++t) {
        if (t >= 0 && t <= 256) {
            int tt = (t == 256) ? 254 : t;
            sx += plane[tt * 256 + w];
        }
    }
    const float* row = plane + h * 256;
    float sy = 0.f;
#pragma unroll
    for (int t = w - 3; t <= w + 4; ++t) {
        if (t >= 0 && t <= 256) {
            int tt = (t == 256) ? 254 : t;
            sy += row[tt];
        }
    }
    size_t idx = ((size_t)bc << 16) + h * 256 + w;
    g_mid[idx] = (sx + sy) * 0.125f + g_local[idx];
}

// ---------------------------------------------------------------------------
// Depthwise 8x8 conv + BN, output pre-split to bf16 hi/lo
// ---------------------------------------------------------------------------
__global__ __launch_bounds__(256) void dwconv_kernel(const float* __restrict__ w_dw)
{
    __shared__ float tile[39 * 40];
    __shared__ float ws[64];

    int tix = blockIdx.x;
    int bc  = blockIdx.y;
    int c   = bc & 255;
    int ty0 = (tix >> 3) * 32;
    int tx0 = (tix & 7) * 32;
    int tid = threadIdx.x;

    const float* plane = g_mid + ((size_t)bc << 16);

    for (int idx = tid; idx < 39 * 39; idx += 256) {
        int r  = idx / 39;
        int cc = idx - r * 39;
        int gh = ty0 - 3 + r;
        int gw = tx0 - 3 + cc;
        float v = 0.f;
        if (gh >= 0 && gh <= 256 && gw >= 0 && gw <= 256) {
            int ih = (gh == 256) ? 254 : gh;
            int iw = (gw == 256) ? 254 : gw;
            v = plane[ih * 256 + iw];
        }
        tile[r * 40 + cc] = v;
    }
    if (tid < 64) ws[tid] = w_dw[c * 64 + tid];
    __syncthreads();

    int lw  = tid & 31;
    int lh0 = (tid >> 5) * 4;
    float acc[4] = {0.f, 0.f, 0.f, 0.f};
#pragma unroll
    for (int j = 0; j < 8; ++j) {
        float wcol[8];
#pragma unroll
        for (int i = 0; i < 8; ++i) wcol[i] = ws[i * 8 + j];
#pragma unroll
        for (int r = 0; r < 11; ++r) {
            float v = tile[(lh0 + r) * 40 + lw + j];
#pragma unroll
            for (int a = 0; a < 4; ++a) {
                int i = r - a;
                if (i >= 0 && i < 8) acc[a] += v * wcol[i];
            }
        }
    }
    float ip = g_invp[c];
    float bb = g_biasp[c];
#pragma unroll
    for (int a = 0; a < 4; ++a) {
        int h = ty0 + lh0 + a;
        float r = acc[a] * ip + bb;
        unsigned short hh, ll;
        splt(r, hh, ll);
        size_t idx = ((size_t)bc << 16) + h * 256 + tx0 + lw;
        g_dwhi[idx] = hh;
        g_dwlo[idx] = ll;
    }
}

// ---------------------------------------------------------------------------
// Launch
// ---------------------------------------------------------------------------
extern "C" void kernel_launch(void* const* d_in, const int* in_sizes, int n_in,
                              void* d_out, int out_size)
{
    const float* x    = (const float*)d_in[0];
    const float* y    = (const float*)d_in[1];
    const float* wqkv = (const float*)d_in[2];
    const float* wl1  = (const float*)d_in[3];
    const float* g1   = (const float*)d_in[4];
    const float* b1   = (const float*)d_in[5];
    const float* m1   = (const float*)d_in[6];
    const float* v1   = (const float*)d_in[7];
    const float* wl2  = (const float*)d_in[8];
    const float* g2   = (const float*)d_in[9];
    const float* b2   = (const float*)d_in[10];
    const float* m2   = (const float*)d_in[11];
    const float* v2   = (const float*)d_in[12];
    const float* wdw  = (const float*)d_in[13];
    const float* gp   = (const float*)d_in[14];
    const float* bp   = (const float*)d_in[15];
    const float* mp   = (const float*)d_in[16];
    const float* vp   = (const float*)d_in[17];
    const float* wpw  = (const float*)d_in[18];
    const float* rpb  = (const float*)d_in[19];
    float* out = (float*)d_out;

    prep_kernel<<<1, 256>>>(g1, b1, m1, v1, g2, b2, m2, v2, gp, bp, mp, vp);
    split_wqkv<<<768, 256>>>(wqkv);
    split_wpw<<<256, 256>>>(wpw);
    split_wlocal<<<2560, 256>>>(wl1, wl2);
    split_x<<<32768, 256>>>(x);
    split_y<<<32768, 256>>>(y);

    // local branch (K=2560) -> g_local
    gemm_local_bf16<<<dim3(2, 1024), 256>>>();

    // qkv (M=768, K=256) -> g_qkv (window-major)
    gemm_aligned<<<dim3(6, 1024), 256>>>(nullptr, 768, 256, 0);

    attn_kernel<<<dim3(2048, 16), 64>>>(rpb);

    pool_add_kernel<<<512 * 256, 256>>>();

    dwconv_kernel<<<dim3(64, 512), 256>>>(wdw);

    // pointwise (M=256, K=256) -> out
    gemm_aligned<<<dim3(2, 1024), 256>>>(out, 256, 256, 1);
}

// round 9
// speedup vs baseline: 2.0235x; 1.0075x over previous
#include <cuda_runtime.h>
#include <cuda_bf16.h>
#include <math.h>
#include <stdint.h>

// ---------------------------------------------------------------------------
// Problem constants: B=2, C=256, H=W=256, SSM=256, NH=16, HD=16, WS=8
// ---------------------------------------------------------------------------
#define PPLANE 65536
#define NBATCH 2

typedef unsigned long long u64;

__device__ float g_local[NBATCH * 256 * PPLANE];
__device__ float g_qkv  [NBATCH * 768 * PPLANE];   // window-major pixel layout
__device__ float g_attn [NBATCH * 256 * PPLANE];

// pre-split bf16 operands
__device__ unsigned short g_xhi [NBATCH * 256 * PPLANE];
__device__ unsigned short g_xlo [NBATCH * 256 * PPLANE];
__device__ uint32_t       g_yhl [NBATCH * 256 * PPLANE];   // (hi<<16)|lo
__device__ unsigned short g_dwhi[NBATCH * 256 * PPLANE];
__device__ unsigned short g_dwlo[NBATCH * 256 * PPLANE];
__device__ unsigned short g_wqh [768 * 256], g_wql [768 * 256];
__device__ unsigned short g_wph [256 * 256], g_wpl [256 * 256];
__device__ unsigned short g_wlh [256 * 2560], g_wll [256 * 2560];

__device__ float g_inv1[256], g_inv2[256], g_biasc[256], g_invp[256], g_biasp[256];

// ---------------------------------------------------------------------------
// helpers
// ---------------------------------------------------------------------------
__device__ __forceinline__ uint32_t smem_u32(const void* p) {
    uint32_t a;
    asm("{ .reg .u64 t; cvta.to.shared.u64 t, %1; cvt.u32.u64 %0, t; }"
        : "=r"(a) : "l"(p));
    return a;
}
__device__ __forceinline__ void splt(float v, unsigned short& h, unsigned short& l) {
    __nv_bfloat16 hb = __float2bfloat16_rn(v);
    float r = v - __bfloat162float(hb);
    __nv_bfloat16 lb = __float2bfloat16_rn(r);
    h = *reinterpret_cast<unsigned short*>(&hb);
    l = *reinterpret_cast<unsigned short*>(&lb);
}
__device__ __forceinline__ void ldsm4(uint32_t* r, uint32_t a) {
    asm volatile("ldmatrix.sync.aligned.m8n8.x4.shared.b16 {%0,%1,%2,%3},[%4];"
                 : "=r"(r[0]), "=r"(r[1]), "=r"(r[2]), "=r"(r[3]) : "r"(a));
}
__device__ __forceinline__ void ldsm4t(uint32_t* r, uint32_t a) {
    asm volatile("ldmatrix.sync.aligned.m8n8.x4.trans.shared.b16 {%0,%1,%2,%3},[%4];"
                 : "=r"(r[0]), "=r"(r[1]), "=r"(r[2]), "=r"(r[3]) : "r"(a));
}
__device__ __forceinline__ void mma16(float* c, const uint32_t* a, const uint32_t* b) {
    asm volatile(
        "mma.sync.aligned.m16n8k16.row.col.f32.bf16.bf16.f32 "
        "{%0,%1,%2,%3},{%4,%5,%6,%7},{%8,%9},{%0,%1,%2,%3};"
        : "+f"(c[0]), "+f"(c[1]), "+f"(c[2]), "+f"(c[3])
        : "r"(a[0]), "r"(a[1]), "r"(a[2]), "r"(a[3]), "r"(b[0]), "r"(b[1]));
}

// f32x2 packed math (attention)
__device__ __forceinline__ u64 pack2(float a, float b) {
    u64 r;
    asm("mov.b64 %0, {%1, %2};" : "=l"(r) : "f"(a), "f"(b));
    return r;
}
__device__ __forceinline__ u64 dup2(float x) {
    u64 r;
    asm("mov.b64 %0, {%1, %1};" : "=l"(r) : "f"(x));
    return r;
}
__device__ __forceinline__ void ffma2(u64& d, u64 a, u64 b) {
    asm("fma.rn.f32x2 %0, %1, %2, %0;" : "+l"(d) : "l"(a), "l"(b));
}
__device__ __forceinline__ u64 mul2(u64 a, u64 b) {
    u64 d;
    asm("mul.rn.f32x2 %0, %1, %2;" : "=l"(d) : "l"(a), "l"(b));
    return d;
}
__device__ __forceinline__ void unpack2(u64 v, float& a, float& b) {
    asm("mov.b64 {%0, %1}, %2;" : "=f"(a), "=f"(b) : "l"(v));
}

#define ASTRIDE 48
#define BSTRIDE 272
#define ABYTES (128 * ASTRIDE)
#define BBYTES (16 * BSTRIDE)

__device__ __forceinline__ int perm_px(int p) {
    int h = p >> 8, w = p & 255;
    return (((h >> 3) * 32 + (w >> 3)) << 6) + ((h & 7) << 3) + (w & 7);
}

// ---------------------------------------------------------------------------
// Prep kernels
// ---------------------------------------------------------------------------
__global__ void prep_kernel(const float* __restrict__ g1, const float* __restrict__ b1,
                            const float* __restrict__ m1, const float* __restrict__ v1,
                            const float* __restrict__ g2, const float* __restrict__ b2,
                            const float* __restrict__ m2, const float* __restrict__ v2,
                            const float* __restrict__ gp, const float* __restrict__ bp,
                            const float* __restrict__ mp, const float* __restrict__ vp)
{
    int c = threadIdx.x;
    float i1 = g1[c] * rsqrtf(v1[c] + 1e-5f);
    float i2 = g2[c] * rsqrtf(v2[c] + 1e-5f);
    g_inv1[c] = i1;
    g_inv2[c] = i2;
    g_biasc[c] = (b1[c] - m1[c] * i1) + (b2[c] - m2[c] * i2);
    float ip = gp[c] * rsqrtf(vp[c] + 1e-5f);
    g_invp[c] = ip;
    g_biasp[c] = bp[c] - mp[c] * ip;
}

__global__ void split_wqkv(const float* __restrict__ w)
{
    int i = blockIdx.x * 256 + threadIdx.x;
    if (i >= 768 * 256) return;
    float sc = (i < 256 * 256) ? 0.25f : 1.0f;
    splt(w[i] * sc, g_wqh[i], g_wql[i]);
}
__global__ void split_wpw(const float* __restrict__ w)
{
    int i = blockIdx.x * 256 + threadIdx.x;
    splt(w[i], g_wph[i], g_wpl[i]);
}
__global__ void split_wlocal(const float* __restrict__ w1, const float* __restrict__ w2)
{
    int i = blockIdx.x * 256 + threadIdx.x;
    if (i >= 256 * 2560) return;
    int m = i / 2560, k = i - m * 2560;
    float v = (k < 2304) ? w1[m * 2304 + k] * g_inv1[m]
                         : w2[m * 256 + (k - 2304)] * g_inv2[m];
    splt(v, g_wlh[i], g_wll[i]);
}
__global__ void split_x(const float* __restrict__ x)
{
    size_t i4 = (size_t)blockIdx.x * 256 + threadIdx.x;
    size_t base = i4 * 4;
    float4 v = *(const float4*)(x + base);
    unsigned short h[4], l[4];
    splt(v.x, h[0], l[0]); splt(v.y, h[1], l[1]);
    splt(v.z, h[2], l[2]); splt(v.w, h[3], l[3]);
    *(uint2*)(g_xhi + base) = *(uint2*)h;
    *(uint2*)(g_xlo + base) = *(uint2*)l;
}
__global__ void split_y(const float* __restrict__ y)
{
    size_t i4 = (size_t)blockIdx.x * 256 + threadIdx.x;
    size_t base = i4 * 4;
    float4 v = *(const float4*)(y + base);
    uint32_t o[4];
    unsigned short h, l;
    splt(v.x, h, l); o[0] = ((uint32_t)h << 16) | l;
    splt(v.y, h, l); o[1] = ((uint32_t)h << 16) | l;
    splt(v.z, h, l); o[2] = ((uint32_t)h << 16) | l;
    splt(v.w, h, l); o[3] = ((uint32_t)h << 16) | l;
    *(uint4*)(g_yhl + base) = *(uint4*)o;
}

// ---------------------------------------------------------------------------
// Consumer: one K=16 step (3-pass split-bf16)
// ---------------------------------------------------------------------------
__device__ __forceinline__ void mma_step(
    uint32_t sAh, uint32_t sAl, uint32_t sBh, uint32_t sBl,
    int wm, int wn, int lane, float acc[4][4][4])
{
    int t  = lane >> 3;
    int r8 = lane & 7;
    uint32_t bh[4][2], bl[4][2];
#pragma unroll
    for (int ng = 0; ng < 2; ++ng) {
        uint32_t addr = ((t >> 1) * 8 + r8) * BSTRIDE + (wn + ng * 16 + (t & 1) * 8) * 2;
        uint32_t tb[4];
        ldsm4t(tb, sBh + addr);
        bh[ng * 2 + 0][0] = tb[0]; bh[ng * 2 + 0][1] = tb[2];
        bh[ng * 2 + 1][0] = tb[1]; bh[ng * 2 + 1][1] = tb[3];
        ldsm4t(tb, sBl + addr);
        bl[ng * 2 + 0][0] = tb[0]; bl[ng * 2 + 0][1] = tb[2];
        bl[ng * 2 + 1][0] = tb[1]; bl[ng * 2 + 1][1] = tb[3];
    }
    uint32_t abase = ((t & 1) * 8 + r8) * ASTRIDE + (t >> 1) * 16;
#pragma unroll
    for (int mt = 0; mt < 4; ++mt) {
        uint32_t arow = abase + (wm + mt * 16) * ASTRIDE;
        uint32_t ah[4], al[4];
        ldsm4(ah, sAh + arow);
#pragma unroll
        for (int j = 0; j < 4; ++j) mma16(acc[mt][j], ah, bh[j]);
#pragma unroll
        for (int j = 0; j < 4; ++j) mma16(acc[mt][j], ah, bl[j]);
        ldsm4(al, sAl + arow);
#pragma unroll
        for (int j = 0; j < 4; ++j) mma16(acc[mt][j], al, bh[j]);
    }
}

// ---------------------------------------------------------------------------
// Aligned GEMM (pre-split bf16 A and B), operands resolved DEVICE-SIDE.
//   which==0: A = wqkv (M=768,K=256), B = x,  C = g_qkv (permuted cols)
//   which==1: A = wpw  (M=256,K=256), B = dw, C = extC
// grid = (M/128, 1024)
// ---------------------------------------------------------------------------
__global__ __launch_bounds__(256, 2) void gemm_aligned(float* extC, int M, int K, int which)
{
    __shared__ __align__(16) char AhS[2][ABYTES];
    __shared__ __align__(16) char AlS[2][ABYTES];
    __shared__ __align__(16) char BhS[2][BBYTES];
    __shared__ __align__(16) char BlS[2][BBYTES];

    const unsigned short *Ah_g, *Al_g, *Bh_g, *Bl_g;
    float* C;
    if (which == 0) {
        Ah_g = g_wqh; Al_g = g_wql; Bh_g = g_xhi; Bl_g = g_xlo; C = (float*)g_qkv;
    } else {
        Ah_g = g_wph; Al_g = g_wpl; Bh_g = g_dwhi; Bl_g = g_dwlo; C = extC;
    }

    int tid = threadIdx.x;
    int m0  = blockIdx.x * 128;
    int pg0 = blockIdx.y * 128;
    int b   = pg0 >> 16;
    int p0  = pg0 & 65535;
    int lane = tid & 31, warp = tid >> 5;
    int wm = (warp >> 2) * 64, wn = (warp & 3) * 32;

    int am = tid >> 1, ak = (tid & 1) * 8;
    const unsigned short* Abh = Ah_g + (size_t)(m0 + am) * K + ak;
    const unsigned short* Abl = Al_g + (size_t)(m0 + am) * K + ak;
    int bk = tid >> 4, bn = (tid & 15) * 8;
    size_t bbase = ((size_t)(b * K + bk) << 16) + p0 + bn;

    int aoff = am * ASTRIDE + ak * 2;
    int boff = bk * BSTRIDE + bn * 2;

    float acc[4][4][4];
#pragma unroll
    for (int i = 0; i < 4; ++i)
#pragma unroll
        for (int j = 0; j < 4; ++j)
#pragma unroll
            for (int r = 0; r < 4; ++r) acc[i][j][r] = 0.f;

    uint4 rah, ral, rbh, rbl;
    auto gload = [&](int k0) {
        rah = *(const uint4*)(Abh + k0);
        ral = *(const uint4*)(Abl + k0);
        rbh = *(const uint4*)(Bh_g + bbase + ((size_t)k0 << 16));
        rbl = *(const uint4*)(Bl_g + bbase + ((size_t)k0 << 16));
    };
    auto sstore = [&](int s) {
        *(uint4*)(AhS[s] + aoff) = rah;
        *(uint4*)(AlS[s] + aoff) = ral;
        *(uint4*)(BhS[s] + boff) = rbh;
        *(uint4*)(BlS[s] + boff) = rbl;
    };

    int nch = K >> 4;
    gload(0);
    sstore(0);
    if (nch > 1) gload(16);
    __syncthreads();

    for (int ch = 0; ch < nch; ++ch) {
        if (ch + 1 < nch) sstore((ch + 1) & 1);
        if (ch + 2 < nch) gload((ch + 2) << 4);
        int s = ch & 1;
        mma_step(smem_u32(AhS[s]), smem_u32(AlS[s]),
                 smem_u32(BhS[s]), smem_u32(BlS[s]), wm, wn, lane, acc);
        __syncthreads();
    }

    int g = lane >> 2, tig = lane & 3;
#pragma unroll
    for (int mt = 0; mt < 4; ++mt) {
        int r0 = m0 + wm + mt * 16 + g;
#pragma unroll
        for (int j = 0; j < 4; ++j) {
            int col = p0 + wn + j * 8 + tig * 2;
            int pc = (which == 0) ? perm_px(col) : col;
            size_t i0 = ((size_t)(b * M + r0) << 16) + pc;
            size_t i1 = ((size_t)(b * M + r0 + 8) << 16) + pc;
            *(float2*)&C[i0] = make_float2(acc[mt][j][0], acc[mt][j][1]);
            *(float2*)&C[i1] = make_float2(acc[mt][j][2], acc[mt][j][3]);
        }
    }
}

// ---------------------------------------------------------------------------
// Fused local branch GEMM, K=2560, B gathered from interleaved g_yhl.
// grid = (2, 1024)
// ---------------------------------------------------------------------------
__global__ __launch_bounds__(256, 2) void gemm_local_bf16(void)
{
    __shared__ __align__(16) char AhS[2][ABYTES];
    __shared__ __align__(16) char AlS[2][ABYTES];
    __shared__ __align__(16) char BhS[2][BBYTES];
    __shared__ __align__(16) char BlS[2][BBYTES];

    int tid = threadIdx.x;
    int m0  = blockIdx.x * 128;
    int pg0 = blockIdx.y * 128;
    int b   = pg0 >> 16;
    int p0  = pg0 & 65535;
    int h   = p0 >> 8;
    int w0  = p0 & 255;
    int lane = tid & 31, warp = tid >> 5;
    int wm = (warp >> 2) * 64, wn = (warp & 3) * 32;

    int am = tid >> 1, ak = (tid & 1) * 8;
    int mg = m0 + am;
    int bk = tid >> 4, bn = (tid & 15) * 8;

    int aoff = am * ASTRIDE + ak * 2;
    int boff = bk * BSTRIDE + bn * 2;

    const unsigned short* Abh = g_wlh + (size_t)mg * 2560 + ak;
    const unsigned short* Abl = g_wll + (size_t)mg * 2560 + ak;

    float acc[4][4][4];
#pragma unroll
    for (int i = 0; i < 4; ++i)
#pragma unroll
        for (int j = 0; j < 4; ++j)
#pragma unroll
            for (int r = 0; r < 4; ++r) acc[i][j][r] = 0.f;

    uint4 rah, ral, rbh, rbl;
    auto gload = [&](int k0) {
        rah = *(const uint4*)(Abh + k0);
        ral = *(const uint4*)(Abl + k0);
        int k = k0 + bk;
        int ci, dy, dx;
        if (k < 2304) {
            ci = k / 9;
            int tap = k - ci * 9;
            int r = tap / 3;
            dy = r - 1;
            dx = tap - r * 3 - 1;
        } else { ci = k - 2304; dy = 0; dx = 0; }
        int hh = h + dy;
        bool hok = (hh >= 0) && (hh < 256);
        const uint32_t* row = g_yhl + ((size_t)(b * 256 + ci) << 16) + hh * 256;
        uint32_t v[8];
#pragma unroll
        for (int j = 0; j < 8; ++j) {
            int ww = w0 + bn + j + dx;
            v[j] = (hok && ww >= 0 && ww < 256) ? row[ww] : 0u;
        }
        uint32_t* ph = (uint32_t*)&rbh;
        uint32_t* pl = (uint32_t*)&rbl;
#pragma unroll
        for (int j = 0; j < 4; ++j) {
            ph[j] = __byte_perm(v[2 * j], v[2 * j + 1], 0x7632);
            pl[j] = __byte_perm(v[2 * j], v[2 * j + 1], 0x5410);
        }
    };
    auto sstore = [&](int s) {
        *(uint4*)(AhS[s] + aoff) = rah;
        *(uint4*)(AlS[s] + aoff) = ral;
        *(uint4*)(BhS[s] + boff) = rbh;
        *(uint4*)(BlS[s] + boff) = rbl;
    };

    const int nch = 160;
    gload(0);
    sstore(0);
    gload(16);
    __syncthreads();

    for (int ch = 0; ch < nch; ++ch) {
        if (ch + 1 < nch) sstore((ch + 1) & 1);
        if (ch + 2 < nch) gload((ch + 2) << 4);
        int s = ch & 1;
        mma_step(smem_u32(AhS[s]), smem_u32(AlS[s]),
                 smem_u32(BhS[s]), smem_u32(BlS[s]), wm, wn, lane, acc);
        __syncthreads();
    }

    int g = lane >> 2, tig = lane & 3;
#pragma unroll
    for (int mt = 0; mt < 4; ++mt) {
        int r0 = m0 + wm + mt * 16 + g;
        float bi0 = g_biasc[r0];
        float bi1 = g_biasc[r0 + 8];
#pragma unroll
        for (int j = 0; j < 4; ++j) {
            int col = p0 + wn + j * 8 + tig * 2;
            size_t i0 = ((size_t)(b * 256 + r0) << 16) + col;
            size_t i1 = ((size_t)(b * 256 + r0 + 8) << 16) + col;
            *(float2*)&g_local[i0] = make_float2(acc[mt][j][0] + bi0, acc[mt][j][1] + bi0);
            *(float2*)&g_local[i1] = make_float2(acc[mt][j][2] + bi1, acc[mt][j][3] + bi1);
        }
    }
}

// ---------------------------------------------------------------------------
// Windowed attention: packed f32x2 math, 2 windows x 1 head per block.
// qkv is window-major; q pre-scaled in weights.
// ---------------------------------------------------------------------------
__global__ __launch_bounds__(128) void attn_kernel(const float* __restrict__ rpb)
{
    int w2   = threadIdx.x >> 6;          // window slot in block
    int i    = threadIdx.x & 63;          // token
    int win  = blockIdx.x * 2 + w2;       // 0..2047
    int head = blockIdx.y;
    int b    = win >> 10;
    int wloc = win & 1023;
    int yi = i >> 3, xi = i & 7;
    int pp = wloc * 64 + i;

    __shared__ u64 ks2[2][64][8];
    __shared__ u64 vs2[2][64][8];
    __shared__ float rpbs[225];

    for (int t = threadIdx.x; t < 225; t += 128) rpbs[t] = rpb[t * 16 + head];

    size_t base = ((size_t)(b * 768 + head * 16) << 16) + pp;
    u64 q2[8];
#pragma unroll
    for (int d = 0; d < 8; ++d) {
        float q0 = g_qkv[base + ((size_t)(2 * d) << 16)];
        float q1 = g_qkv[base + ((size_t)(2 * d + 1) << 16)];
        q2[d] = pack2(q0, q1);
        float k0 = g_qkv[base + ((size_t)(256 + 2 * d) << 16)];
        float k1 = g_qkv[base + ((size_t)(256 + 2 * d + 1) << 16)];
        ks2[w2][i][d] = pack2(k0, k1);
        float v0 = g_qkv[base + ((size_t)(512 + 2 * d) << 16)];
        float v1 = g_qkv[base + ((size_t)(512 + 2 * d + 1) << 16)];
        vs2[w2][i][d] = pack2(v0, v1);
    }
    __syncthreads();

    float m_run = -1e30f, l_run = 0.f;
    u64 o2[8];
#pragma unroll
    for (int d = 0; d < 8; ++d) o2[d] = 0ULL;

#pragma unroll
    for (int cchunk = 0; cchunk < 4; ++cchunk) {
        float s[16];
        float cm = -1e30f;
#pragma unroll
        for (int jj = 0; jj < 16; ++jj) {
            int j = cchunk * 16 + jj;
            u64 a2 = 0ULL;
            const u64* kj = ks2[w2][j];
#pragma unroll
            for (int d = 0; d < 8; ++d) ffma2(a2, q2[d], kj[d]);
            float lo, hi;
            unpack2(a2, lo, hi);
            int yj = j >> 3, xj = j & 7;
            float sc = lo + hi + rpbs[(yi - yj + 7) * 15 + (xi - xj + 7)];
            s[jj] = sc;
            cm = fmaxf(cm, sc);
        }
        float mnew = fmaxf(m_run, cm);
        float corr = __expf(m_run - mnew);
        l_run *= corr;
        u64 c2 = dup2(corr);
#pragma unroll
        for (int d = 0; d < 8; ++d) o2[d] = mul2(o2[d], c2);
#pragma unroll
        for (int jj = 0; jj < 16; ++jj) {
            int j = cchunk * 16 + jj;
            float pj = __expf(s[jj] - mnew);
            l_run += pj;
            u64 p2 = dup2(pj);
            const u64* vj = vs2[w2][j];
#pragma unroll
            for (int d = 0; d < 8; ++d) ffma2(o2[d], p2, vj[d]);
        }
        m_run = mnew;
    }
    float inv = 1.f / l_run;

    int wy = wloc >> 5, wx = wloc & 31;
    int p  = (((wy * 8) + yi) << 8) + wx * 8 + xi;
#pragma unroll
    for (int d = 0; d < 8; ++d) {
        float lo, hi;
        unpack2(o2[d], lo, hi);
        g_attn[((size_t)(b * 256 + head * 16 + 2 * d) << 16) + p]     = lo * inv;
        g_attn[((size_t)(b * 256 + head * 16 + 2 * d + 1) << 16) + p] = hi * inv;
    }
}

// ---------------------------------------------------------------------------
// Fused pool + depthwise 8x8 conv + BN:
//   mid = avgpool_v(attn) + avgpool_h(attn) + local  (computed in smem),
//   then dw conv on reflect(+1)/zero-pad-3 mid, + BN, output split bf16 hi/lo.
// One block = one 32x32 output tile of one plane.
// ---------------------------------------------------------------------------
__global__ __launch_bounds__(256) void dwpool_kernel(const float* __restrict__ w_dw)
{
    __shared__ float attnS[46][48];
    __shared__ float midS[39][40];
    __shared__ float ws[64];

    int tix = blockIdx.x;           // 0..63
    int bc  = blockIdx.y;           // 0..511
    int c   = bc & 255;
    int ty0 = (tix >> 3) * 32;
    int tx0 = (tix & 7) * 32;
    int tid = threadIdx.x;

    const float* aplane = g_attn + ((size_t)bc << 16);
    const float* lplane = g_local + ((size_t)bc << 16);

    // attn halo 46x46: global rows ty0-6.., cols tx0-6.., zero outside [0,255]
    for (int idx = tid; idx < 46 * 46; idx += 256) {
        int r  = idx / 46;
        int cc = idx - r * 46;
        int gh = ty0 - 6 + r;
        int gw = tx0 - 6 + cc;
        float v = 0.f;
        if (gh >= 0 && gh < 256 && gw >= 0 && gw < 256) v = aplane[gh * 256 + gw];
        attnS[r][cc] = v;
    }
    if (tid < 64) ws[tid] = w_dw[c * 64 + tid];
    __syncthreads();

    // mid 39x39 at dw-input coords (ty0-3+r, tx0-3+c) with zero/reflect mapping
    for (int idx = tid; idx < 39 * 39; idx += 256) {
        int r  = idx / 39;
        int cc = idx - r * 39;
        int gh = ty0 - 3 + r;
        int gw = tx0 - 3 + cc;
        float v = 0.f;
        if (gh >= 0 && gh <= 256 && gw >= 0 && gw <= 256) {
            int gh2 = (gh == 256) ? 254 : gh;
            int gw2 = (gw == 256) ? 254 : gw;
            int co = gw2 - (tx0 - 6);
            float vs = 0.f;
#pragma unroll
            for (int t = gh2 - 3; t <= gh2 + 4; ++t) {
                if (t >= 0 && t <= 256) {
                    int tt = (t == 256) ? 254 : t;
                    vs += attnS[tt - (ty0 - 6)][co];
                }
            }
            int ro = gh2 - (ty0 - 6);
            float hs = 0.f;
#pragma unroll
            for (int s = gw2 - 3; s <= gw2 + 4; ++s) {
                if (s >= 0 && s <= 256) {
                    int ss = (s == 256) ? 254 : s;
                    hs += attnS[ro][ss - (tx0 - 6)];
                }
            }
            v = (vs + hs) * 0.125f + lplane[gh2 * 256 + gw2];
        }
        midS[r][cc] = v;
    }
    __syncthreads();

    int lw  = tid & 31;
    int lh0 = (tid >> 5) * 4;
    float acc[4] = {0.f, 0.f, 0.f, 0.f};
#pragma unroll
    for (int j = 0; j < 8; ++j) {
        float wcol[8];
#pragma unroll
        for (int i = 0; i < 8; ++i) wcol[i] = ws[i * 8 + j];
#pragma unroll
        for (int r = 0; r < 11; ++r) {
            float v = midS[lh0 + r][lw + j];
#pragma unroll
            for (int a = 0; a < 4; ++a) {
                int i = r - a;
                if (i >= 0 && i < 8) acc[a] += v * wcol[i];
            }
        }
    }
    float ip = g_invp[c];
    float bb = g_biasp[c];
#pragma unroll
    for (int a = 0; a < 4; ++a) {
        int h = ty0 + lh0 + a;
        float r = acc[a] * ip + bb;
        unsigned short hh, ll;
        splt(r, hh, ll);
        size_t idx = ((size_t)bc << 16) + h * 256 + tx0 + lw;
        g_dwhi[idx] = hh;
        g_dwlo[idx] = ll;
    }
}

// ---------------------------------------------------------------------------
// Launch
// ---------------------------------------------------------------------------
extern "C" void kernel_launch(void* const* d_in, const int* in_sizes, int n_in,
                              void* d_out, int out_size)
{
    const float* x    = (const float*)d_in[0];
    const float* y    = (const float*)d_in[1];
    const float* wqkv = (const float*)d_in[2];
    const float* wl1  = (const float*)d_in[3];
    const float* g1   = (const float*)d_in[4];
    const float* b1   = (const float*)d_in[5];
    const float* m1   = (const float*)d_in[6];
    const float* v1   = (const float*)d_in[7];
    const float* wl2  = (const float*)d_in[8];
    const float* g2   = (const float*)d_in[9];
    const float* b2   = (const float*)d_in[10];
    const float* m2   = (const float*)d_in[11];
    const float* v2   = (const float*)d_in[12];
    const float* wdw  = (const float*)d_in[13];
    const float* gp   = (const float*)d_in[14];
    const float* bp   = (const float*)d_in[15];
    const float* mp   = (const float*)d_in[16];
    const float* vp   = (const float*)d_in[17];
    const float* wpw  = (const float*)d_in[18];
    const float* rpb  = (const float*)d_in[19];
    float* out = (float*)d_out;

    prep_kernel<<<1, 256>>>(g1, b1, m1, v1, g2, b2, m2, v2, gp, bp, mp, vp);
    split_wqkv<<<768, 256>>>(wqkv);
    split_wpw<<<256, 256>>>(wpw);
    split_wlocal<<<2560, 256>>>(wl1, wl2);
    split_x<<<32768, 256>>>(x);
    split_y<<<32768, 256>>>(y);

    // local branch (K=2560) -> g_local
    gemm_local_bf16<<<dim3(2, 1024), 256>>>();

    // qkv (M=768, K=256) -> g_qkv (window-major)
    gemm_aligned<<<dim3(6, 1024), 256>>>(nullptr, 768, 256, 0);

    // attention (2 windows x 1 head per block)
    attn_kernel<<<dim3(1024, 16), 128>>>(rpb);

    // fused pools + depthwise conv + BN -> g_dwhi/g_dwlo
    dwpool_kernel<<<dim3(64, 512), 256>>>(wdw);

    // pointwise (M=256, K=256) -> out
    gemm_aligned<<<dim3(2, 1024), 256>>>(out, 256, 256, 1);
}

// round 10
// speedup vs baseline: 2.3983x; 1.1852x over previous
#include <cuda_runtime.h>
#include <cuda_fp16.h>
#include <math.h>
#include <stdint.h>

// ---------------------------------------------------------------------------
// Problem constants: B=2, C=256, H=W=256, SSM=256, NH=16, HD=16, WS=8
// ---------------------------------------------------------------------------
#define PPLANE 65536
#define NBATCH 2

typedef unsigned long long u64;
typedef unsigned short u16;

__device__ float g_local[NBATCH * 256 * PPLANE];
__device__ float g_qkv  [NBATCH * 768 * PPLANE];   // window-major pixel layout
__device__ float g_attn [NBATCH * 256 * PPLANE];

// pre-converted fp16 operands (weights split hi/lo; activations single fp16)
__device__ u16 g_xh [NBATCH * 256 * PPLANE];
__device__ u16 g_yh [NBATCH * 256 * PPLANE];
__device__ u16 g_dwh[NBATCH * 256 * PPLANE];
__device__ u16 g_wqh [768 * 256], g_wql [768 * 256];
__device__ u16 g_wph [256 * 256], g_wpl [256 * 256];
__device__ u16 g_wlh [256 * 2560], g_wll [256 * 2560];

__device__ float g_inv1[256], g_inv2[256], g_biasc[256], g_invp[256], g_biasp[256];

// ---------------------------------------------------------------------------
// helpers
// ---------------------------------------------------------------------------
__device__ __forceinline__ uint32_t smem_u32(const void* p) {
    uint32_t a;
    asm("{ .reg .u64 t; cvta.to.shared.u64 t, %1; cvt.u32.u64 %0, t; }"
        : "=r"(a) : "l"(p));
    return a;
}
__device__ __forceinline__ u16 h16(float v) {
    __half h = __float2half_rn(v);
    return *reinterpret_cast<u16*>(&h);
}
__device__ __forceinline__ void splt16(float v, u16& h, u16& l) {
    __half hb = __float2half_rn(v);
    float r = v - __half2float(hb);
    __half lb = __float2half_rn(r);
    h = *reinterpret_cast<u16*>(&hb);
    l = *reinterpret_cast<u16*>(&lb);
}
__device__ __forceinline__ void ldsm4(uint32_t* r, uint32_t a) {
    asm volatile("ldmatrix.sync.aligned.m8n8.x4.shared.b16 {%0,%1,%2,%3},[%4];"
                 : "=r"(r[0]), "=r"(r[1]), "=r"(r[2]), "=r"(r[3]) : "r"(a));
}
__device__ __forceinline__ void ldsm4t(uint32_t* r, uint32_t a) {
    asm volatile("ldmatrix.sync.aligned.m8n8.x4.trans.shared.b16 {%0,%1,%2,%3},[%4];"
                 : "=r"(r[0]), "=r"(r[1]), "=r"(r[2]), "=r"(r[3]) : "r"(a));
}
__device__ __forceinline__ void mma16(float* c, const uint32_t* a, const uint32_t* b) {
    asm volatile(
        "mma.sync.aligned.m16n8k16.row.col.f32.f16.f16.f32 "
        "{%0,%1,%2,%3},{%4,%5,%6,%7},{%8,%9},{%0,%1,%2,%3};"
        : "+f"(c[0]), "+f"(c[1]), "+f"(c[2]), "+f"(c[3])
        : "r"(a[0]), "r"(a[1]), "r"(a[2]), "r"(a[3]), "r"(b[0]), "r"(b[1]));
}

// f32x2 packed math (attention)
__device__ __forceinline__ u64 pack2(float a, float b) {
    u64 r;
    asm("mov.b64 %0, {%1, %2};" : "=l"(r) : "f"(a), "f"(b));
    return r;
}
__device__ __forceinline__ u64 dup2(float x) {
    u64 r;
    asm("mov.b64 %0, {%1, %1};" : "=l"(r) : "f"(x));
    return r;
}
__device__ __forceinline__ void ffma2(u64& d, u64 a, u64 b) {
    asm("fma.rn.f32x2 %0, %1, %2, %0;" : "+l"(d) : "l"(a), "l"(b));
}
__device__ __forceinline__ u64 mul2(u64 a, u64 b) {
    u64 d;
    asm("mul.rn.f32x2 %0, %1, %2;" : "=l"(d) : "l"(a), "l"(b));
    return d;
}
__device__ __forceinline__ void unpack2(u64 v, float& a, float& b) {
    asm("mov.b64 {%0, %1}, %2;" : "=f"(a), "=f"(b) : "l"(v));
}

#define ASTRIDE 48
#define BSTRIDE 272
#define ABYTES (128 * ASTRIDE)
#define BBYTES (16 * BSTRIDE)

__device__ __forceinline__ int perm_px(int p) {
    int h = p >> 8, w = p & 255;
    return (((h >> 3) * 32 + (w >> 3)) << 6) + ((h & 7) << 3) + (w & 7);
}

// ---------------------------------------------------------------------------
// Prep kernels
// ---------------------------------------------------------------------------
__global__ void prep_kernel(const float* __restrict__ g1, const float* __restrict__ b1,
                            const float* __restrict__ m1, const float* __restrict__ v1,
                            const float* __restrict__ g2, const float* __restrict__ b2,
                            const float* __restrict__ m2, const float* __restrict__ v2,
                            const float* __restrict__ gp, const float* __restrict__ bp,
                            const float* __restrict__ mp, const float* __restrict__ vp)
{
    int c = threadIdx.x;
    float i1 = g1[c] * rsqrtf(v1[c] + 1e-5f);
    float i2 = g2[c] * rsqrtf(v2[c] + 1e-5f);
    g_inv1[c] = i1;
    g_inv2[c] = i2;
    g_biasc[c] = (b1[c] - m1[c] * i1) + (b2[c] - m2[c] * i2);
    float ip = gp[c] * rsqrtf(vp[c] + 1e-5f);
    g_invp[c] = ip;
    g_biasp[c] = bp[c] - mp[c] * ip;
}

__global__ void split_wqkv(const float* __restrict__ w)
{
    int i = blockIdx.x * 256 + threadIdx.x;
    if (i >= 768 * 256) return;
    float sc = (i < 256 * 256) ? 0.25f : 1.0f;
    splt16(w[i] * sc, g_wqh[i], g_wql[i]);
}
__global__ void split_wpw(const float* __restrict__ w)
{
    int i = blockIdx.x * 256 + threadIdx.x;
    splt16(w[i], g_wph[i], g_wpl[i]);
}
__global__ void split_wlocal(const float* __restrict__ w1, const float* __restrict__ w2)
{
    int i = blockIdx.x * 256 + threadIdx.x;
    if (i >= 256 * 2560) return;
    int m = i / 2560, k = i - m * 2560;
    float v = (k < 2304) ? w1[m * 2304 + k] * g_inv1[m]
                         : w2[m * 256 + (k - 2304)] * g_inv2[m];
    splt16(v, g_wlh[i], g_wll[i]);
}
__global__ void cvt_x(const float* __restrict__ x)
{
    size_t base = ((size_t)blockIdx.x * 256 + threadIdx.x) * 4;
    float4 v = *(const float4*)(x + base);
    u16 h[4] = { h16(v.x), h16(v.y), h16(v.z), h16(v.w) };
    *(uint2*)(g_xh + base) = *(uint2*)h;
}
__global__ void cvt_y(const float* __restrict__ y)
{
    size_t base = ((size_t)blockIdx.x * 256 + threadIdx.x) * 4;
    float4 v = *(const float4*)(y + base);
    u16 h[4] = { h16(v.x), h16(v.y), h16(v.z), h16(v.w) };
    *(uint2*)(g_yh + base) = *(uint2*)h;
}

// ---------------------------------------------------------------------------
// Consumer: one K=16 step, 2-pass fp16 split: (Ah + Al) * B
// ---------------------------------------------------------------------------
__device__ __forceinline__ void mma_step(
    uint32_t sAh, uint32_t sAl, uint32_t sB,
    int wm, int wn, int lane, float acc[4][4][4])
{
    int t  = lane >> 3;
    int r8 = lane & 7;
    uint32_t bh[4][2];
#pragma unroll
    for (int ng = 0; ng < 2; ++ng) {
        uint32_t addr = ((t >> 1) * 8 + r8) * BSTRIDE + (wn + ng * 16 + (t & 1) * 8) * 2;
        uint32_t tb[4];
        ldsm4t(tb, sB + addr);
        bh[ng * 2 + 0][0] = tb[0]; bh[ng * 2 + 0][1] = tb[2];
        bh[ng * 2 + 1][0] = tb[1]; bh[ng * 2 + 1][1] = tb[3];
    }
    uint32_t abase = ((t & 1) * 8 + r8) * ASTRIDE + (t >> 1) * 16;
#pragma unroll
    for (int mt = 0; mt < 4; ++mt) {
        uint32_t arow = abase + (wm + mt * 16) * ASTRIDE;
        uint32_t ah[4], al[4];
        ldsm4(ah, sAh + arow);
#pragma unroll
        for (int j = 0; j < 4; ++j) mma16(acc[mt][j], ah, bh[j]);
        ldsm4(al, sAl + arow);
#pragma unroll
        for (int j = 0; j < 4; ++j) mma16(acc[mt][j], al, bh[j]);
    }
}

// ---------------------------------------------------------------------------
// Aligned GEMM (A split fp16 hi/lo, B single fp16), operands device-side.
//   which==0: A = wqkv (M=768,K=256), B = x,  C = g_qkv (permuted cols)
//   which==1: A = wpw  (M=256,K=256), B = dw, C = extC
// grid = (M/128, 1024)
// ---------------------------------------------------------------------------
__global__ __launch_bounds__(256, 2) void gemm_aligned(float* extC, int M, int K, int which)
{
    __shared__ __align__(16) char AhS[2][ABYTES];
    __shared__ __align__(16) char AlS[2][ABYTES];
    __shared__ __align__(16) char BS [2][BBYTES];

    const u16 *Ah_g, *Al_g, *B_g;
    float* C;
    if (which == 0) {
        Ah_g = g_wqh; Al_g = g_wql; B_g = g_xh; C = (float*)g_qkv;
    } else {
        Ah_g = g_wph; Al_g = g_wpl; B_g = g_dwh; C = extC;
    }

    int tid = threadIdx.x;
    int m0  = blockIdx.x * 128;
    int pg0 = blockIdx.y * 128;
    int b   = pg0 >> 16;
    int p0  = pg0 & 65535;
    int lane = tid & 31, warp = tid >> 5;
    int wm = (warp >> 2) * 64, wn = (warp & 3) * 32;

    int am = tid >> 1, ak = (tid & 1) * 8;
    const u16* Abh = Ah_g + (size_t)(m0 + am) * K + ak;
    const u16* Abl = Al_g + (size_t)(m0 + am) * K + ak;
    int bk = tid >> 4, bn = (tid & 15) * 8;
    size_t bbase = ((size_t)(b * K + bk) << 16) + p0 + bn;

    int aoff = am * ASTRIDE + ak * 2;
    int boff = bk * BSTRIDE + bn * 2;

    float acc[4][4][4];
#pragma unroll
    for (int i = 0; i < 4; ++i)
#pragma unroll
        for (int j = 0; j < 4; ++j)
#pragma unroll
            for (int r = 0; r < 4; ++r) acc[i][j][r] = 0.f;

    uint4 rah, ral, rb;
    auto gload = [&](int k0) {
        rah = *(const uint4*)(Abh + k0);
        ral = *(const uint4*)(Abl + k0);
        rb  = *(const uint4*)(B_g + bbase + ((size_t)k0 << 16));
    };
    auto sstore = [&](int s) {
        *(uint4*)(AhS[s] + aoff) = rah;
        *(uint4*)(AlS[s] + aoff) = ral;
        *(uint4*)(BS[s]  + boff) = rb;
    };

    int nch = K >> 4;
    gload(0);
    sstore(0);
    if (nch > 1) gload(16);
    __syncthreads();

    for (int ch = 0; ch < nch; ++ch) {
        if (ch + 1 < nch) sstore((ch + 1) & 1);
        if (ch + 2 < nch) gload((ch + 2) << 4);
        int s = ch & 1;
        mma_step(smem_u32(AhS[s]), smem_u32(AlS[s]), smem_u32(BS[s]),
                 wm, wn, lane, acc);
        __syncthreads();
    }

    int g = lane >> 2, tig = lane & 3;
#pragma unroll
    for (int mt = 0; mt < 4; ++mt) {
        int r0 = m0 + wm + mt * 16 + g;
#pragma unroll
        for (int j = 0; j < 4; ++j) {
            int col = p0 + wn + j * 8 + tig * 2;
            int pc = (which == 0) ? perm_px(col) : col;
            size_t i0 = ((size_t)(b * M + r0) << 16) + pc;
            size_t i1 = ((size_t)(b * M + r0 + 8) << 16) + pc;
            *(float2*)&C[i0] = make_float2(acc[mt][j][0], acc[mt][j][1]);
            *(float2*)&C[i1] = make_float2(acc[mt][j][2], acc[mt][j][3]);
        }
    }
}

// ---------------------------------------------------------------------------
// Fused local branch GEMM, K=2560, B gathered from fp16 g_yh.
// grid = (2, 1024)
// ---------------------------------------------------------------------------
__global__ __launch_bounds__(256, 2) void gemm_local_f16(void)
{
    __shared__ __align__(16) char AhS[2][ABYTES];
    __shared__ __align__(16) char AlS[2][ABYTES];
    __shared__ __align__(16) char BS [2][BBYTES];

    int tid = threadIdx.x;
    int m0  = blockIdx.x * 128;
    int pg0 = blockIdx.y * 128;
    int b   = pg0 >> 16;
    int p0  = pg0 & 65535;
    int h   = p0 >> 8;
    int w0  = p0 & 255;
    int lane = tid & 31, warp = tid >> 5;
    int wm = (warp >> 2) * 64, wn = (warp & 3) * 32;

    int am = tid >> 1, ak = (tid & 1) * 8;
    int mg = m0 + am;
    int bk = tid >> 4, bn = (tid & 15) * 8;

    int aoff = am * ASTRIDE + ak * 2;
    int boff = bk * BSTRIDE + bn * 2;

    const u16* Abh = g_wlh + (size_t)mg * 2560 + ak;
    const u16* Abl = g_wll + (size_t)mg * 2560 + ak;

    float acc[4][4][4];
#pragma unroll
    for (int i = 0; i < 4; ++i)
#pragma unroll
        for (int j = 0; j < 4; ++j)
#pragma unroll
            for (int r = 0; r < 4; ++r) acc[i][j][r] = 0.f;

    uint4 rah, ral, rb;
    auto gload = [&](int k0) {
        rah = *(const uint4*)(Abh + k0);
        ral = *(const uint4*)(Abl + k0);
        int k = k0 + bk;
        int ci, dy, dx;
        if (k < 2304) {
            ci = k / 9;
            int tap = k - ci * 9;
            int r = tap / 3;
            dy = r - 1;
            dx = tap - r * 3 - 1;
        } else { ci = k - 2304; dy = 0; dx = 0; }
        int hh = h + dy;
        bool hok = (hh >= 0) && (hh < 256);
        const u16* row = g_yh + ((size_t)(b * 256 + ci) << 16) + hh * 256;
        uint32_t v[8];
#pragma unroll
        for (int j = 0; j < 8; ++j) {
            int ww = w0 + bn + j + dx;
            v[j] = (hok && ww >= 0 && ww < 256) ? (uint32_t)row[ww] : 0u;
        }
        uint32_t* pb = (uint32_t*)&rb;
#pragma unroll
        for (int j = 0; j < 4; ++j) pb[j] = v[2 * j] | (v[2 * j + 1] << 16);
    };
    auto sstore = [&](int s) {
        *(uint4*)(AhS[s] + aoff) = rah;
        *(uint4*)(AlS[s] + aoff) = ral;
        *(uint4*)(BS[s]  + boff) = rb;
    };

    const int nch = 160;
    gload(0);
    sstore(0);
    gload(16);
    __syncthreads();

    for (int ch = 0; ch < nch; ++ch) {
        if (ch + 1 < nch) sstore((ch + 1) & 1);
        if (ch + 2 < nch) gload((ch + 2) << 4);
        int s = ch & 1;
        mma_step(smem_u32(AhS[s]), smem_u32(AlS[s]), smem_u32(BS[s]),
                 wm, wn, lane, acc);
        __syncthreads();
    }

    int g = lane >> 2, tig = lane & 3;
#pragma unroll
    for (int mt = 0; mt < 4; ++mt) {
        int r0 = m0 + wm + mt * 16 + g;
        float bi0 = g_biasc[r0];
        float bi1 = g_biasc[r0 + 8];
#pragma unroll
        for (int j = 0; j < 4; ++j) {
            int col = p0 + wn + j * 8 + tig * 2;
            size_t i0 = ((size_t)(b * 256 + r0) << 16) + col;
            size_t i1 = ((size_t)(b * 256 + r0 + 8) << 16) + col;
            *(float2*)&g_local[i0] = make_float2(acc[mt][j][0] + bi0, acc[mt][j][1] + bi0);
            *(float2*)&g_local[i1] = make_float2(acc[mt][j][2] + bi1, acc[mt][j][3] + bi1);
        }
    }
}

// ---------------------------------------------------------------------------
// Windowed attention: packed f32x2 math, 2 windows x 1 head per block.
// ---------------------------------------------------------------------------
__global__ __launch_bounds__(128) void attn_kernel(const float* __restrict__ rpb)
{
    int w2   = threadIdx.x >> 6;
    int i    = threadIdx.x & 63;
    int win  = blockIdx.x * 2 + w2;
    int head = blockIdx.y;
    int b    = win >> 10;
    int wloc = win & 1023;
    int yi = i >> 3, xi = i & 7;
    int pp = wloc * 64 + i;

    __shared__ u64 ks2[2][64][8];
    __shared__ u64 vs2[2][64][8];
    __shared__ float rpbs[225];

    for (int t = threadIdx.x; t < 225; t += 128) rpbs[t] = rpb[t * 16 + head];

    size_t base = ((size_t)(b * 768 + head * 16) << 16) + pp;
    u64 q2[8];
#pragma unroll
    for (int d = 0; d < 8; ++d) {
        float q0 = g_qkv[base + ((size_t)(2 * d) << 16)];
        float q1 = g_qkv[base + ((size_t)(2 * d + 1) << 16)];
        q2[d] = pack2(q0, q1);
        float k0 = g_qkv[base + ((size_t)(256 + 2 * d) << 16)];
        float k1 = g_qkv[base + ((size_t)(256 + 2 * d + 1) << 16)];
        ks2[w2][i][d] = pack2(k0, k1);
        float v0 = g_qkv[base + ((size_t)(512 + 2 * d) << 16)];
        float v1 = g_qkv[base + ((size_t)(512 + 2 * d + 1) << 16)];
        vs2[w2][i][d] = pack2(v0, v1);
    }
    __syncthreads();

    float m_run = -1e30f, l_run = 0.f;
    u64 o2[8];
#pragma unroll
    for (int d = 0; d < 8; ++d) o2[d] = 0ULL;

#pragma unroll
    for (int cchunk = 0; cchunk < 4; ++cchunk) {
        float s[16];
        float cm = -1e30f;
#pragma unroll
        for (int jj = 0; jj < 16; ++jj) {
            int j = cchunk * 16 + jj;
            u64 a2 = 0ULL;
            const u64* kj = ks2[w2][j];
#pragma unroll
            for (int d = 0; d < 8; ++d) ffma2(a2, q2[d], kj[d]);
            float lo, hi;
            unpack2(a2, lo, hi);
            int yj = j >> 3, xj = j & 7;
            float sc = lo + hi + rpbs[(yi - yj + 7) * 15 + (xi - xj + 7)];
            s[jj] = sc;
            cm = fmaxf(cm, sc);
        }
        float mnew = fmaxf(m_run, cm);
        float corr = __expf(m_run - mnew);
        l_run *= corr;
        u64 c2 = dup2(corr);
#pragma unroll
        for (int d = 0; d < 8; ++d) o2[d] = mul2(o2[d], c2);
#pragma unroll
        for (int jj = 0; jj < 16; ++jj) {
            int j = cchunk * 16 + jj;
            float pj = __expf(s[jj] - mnew);
            l_run += pj;
            u64 p2 = dup2(pj);
            const u64* vj = vs2[w2][j];
#pragma unroll
            for (int d = 0; d < 8; ++d) ffma2(o2[d], p2, vj[d]);
        }
        m_run = mnew;
    }
    float inv = 1.f / l_run;

    int wy = wloc >> 5, wx = wloc & 31;
    int p  = (((wy * 8) + yi) << 8) + wx * 8 + xi;
#pragma unroll
    for (int d = 0; d < 8; ++d) {
        float lo, hi;
        unpack2(o2[d], lo, hi);
        g_attn[((size_t)(b * 256 + head * 16 + 2 * d) << 16) + p]     = lo * inv;
        g_attn[((size_t)(b * 256 + head * 16 + 2 * d + 1) << 16) + p] = hi * inv;
    }
}

// ---------------------------------------------------------------------------
// Fused pool + depthwise 8x8 conv + BN -> single fp16 output g_dwh.
// ---------------------------------------------------------------------------
__global__ __launch_bounds__(256) void dwpool_kernel(const float* __restrict__ w_dw)
{
    __shared__ float attnS[46][48];
    __shared__ float midS[39][40];
    __shared__ float ws[64];

    int tix = blockIdx.x;
    int bc  = blockIdx.y;
    int c   = bc & 255;
    int ty0 = (tix >> 3) * 32;
    int tx0 = (tix & 7) * 32;
    int tid = threadIdx.x;

    const float* aplane = g_attn + ((size_t)bc << 16);
    const float* lplane = g_local + ((size_t)bc << 16);

    for (int idx = tid; idx < 46 * 46; idx += 256) {
        int r  = idx / 46;
        int cc = idx - r * 46;
        int gh = ty0 - 6 + r;
        int gw = tx0 - 6 + cc;
        float v = 0.f;
        if (gh >= 0 && gh < 256 && gw >= 0 && gw < 256) v = aplane[gh * 256 + gw];
        attnS[r][cc] = v;
    }
    if (tid < 64) ws[tid] = w_dw[c * 64 + tid];
    __syncthreads();

    for (int idx = tid; idx < 39 * 39; idx += 256) {
        int r  = idx / 39;
        int cc = idx - r * 39;
        int gh = ty0 - 3 + r;
        int gw = tx0 - 3 + cc;
        float v = 0.f;
        if (gh >= 0 && gh <= 256 && gw >= 0 && gw <= 256) {
            int gh2 = (gh == 256) ? 254 : gh;
            int gw2 = (gw == 256) ? 254 : gw;
            int co = gw2 - (tx0 - 6);
            float vs = 0.f;
#pragma unroll
            for (int t = gh2 - 3; t <= gh2 + 4; ++t) {
                if (t >= 0 && t <= 256) {
                    int tt = (t == 256) ? 254 : t;
                    vs += attnS[tt - (ty0 - 6)][co];
                }
            }
            int ro = gh2 - (ty0 - 6);
            float hs = 0.f;
#pragma unroll
            for (int s = gw2 - 3; s <= gw2 + 4; ++s) {
                if (s >= 0 && s <= 256) {
                    int ss = (s == 256) ? 254 : s;
                    hs += attnS[ro][ss - (tx0 - 6)];
                }
            }
            v = (vs + hs) * 0.125f + lplane[gh2 * 256 + gw2];
        }
        midS[r][cc] = v;
    }
    __syncthreads();

    int lw  = tid & 31;
    int lh0 = (tid >> 5) * 4;
    float acc[4] = {0.f, 0.f, 0.f, 0.f};
#pragma unroll
    for (int j = 0; j < 8; ++j) {
        float wcol[8];
#pragma unroll
        for (int i = 0; i < 8; ++i) wcol[i] = ws[i * 8 + j];
#pragma unroll
        for (int r = 0; r < 11; ++r) {
            float v = midS[lh0 + r][lw + j];
#pragma unroll
            for (int a = 0; a < 4; ++a) {
                int i = r - a;
                if (i >= 0 && i < 8) acc[a] += v * wcol[i];
            }
        }
    }
    float ip = g_invp[c];
    float bb = g_biasp[c];
#pragma unroll
    for (int a = 0; a < 4; ++a) {
        int h = ty0 + lh0 + a;
        float r = acc[a] * ip + bb;
        size_t idx = ((size_t)bc << 16) + h * 256 + tx0 + lw;
        g_dwh[idx] = h16(r);
    }
}

// ---------------------------------------------------------------------------
// Launch
// ---------------------------------------------------------------------------
extern "C" void kernel_launch(void* const* d_in, const int* in_sizes, int n_in,
                              void* d_out, int out_size)
{
    const float* x    = (const float*)d_in[0];
    const float* y    = (const float*)d_in[1];
    const float* wqkv = (const float*)d_in[2];
    const float* wl1  = (const float*)d_in[3];
    const float* g1   = (const float*)d_in[4];
    const float* b1   = (const float*)d_in[5];
    const float* m1   = (const float*)d_in[6];
    const float* v1   = (const float*)d_in[7];
    const float* wl2  = (const float*)d_in[8];
    const float* g2   = (const float*)d_in[9];
    const float* b2   = (const float*)d_in[10];
    const float* m2   = (const float*)d_in[11];
    const float* v2   = (const float*)d_in[12];
    const float* wdw  = (const float*)d_in[13];
    const float* gp   = (const float*)d_in[14];
    const float* bp   = (const float*)d_in[15];
    const float* mp   = (const float*)d_in[16];
    const float* vp   = (const float*)d_in[17];
    const float* wpw  = (const float*)d_in[18];
    const float* rpb  = (const float*)d_in[19];
    float* out = (float*)d_out;

    prep_kernel<<<1, 256>>>(g1, b1, m1, v1, g2, b2, m2, v2, gp, bp, mp, vp);
    split_wqkv<<<768, 256>>>(wqkv);
    split_wpw<<<256, 256>>>(wpw);
    split_wlocal<<<2560, 256>>>(wl1, wl2);
    cvt_x<<<32768, 256>>>(x);
    cvt_y<<<32768, 256>>>(y);

    // local branch (K=2560) -> g_local
    gemm_local_f16<<<dim3(2, 1024), 256>>>();

    // qkv (M=768, K=256) -> g_qkv (window-major)
    gemm_aligned<<<dim3(6, 1024), 256>>>(nullptr, 768, 256, 0);

    // attention (2 windows x 1 head per block)
    attn_kernel<<<dim3(1024, 16), 128>>>(rpb);

    // fused pools + depthwise conv + BN -> g_dwh (fp16)
    dwpool_kernel<<<dim3(64, 512), 256>>>(wdw);

    // pointwise (M=256, K=256) -> out
    gemm_aligned<<<dim3(2, 1024), 256>>>(out, 256, 256, 1);
}

// round 11
// speedup vs baseline: 2.9508x; 1.2304x over previous
#include <cuda_runtime.h>
#include <cuda_fp16.h>
#include <math.h>
#include <stdint.h>

// ---------------------------------------------------------------------------
// Problem constants: B=2, C=256, H=W=256, SSM=256, NH=16, HD=16, WS=8
// ---------------------------------------------------------------------------
#define PPLANE 65536
#define NBATCH 2

typedef unsigned long long u64;
typedef unsigned short u16;

__device__ float g_local[NBATCH * 256 * PPLANE];
__device__ float g_qkv  [NBATCH * 768 * PPLANE];   // window-major pixel layout
__device__ float g_attn [NBATCH * 256 * PPLANE];

// pre-converted fp16 operands
__device__ u16 g_xh [NBATCH * 256 * PPLANE];
__device__ u16 g_yh [NBATCH * 256 * PPLANE];
__device__ u16 g_dwh[NBATCH * 256 * PPLANE];
__device__ u16 g_wqh [768 * 256];                   // single-pass fp16
__device__ u16 g_wph [256 * 256], g_wpl [256 * 256]; // 2-pass (output-facing)
__device__ u16 g_wlh [256 * 2560];                  // single-pass fp16

__device__ float g_inv1[256], g_inv2[256], g_biasc[256], g_invp[256], g_biasp[256];

// ---------------------------------------------------------------------------
// helpers
// ---------------------------------------------------------------------------
__device__ __forceinline__ uint32_t smem_u32(const void* p) {
    uint32_t a;
    asm("{ .reg .u64 t; cvta.to.shared.u64 t, %1; cvt.u32.u64 %0, t; }"
        : "=r"(a) : "l"(p));
    return a;
}
__device__ __forceinline__ u16 h16(float v) {
    __half h = __float2half_rn(v);
    return *reinterpret_cast<u16*>(&h);
}
__device__ __forceinline__ void splt16(float v, u16& h, u16& l) {
    __half hb = __float2half_rn(v);
    float r = v - __half2float(hb);
    __half lb = __float2half_rn(r);
    h = *reinterpret_cast<u16*>(&hb);
    l = *reinterpret_cast<u16*>(&lb);
}
__device__ __forceinline__ void ldsm4(uint32_t* r, uint32_t a) {
    asm volatile("ldmatrix.sync.aligned.m8n8.x4.shared.b16 {%0,%1,%2,%3},[%4];"
                 : "=r"(r[0]), "=r"(r[1]), "=r"(r[2]), "=r"(r[3]) : "r"(a));
}
__device__ __forceinline__ void ldsm4t(uint32_t* r, uint32_t a) {
    asm volatile("ldmatrix.sync.aligned.m8n8.x4.trans.shared.b16 {%0,%1,%2,%3},[%4];"
                 : "=r"(r[0]), "=r"(r[1]), "=r"(r[2]), "=r"(r[3]) : "r"(a));
}
__device__ __forceinline__ void mma16(float* c, const uint32_t* a, const uint32_t* b) {
    asm volatile(
        "mma.sync.aligned.m16n8k16.row.col.f32.f16.f16.f32 "
        "{%0,%1,%2,%3},{%4,%5,%6,%7},{%8,%9},{%0,%1,%2,%3};"
        : "+f"(c[0]), "+f"(c[1]), "+f"(c[2]), "+f"(c[3])
        : "r"(a[0]), "r"(a[1]), "r"(a[2]), "r"(a[3]), "r"(b[0]), "r"(b[1]));
}

// f32x2 packed math (attention)
__device__ __forceinline__ u64 pack2(float a, float b) {
    u64 r;
    asm("mov.b64 %0, {%1, %2};" : "=l"(r) : "f"(a), "f"(b));
    return r;
}
__device__ __forceinline__ u64 dup2(float x) {
    u64 r;
    asm("mov.b64 %0, {%1, %1};" : "=l"(r) : "f"(x));
    return r;
}
__device__ __forceinline__ void ffma2(u64& d, u64 a, u64 b) {
    asm("fma.rn.f32x2 %0, %1, %2, %0;" : "+l"(d) : "l"(a), "l"(b));
}
__device__ __forceinline__ u64 mul2(u64 a, u64 b) {
    u64 d;
    asm("mul.rn.f32x2 %0, %1, %2;" : "=l"(d) : "l"(a), "l"(b));
    return d;
}
__device__ __forceinline__ void unpack2(u64 v, float& a, float& b) {
    asm("mov.b64 {%0, %1}, %2;" : "=f"(a), "=f"(b) : "l"(v));
}

#define ASTRIDE 48
#define BSTRIDE 272
#define ABYTES (128 * ASTRIDE)
#define BBYTES (16 * BSTRIDE)

__device__ __forceinline__ int perm_px(int p) {
    int h = p >> 8, w = p & 255;
    return (((h >> 3) * 32 + (w >> 3)) << 6) + ((h & 7) << 3) + (w & 7);
}

// ---------------------------------------------------------------------------
// Prep kernels
// ---------------------------------------------------------------------------
__global__ void prep_kernel(const float* __restrict__ g1, const float* __restrict__ b1,
                            const float* __restrict__ m1, const float* __restrict__ v1,
                            const float* __restrict__ g2, const float* __restrict__ b2,
                            const float* __restrict__ m2, const float* __restrict__ v2,
                            const float* __restrict__ gp, const float* __restrict__ bp,
                            const float* __restrict__ mp, const float* __restrict__ vp)
{
    int c = threadIdx.x;
    float i1 = g1[c] * rsqrtf(v1[c] + 1e-5f);
    float i2 = g2[c] * rsqrtf(v2[c] + 1e-5f);
    g_inv1[c] = i1;
    g_inv2[c] = i2;
    g_biasc[c] = (b1[c] - m1[c] * i1) + (b2[c] - m2[c] * i2);
    float ip = gp[c] * rsqrtf(vp[c] + 1e-5f);
    g_invp[c] = ip;
    g_biasp[c] = bp[c] - mp[c] * ip;
}

__global__ void cvt_wqkv(const float* __restrict__ w)
{
    int i = blockIdx.x * 256 + threadIdx.x;
    if (i >= 768 * 256) return;
    float sc = (i < 256 * 256) ? 0.25f : 1.0f;
    g_wqh[i] = h16(w[i] * sc);
}
__global__ void split_wpw(const float* __restrict__ w)
{
    int i = blockIdx.x * 256 + threadIdx.x;
    splt16(w[i], g_wph[i], g_wpl[i]);
}
__global__ void cvt_wlocal(const float* __restrict__ w1, const float* __restrict__ w2)
{
    int i = blockIdx.x * 256 + threadIdx.x;
    if (i >= 256 * 2560) return;
    int m = i / 2560, k = i - m * 2560;
    float v = (k < 2304) ? w1[m * 2304 + k] * g_inv1[m]
                         : w2[m * 256 + (k - 2304)] * g_inv2[m];
    g_wlh[i] = h16(v);
}
__global__ void cvt_x(const float* __restrict__ x)
{
    size_t base = ((size_t)blockIdx.x * 256 + threadIdx.x) * 4;
    float4 v = *(const float4*)(x + base);
    u16 h[4] = { h16(v.x), h16(v.y), h16(v.z), h16(v.w) };
    *(uint2*)(g_xh + base) = *(uint2*)h;
}
__global__ void cvt_y(const float* __restrict__ y)
{
    size_t base = ((size_t)blockIdx.x * 256 + threadIdx.x) * 4;
    float4 v = *(const float4*)(y + base);
    u16 h[4] = { h16(v.x), h16(v.y), h16(v.z), h16(v.w) };
    *(uint2*)(g_yh + base) = *(uint2*)h;
}

// ---------------------------------------------------------------------------
// Consumer: one K=16 step.  TWOPASS: (Ah + Al) * B, else Ah * B.
// ---------------------------------------------------------------------------
template <bool TWOPASS>
__device__ __forceinline__ void mma_step(
    uint32_t sAh, uint32_t sAl, uint32_t sB,
    int wm, int wn, int lane, float acc[4][4][4])
{
    int t  = lane >> 3;
    int r8 = lane & 7;
    uint32_t bh[4][2];
#pragma unroll
    for (int ng = 0; ng < 2; ++ng) {
        uint32_t addr = ((t >> 1) * 8 + r8) * BSTRIDE + (wn + ng * 16 + (t & 1) * 8) * 2;
        uint32_t tb[4];
        ldsm4t(tb, sB + addr);
        bh[ng * 2 + 0][0] = tb[0]; bh[ng * 2 + 0][1] = tb[2];
        bh[ng * 2 + 1][0] = tb[1]; bh[ng * 2 + 1][1] = tb[3];
    }
    uint32_t abase = ((t & 1) * 8 + r8) * ASTRIDE + (t >> 1) * 16;
#pragma unroll
    for (int mt = 0; mt < 4; ++mt) {
        uint32_t arow = abase + (wm + mt * 16) * ASTRIDE;
        uint32_t ah[4];
        ldsm4(ah, sAh + arow);
#pragma unroll
        for (int j = 0; j < 4; ++j) mma16(acc[mt][j], ah, bh[j]);
        if (TWOPASS) {
            uint32_t al[4];
            ldsm4(al, sAl + arow);
#pragma unroll
            for (int j = 0; j < 4; ++j) mma16(acc[mt][j], al, bh[j]);
        }
    }
}

// ---------------------------------------------------------------------------
// qkv GEMM: A = wqkv single fp16 (M=768,K=256), B = x, C = g_qkv (permuted)
// grid = (6, 1024)
// ---------------------------------------------------------------------------
__global__ __launch_bounds__(256, 2) void gemm_qkv(void)
{
    __shared__ __align__(16) char AhS[2][ABYTES];
    __shared__ __align__(16) char BS [2][BBYTES];

    const int M = 768, K = 256;
    int tid = threadIdx.x;
    int m0  = blockIdx.x * 128;
    int pg0 = blockIdx.y * 128;
    int b   = pg0 >> 16;
    int p0  = pg0 & 65535;
    int lane = tid & 31, warp = tid >> 5;
    int wm = (warp >> 2) * 64, wn = (warp & 3) * 32;

    int am = tid >> 1, ak = (tid & 1) * 8;
    const u16* Abh = g_wqh + (size_t)(m0 + am) * K + ak;
    int bk = tid >> 4, bn = (tid & 15) * 8;
    size_t bbase = ((size_t)(b * K + bk) << 16) + p0 + bn;

    int aoff = am * ASTRIDE + ak * 2;
    int boff = bk * BSTRIDE + bn * 2;

    float acc[4][4][4];
#pragma unroll
    for (int i = 0; i < 4; ++i)
#pragma unroll
        for (int j = 0; j < 4; ++j)
#pragma unroll
            for (int r = 0; r < 4; ++r) acc[i][j][r] = 0.f;

    uint4 rah, rb;
    auto gload = [&](int k0) {
        rah = *(const uint4*)(Abh + k0);
        rb  = *(const uint4*)(g_xh + bbase + ((size_t)k0 << 16));
    };
    auto sstore = [&](int s) {
        *(uint4*)(AhS[s] + aoff) = rah;
        *(uint4*)(BS[s]  + boff) = rb;
    };

    const int nch = 16;
    gload(0);
    sstore(0);
    gload(16);
    __syncthreads();

    for (int ch = 0; ch < nch; ++ch) {
        if (ch + 1 < nch) sstore((ch + 1) & 1);
        if (ch + 2 < nch) gload((ch + 2) << 4);
        int s = ch & 1;
        mma_step<false>(smem_u32(AhS[s]), 0, smem_u32(BS[s]), wm, wn, lane, acc);
        __syncthreads();
    }

    int g = lane >> 2, tig = lane & 3;
#pragma unroll
    for (int mt = 0; mt < 4; ++mt) {
        int r0 = m0 + wm + mt * 16 + g;
#pragma unroll
        for (int j = 0; j < 4; ++j) {
            int col = p0 + wn + j * 8 + tig * 2;
            int pc = perm_px(col);
            size_t i0 = ((size_t)(b * M + r0) << 16) + pc;
            size_t i1 = ((size_t)(b * M + r0 + 8) << 16) + pc;
            *(float2*)&g_qkv[i0] = make_float2(acc[mt][j][0], acc[mt][j][1]);
            *(float2*)&g_qkv[i1] = make_float2(acc[mt][j][2], acc[mt][j][3]);
        }
    }
}

// ---------------------------------------------------------------------------
// pw GEMM (2-pass, output-facing): A = wpw hi/lo (M=256,K=256), B = dw
// grid = (2, 1024)
// ---------------------------------------------------------------------------
__global__ __launch_bounds__(256, 2) void gemm_pw(float* __restrict__ C)
{
    __shared__ __align__(16) char AhS[2][ABYTES];
    __shared__ __align__(16) char AlS[2][ABYTES];
    __shared__ __align__(16) char BS [2][BBYTES];

    const int M = 256, K = 256;
    int tid = threadIdx.x;
    int m0  = blockIdx.x * 128;
    int pg0 = blockIdx.y * 128;
    int b   = pg0 >> 16;
    int p0  = pg0 & 65535;
    int lane = tid & 31, warp = tid >> 5;
    int wm = (warp >> 2) * 64, wn = (warp & 3) * 32;

    int am = tid >> 1, ak = (tid & 1) * 8;
    const u16* Abh = g_wph + (size_t)(m0 + am) * K + ak;
    const u16* Abl = g_wpl + (size_t)(m0 + am) * K + ak;
    int bk = tid >> 4, bn = (tid & 15) * 8;
    size_t bbase = ((size_t)(b * K + bk) << 16) + p0 + bn;

    int aoff = am * ASTRIDE + ak * 2;
    int boff = bk * BSTRIDE + bn * 2;

    float acc[4][4][4];
#pragma unroll
    for (int i = 0; i < 4; ++i)
#pragma unroll
        for (int j = 0; j < 4; ++j)
#pragma unroll
            for (int r = 0; r < 4; ++r) acc[i][j][r] = 0.f;

    uint4 rah, ral, rb;
    auto gload = [&](int k0) {
        rah = *(const uint4*)(Abh + k0);
        ral = *(const uint4*)(Abl + k0);
        rb  = *(const uint4*)(g_dwh + bbase + ((size_t)k0 << 16));
    };
    auto sstore = [&](int s) {
        *(uint4*)(AhS[s] + aoff) = rah;
        *(uint4*)(AlS[s] + aoff) = ral;
        *(uint4*)(BS[s]  + boff) = rb;
    };

    const int nch = 16;
    gload(0);
    sstore(0);
    gload(16);
    __syncthreads();

    for (int ch = 0; ch < nch; ++ch) {
        if (ch + 1 < nch) sstore((ch + 1) & 1);
        if (ch + 2 < nch) gload((ch + 2) << 4);
        int s = ch & 1;
        mma_step<true>(smem_u32(AhS[s]), smem_u32(AlS[s]), smem_u32(BS[s]),
                       wm, wn, lane, acc);
        __syncthreads();
    }

    int g = lane >> 2, tig = lane & 3;
#pragma unroll
    for (int mt = 0; mt < 4; ++mt) {
        int r0 = m0 + wm + mt * 16 + g;
#pragma unroll
        for (int j = 0; j < 4; ++j) {
            int col = p0 + wn + j * 8 + tig * 2;
            size_t i0 = ((size_t)(b * M + r0) << 16) + col;
            size_t i1 = ((size_t)(b * M + r0 + 8) << 16) + col;
            *(float2*)&C[i0] = make_float2(acc[mt][j][0], acc[mt][j][1]);
            *(float2*)&C[i1] = make_float2(acc[mt][j][2], acc[mt][j][3]);
        }
    }
}

// ---------------------------------------------------------------------------
// Fused local branch GEMM (1-pass fp16), K=2560, B gathered from g_yh.
// grid = (2, 1024)
// ---------------------------------------------------------------------------
__global__ __launch_bounds__(256, 2) void gemm_local_f16(void)
{
    __shared__ __align__(16) char AhS[2][ABYTES];
    __shared__ __align__(16) char BS [2][BBYTES];

    int tid = threadIdx.x;
    int m0  = blockIdx.x * 128;
    int pg0 = blockIdx.y * 128;
    int b   = pg0 >> 16;
    int p0  = pg0 & 65535;
    int h   = p0 >> 8;
    int w0  = p0 & 255;
    int lane = tid & 31, warp = tid >> 5;
    int wm = (warp >> 2) * 64, wn = (warp & 3) * 32;

    int am = tid >> 1, ak = (tid & 1) * 8;
    int mg = m0 + am;
    int bk = tid >> 4, bn = (tid & 15) * 8;

    int aoff = am * ASTRIDE + ak * 2;
    int boff = bk * BSTRIDE + bn * 2;

    const u16* Abh = g_wlh + (size_t)mg * 2560 + ak;

    float acc[4][4][4];
#pragma unroll
    for (int i = 0; i < 4; ++i)
#pragma unroll
        for (int j = 0; j < 4; ++j)
#pragma unroll
            for (int r = 0; r < 4; ++r) acc[i][j][r] = 0.f;

    uint4 rah, rb;
    auto gload = [&](int k0) {
        rah = *(const uint4*)(Abh + k0);
        int k = k0 + bk;
        int ci, dy, dx;
        if (k < 2304) {
            ci = k / 9;
            int tap = k - ci * 9;
            int r = tap / 3;
            dy = r - 1;
            dx = tap - r * 3 - 1;
        } else { ci = k - 2304; dy = 0; dx = 0; }
        int hh = h + dy;
        bool hok = (hh >= 0) && (hh < 256);
        const u16* row = g_yh + ((size_t)(b * 256 + ci) << 16) + hh * 256;
        uint32_t v[8];
#pragma unroll
        for (int j = 0; j < 8; ++j) {
            int ww = w0 + bn + j + dx;
            v[j] = (hok && ww >= 0 && ww < 256) ? (uint32_t)row[ww] : 0u;
        }
        uint32_t* pb = (uint32_t*)&rb;
#pragma unroll
        for (int j = 0; j < 4; ++j) pb[j] = v[2 * j] | (v[2 * j + 1] << 16);
    };
    auto sstore = [&](int s) {
        *(uint4*)(AhS[s] + aoff) = rah;
        *(uint4*)(BS[s]  + boff) = rb;
    };

    const int nch = 160;
    gload(0);
    sstore(0);
    gload(16);
    __syncthreads();

    for (int ch = 0; ch < nch; ++ch) {
        if (ch + 1 < nch) sstore((ch + 1) & 1);
        if (ch + 2 < nch) gload((ch + 2) << 4);
        int s = ch & 1;
        mma_step<false>(smem_u32(AhS[s]), 0, smem_u32(BS[s]), wm, wn, lane, acc);
        __syncthreads();
    }

    int g = lane >> 2, tig = lane & 3;
#pragma unroll
    for (int mt = 0; mt < 4; ++mt) {
        int r0 = m0 + wm + mt * 16 + g;
        float bi0 = g_biasc[r0];
        float bi1 = g_biasc[r0 + 8];
#pragma unroll
        for (int j = 0; j < 4; ++j) {
            int col = p0 + wn + j * 8 + tig * 2;
            size_t i0 = ((size_t)(b * 256 + r0) << 16) + col;
            size_t i1 = ((size_t)(b * 256 + r0 + 8) << 16) + col;
            *(float2*)&g_local[i0] = make_float2(acc[mt][j][0] + bi0, acc[mt][j][1] + bi0);
            *(float2*)&g_local[i1] = make_float2(acc[mt][j][2] + bi1, acc[mt][j][3] + bi1);
        }
    }
}

// ---------------------------------------------------------------------------
// Windowed attention: packed f32x2 math, 2 windows x 1 head per block.
// ---------------------------------------------------------------------------
__global__ __launch_bounds__(128) void attn_kernel(const float* __restrict__ rpb)
{
    int w2   = threadIdx.x >> 6;
    int i    = threadIdx.x & 63;
    int win  = blockIdx.x * 2 + w2;
    int head = blockIdx.y;
    int b    = win >> 10;
    int wloc = win & 1023;
    int yi = i >> 3, xi = i & 7;
    int pp = wloc * 64 + i;

    __shared__ u64 ks2[2][64][8];
    __shared__ u64 vs2[2][64][8];
    __shared__ float rpbs[225];

    for (int t = threadIdx.x; t < 225; t += 128) rpbs[t] = rpb[t * 16 + head];

    size_t base = ((size_t)(b * 768 + head * 16) << 16) + pp;
    u64 q2[8];
#pragma unroll
    for (int d = 0; d < 8; ++d) {
        float q0 = g_qkv[base + ((size_t)(2 * d) << 16)];
        float q1 = g_qkv[base + ((size_t)(2 * d + 1) << 16)];
        q2[d] = pack2(q0, q1);
        float k0 = g_qkv[base + ((size_t)(256 + 2 * d) << 16)];
        float k1 = g_qkv[base + ((size_t)(256 + 2 * d + 1) << 16)];
        ks2[w2][i][d] = pack2(k0, k1);
        float v0 = g_qkv[base + ((size_t)(512 + 2 * d) << 16)];
        float v1 = g_qkv[base + ((size_t)(512 + 2 * d + 1) << 16)];
        vs2[w2][i][d] = pack2(v0, v1);
    }
    __syncthreads();

    float m_run = -1e30f, l_run = 0.f;
    u64 o2[8];
#pragma unroll
    for (int d = 0; d < 8; ++d) o2[d] = 0ULL;

#pragma unroll
    for (int cchunk = 0; cchunk < 4; ++cchunk) {
        float s[16];
        float cm = -1e30f;
#pragma unroll
        for (int jj = 0; jj < 16; ++jj) {
            int j = cchunk * 16 + jj;
            u64 a2 = 0ULL;
            const u64* kj = ks2[w2][j];
#pragma unroll
            for (int d = 0; d < 8; ++d) ffma2(a2, q2[d], kj[d]);
            float lo, hi;
            unpack2(a2, lo, hi);
            int yj = j >> 3, xj = j & 7;
            float sc = lo + hi + rpbs[(yi - yj + 7) * 15 + (xi - xj + 7)];
            s[jj] = sc;
            cm = fmaxf(cm, sc);
        }
        float mnew = fmaxf(m_run, cm);
        float corr = __expf(m_run - mnew);
        l_run *= corr;
        u64 c2 = dup2(corr);
#pragma unroll
        for (int d = 0; d < 8; ++d) o2[d] = mul2(o2[d], c2);
#pragma unroll
        for (int jj = 0; jj < 16; ++jj) {
            int j = cchunk * 16 + jj;
            float pj = __expf(s[jj] - mnew);
            l_run += pj;
            u64 p2 = dup2(pj);
            const u64* vj = vs2[w2][j];
#pragma unroll
            for (int d = 0; d < 8; ++d) ffma2(o2[d], p2, vj[d]);
        }
        m_run = mnew;
    }
    float inv = 1.f / l_run;

    int wy = wloc >> 5, wx = wloc & 31;
    int p  = (((wy * 8) + yi) << 8) + wx * 8 + xi;
#pragma unroll
    for (int d = 0; d < 8; ++d) {
        float lo, hi;
        unpack2(o2[d], lo, hi);
        g_attn[((size_t)(b * 256 + head * 16 + 2 * d) << 16) + p]     = lo * inv;
        g_attn[((size_t)(b * 256 + head * 16 + 2 * d + 1) << 16) + p] = hi * inv;
    }
}

// ---------------------------------------------------------------------------
// Fused pool + depthwise 8x8 conv + BN -> single fp16 output g_dwh.
// ---------------------------------------------------------------------------
__global__ __launch_bounds__(256) void dwpool_kernel(const float* __restrict__ w_dw)
{
    __shared__ float attnS[46][48];
    __shared__ float midS[39][40];
    __shared__ float ws[64];

    int tix = blockIdx.x;
    int bc  = blockIdx.y;
    int c   = bc & 255;
    int ty0 = (tix >> 3) * 32;
    int tx0 = (tix & 7) * 32;
    int tid = threadIdx.x;

    const float* aplane = g_attn + ((size_t)bc << 16);
    const float* lplane = g_local + ((size_t)bc << 16);

    for (int idx = tid; idx < 46 * 46; idx += 256) {
        int r  = idx / 46;
        int cc = idx - r * 46;
        int gh = ty0 - 6 + r;
        int gw = tx0 - 6 + cc;
        float v = 0.f;
        if (gh >= 0 && gh < 256 && gw >= 0 && gw < 256) v = aplane[gh * 256 + gw];
        attnS[r][cc] = v;
    }
    if (tid < 64) ws[tid] = w_dw[c * 64 + tid];
    __syncthreads();

    for (int idx = tid; idx < 39 * 39; idx += 256) {
        int r  = idx / 39;
        int cc = idx - r * 39;
        int gh = ty0 - 3 + r;
        int gw = tx0 - 3 + cc;
        float v = 0.f;
        if (gh >= 0 && gh <= 256 && gw >= 0 && gw <= 256) {
            int gh2 = (gh == 256) ? 254 : gh;
            int gw2 = (gw == 256) ? 254 : gw;
            int co = gw2 - (tx0 - 6);
            float vs = 0.f;
#pragma unroll
            for (int t = gh2 - 3; t <= gh2 + 4; ++t) {
                if (t >= 0 && t <= 256) {
                    int tt = (t == 256) ? 254 : t;
                    vs += attnS[tt - (ty0 - 6)][co];
                }
            }
            int ro = gh2 - (ty0 - 6);
            float hs = 0.f;
#pragma unroll
            for (int s = gw2 - 3; s <= gw2 + 4; ++s) {
                if (s >= 0 && s <= 256) {
                    int ss = (s == 256) ? 254 : s;
                    hs += attnS[ro][ss - (tx0 - 6)];
                }
            }
            v = (vs + hs) * 0.125f + lplane[gh2 * 256 + gw2];
        }
        midS[r][cc] = v;
    }
    __syncthreads();

    int lw  = tid & 31;
    int lh0 = (tid >> 5) * 4;
    float acc[4] = {0.f, 0.f, 0.f, 0.f};
#pragma unroll
    for (int j = 0; j < 8; ++j) {
        float wcol[8];
#pragma unroll
        for (int i = 0; i < 8; ++i) wcol[i] = ws[i * 8 + j];
#pragma unroll
        for (int r = 0; r < 11; ++r) {
            float v = midS[lh0 + r][lw + j];
#pragma unroll
            for (int a = 0; a < 4; ++a) {
                int i = r - a;
                if (i >= 0 && i < 8) acc[a] += v * wcol[i];
            }
        }
    }
    float ip = g_invp[c];
    float bb = g_biasp[c];
#pragma unroll
    for (int a = 0; a < 4; ++a) {
        int h = ty0 + lh0 + a;
        float r = acc[a] * ip + bb;
        size_t idx = ((size_t)bc << 16) + h * 256 + tx0 + lw;
        g_dwh[idx] = h16(r);
    }
}

// ---------------------------------------------------------------------------
// Launch
// ---------------------------------------------------------------------------
extern "C" void kernel_launch(void* const* d_in, const int* in_sizes, int n_in,
                              void* d_out, int out_size)
{
    const float* x    = (const float*)d_in[0];
    const float* y    = (const float*)d_in[1];
    const float* wqkv = (const float*)d_in[2];
    const float* wl1  = (const float*)d_in[3];
    const float* g1   = (const float*)d_in[4];
    const float* b1   = (const float*)d_in[5];
    const float* m1   = (const float*)d_in[6];
    const float* v1   = (const float*)d_in[7];
    const float* wl2  = (const float*)d_in[8];
    const float* g2   = (const float*)d_in[9];
    const float* b2   = (const float*)d_in[10];
    const float* m2   = (const float*)d_in[11];
    const float* v2   = (const float*)d_in[12];
    const float* wdw  = (const float*)d_in[13];
    const float* gp   = (const float*)d_in[14];
    const float* bp   = (const float*)d_in[15];
    const float* mp   = (const float*)d_in[16];
    const float* vp   = (const float*)d_in[17];
    const float* wpw  = (const float*)d_in[18];
    const float* rpb  = (const float*)d_in[19];
    float* out = (float*)d_out;

    prep_kernel<<<1, 256>>>(g1, b1, m1, v1, g2, b2, m2, v2, gp, bp, mp, vp);
    cvt_wqkv<<<768, 256>>>(wqkv);
    split_wpw<<<256, 256>>>(wpw);
    cvt_wlocal<<<2560, 256>>>(wl1, wl2);
    cvt_x<<<32768, 256>>>(x);
    cvt_y<<<32768, 256>>>(y);

    // local branch (K=2560, 1-pass fp16) -> g_local
    gemm_local_f16<<<dim3(2, 1024), 256>>>();

    // qkv (M=768, K=256, 1-pass fp16) -> g_qkv (window-major)
    gemm_qkv<<<dim3(6, 1024), 256>>>();

    // attention (2 windows x 1 head per block)
    attn_kernel<<<dim3(1024, 16), 128>>>(rpb);

    // fused pools + depthwise conv + BN -> g_dwh (fp16)
    dwpool_kernel<<<dim3(64, 512), 256>>>(wdw);

    // pointwise (M=256, K=256, 2-pass) -> out
    gemm_pw<<<dim3(2, 1024), 256>>>(out);
}

// round 12
// speedup vs baseline: 3.2415x; 1.0985x over previous
#include <cuda_runtime.h>
#include <cuda_fp16.h>
#include <math.h>
#include <stdint.h>

// ---------------------------------------------------------------------------
// Problem constants: B=2, C=256, H=W=256, SSM=256, NH=16, HD=16, WS=8
// ---------------------------------------------------------------------------
#define PPLANE 65536
#define NBATCH 2

typedef unsigned long long u64;
typedef unsigned short u16;

__device__ float g_local[NBATCH * 256 * PPLANE];
__device__ u16   g_qkvh [NBATCH * 768 * PPLANE];   // fp16, window-major pixels
__device__ float g_attn [NBATCH * 256 * PPLANE];

// pre-converted fp16 operands
__device__ u16 g_xh [NBATCH * 256 * PPLANE];
__device__ u16 g_yh [NBATCH * 256 * PPLANE];
__device__ u16 g_dwh[NBATCH * 256 * PPLANE];
__device__ u16 g_wqh [768 * 256];                    // single-pass fp16
__device__ u16 g_wph [256 * 256], g_wpl [256 * 256]; // 2-pass (output-facing)
__device__ u16 g_wlh [256 * 2560];                   // single-pass fp16

__device__ float g_inv1[256], g_inv2[256], g_biasc[256], g_invp[256], g_biasp[256];

// ---------------------------------------------------------------------------
// helpers
// ---------------------------------------------------------------------------
__device__ __forceinline__ uint32_t smem_u32(const void* p) {
    uint32_t a;
    asm("{ .reg .u64 t; cvta.to.shared.u64 t, %1; cvt.u32.u64 %0, t; }"
        : "=r"(a) : "l"(p));
    return a;
}
__device__ __forceinline__ u16 h16(float v) {
    __half h = __float2half_rn(v);
    return *reinterpret_cast<u16*>(&h);
}
__device__ __forceinline__ uint32_t h2bits(float a, float b) {
    __half2 h = __floats2half2_rn(a, b);
    return *reinterpret_cast<uint32_t*>(&h);
}
__device__ __forceinline__ void splt16(float v, u16& h, u16& l) {
    __half hb = __float2half_rn(v);
    float r = v - __half2float(hb);
    __half lb = __float2half_rn(r);
    h = *reinterpret_cast<u16*>(&hb);
    l = *reinterpret_cast<u16*>(&lb);
}
__device__ __forceinline__ void ldsm4(uint32_t* r, uint32_t a) {
    asm volatile("ldmatrix.sync.aligned.m8n8.x4.shared.b16 {%0,%1,%2,%3},[%4];"
                 : "=r"(r[0]), "=r"(r[1]), "=r"(r[2]), "=r"(r[3]) : "r"(a));
}
__device__ __forceinline__ void ldsm4t(uint32_t* r, uint32_t a) {
    asm volatile("ldmatrix.sync.aligned.m8n8.x4.trans.shared.b16 {%0,%1,%2,%3},[%4];"
                 : "=r"(r[0]), "=r"(r[1]), "=r"(r[2]), "=r"(r[3]) : "r"(a));
}
__device__ __forceinline__ void mma16(float* c, const uint32_t* a, const uint32_t* b) {
    asm volatile(
        "mma.sync.aligned.m16n8k16.row.col.f32.f16.f16.f32 "
        "{%0,%1,%2,%3},{%4,%5,%6,%7},{%8,%9},{%0,%1,%2,%3};"
        : "+f"(c[0]), "+f"(c[1]), "+f"(c[2]), "+f"(c[3])
        : "r"(a[0]), "r"(a[1]), "r"(a[2]), "r"(a[3]), "r"(b[0]), "r"(b[1]));
}

#define ASTRIDE 48
#define BSTRIDE 272
#define ABYTES (128 * ASTRIDE)
#define BBYTES (16 * BSTRIDE)

__device__ __forceinline__ int perm_px(int p) {
    int h = p >> 8, w = p & 255;
    return (((h >> 3) * 32 + (w >> 3)) << 6) + ((h & 7) << 3) + (w & 7);
}

// ---------------------------------------------------------------------------
// Prep kernels
// ---------------------------------------------------------------------------
__global__ void prep_kernel(const float* __restrict__ g1, const float* __restrict__ b1,
                            const float* __restrict__ m1, const float* __restrict__ v1,
                            const float* __restrict__ g2, const float* __restrict__ b2,
                            const float* __restrict__ m2, const float* __restrict__ v2,
                            const float* __restrict__ gp, const float* __restrict__ bp,
                            const float* __restrict__ mp, const float* __restrict__ vp)
{
    int c = threadIdx.x;
    float i1 = g1[c] * rsqrtf(v1[c] + 1e-5f);
    float i2 = g2[c] * rsqrtf(v2[c] + 1e-5f);
    g_inv1[c] = i1;
    g_inv2[c] = i2;
    g_biasc[c] = (b1[c] - m1[c] * i1) + (b2[c] - m2[c] * i2);
    float ip = gp[c] * rsqrtf(vp[c] + 1e-5f);
    g_invp[c] = ip;
    g_biasp[c] = bp[c] - mp[c] * ip;
}

__global__ void cvt_wqkv(const float* __restrict__ w)
{
    int i = blockIdx.x * 256 + threadIdx.x;
    if (i >= 768 * 256) return;
    float sc = (i < 256 * 256) ? 0.25f : 1.0f;
    g_wqh[i] = h16(w[i] * sc);
}
__global__ void split_wpw(const float* __restrict__ w)
{
    int i = blockIdx.x * 256 + threadIdx.x;
    splt16(w[i], g_wph[i], g_wpl[i]);
}
__global__ void cvt_wlocal(const float* __restrict__ w1, const float* __restrict__ w2)
{
    int i = blockIdx.x * 256 + threadIdx.x;
    if (i >= 256 * 2560) return;
    int m = i / 2560, k = i - m * 2560;
    float v = (k < 2304) ? w1[m * 2304 + k] * g_inv1[m]
                         : w2[m * 256 + (k - 2304)] * g_inv2[m];
    g_wlh[i] = h16(v);
}
__global__ void cvt_x(const float* __restrict__ x)
{
    size_t base = ((size_t)blockIdx.x * 256 + threadIdx.x) * 4;
    float4 v = *(const float4*)(x + base);
    u16 h[4] = { h16(v.x), h16(v.y), h16(v.z), h16(v.w) };
    *(uint2*)(g_xh + base) = *(uint2*)h;
}
__global__ void cvt_y(const float* __restrict__ y)
{
    size_t base = ((size_t)blockIdx.x * 256 + threadIdx.x) * 4;
    float4 v = *(const float4*)(y + base);
    u16 h[4] = { h16(v.x), h16(v.y), h16(v.z), h16(v.w) };
    *(uint2*)(g_yh + base) = *(uint2*)h;
}

// ---------------------------------------------------------------------------
// Consumer: one K=16 step.  TWOPASS: (Ah + Al) * B, else Ah * B.
// ---------------------------------------------------------------------------
template <bool TWOPASS>
__device__ __forceinline__ void mma_step(
    uint32_t sAh, uint32_t sAl, uint32_t sB,
    int wm, int wn, int lane, float acc[4][4][4])
{
    int t  = lane >> 3;
    int r8 = lane & 7;
    uint32_t bh[4][2];
#pragma unroll
    for (int ng = 0; ng < 2; ++ng) {
        uint32_t addr = ((t >> 1) * 8 + r8) * BSTRIDE + (wn + ng * 16 + (t & 1) * 8) * 2;
        uint32_t tb[4];
        ldsm4t(tb, sB + addr);
        bh[ng * 2 + 0][0] = tb[0]; bh[ng * 2 + 0][1] = tb[2];
        bh[ng * 2 + 1][0] = tb[1]; bh[ng * 2 + 1][1] = tb[3];
    }
    uint32_t abase = ((t & 1) * 8 + r8) * ASTRIDE + (t >> 1) * 16;
#pragma unroll
    for (int mt = 0; mt < 4; ++mt) {
        uint32_t arow = abase + (wm + mt * 16) * ASTRIDE;
        uint32_t ah[4];
        ldsm4(ah, sAh + arow);
#pragma unroll
        for (int j = 0; j < 4; ++j) mma16(acc[mt][j], ah, bh[j]);
        if (TWOPASS) {
            uint32_t al[4];
            ldsm4(al, sAl + arow);
#pragma unroll
            for (int j = 0; j < 4; ++j) mma16(acc[mt][j], al, bh[j]);
        }
    }
}

// ---------------------------------------------------------------------------
// qkv GEMM: A = wqkv fp16 (M=768,K=256), B = x, C = g_qkvh (fp16, permuted)
// grid = (6, 1024)
// ---------------------------------------------------------------------------
__global__ __launch_bounds__(256, 2) void gemm_qkv(void)
{
    __shared__ __align__(16) char AhS[2][ABYTES];
    __shared__ __align__(16) char BS [2][BBYTES];

    const int M = 768, K = 256;
    int tid = threadIdx.x;
    int m0  = blockIdx.x * 128;
    int pg0 = blockIdx.y * 128;
    int b   = pg0 >> 16;
    int p0  = pg0 & 65535;
    int lane = tid & 31, warp = tid >> 5;
    int wm = (warp >> 2) * 64, wn = (warp & 3) * 32;

    int am = tid >> 1, ak = (tid & 1) * 8;
    const u16* Abh = g_wqh + (size_t)(m0 + am) * K + ak;
    int bk = tid >> 4, bn = (tid & 15) * 8;
    size_t bbase = ((size_t)(b * K + bk) << 16) + p0 + bn;

    int aoff = am * ASTRIDE + ak * 2;
    int boff = bk * BSTRIDE + bn * 2;

    float acc[4][4][4];
#pragma unroll
    for (int i = 0; i < 4; ++i)
#pragma unroll
        for (int j = 0; j < 4; ++j)
#pragma unroll
            for (int r = 0; r < 4; ++r) acc[i][j][r] = 0.f;

    uint4 rah, rb;
    auto gload = [&](int k0) {
        rah = *(const uint4*)(Abh + k0);
        rb  = *(const uint4*)(g_xh + bbase + ((size_t)k0 << 16));
    };
    auto sstore = [&](int s) {
        *(uint4*)(AhS[s] + aoff) = rah;
        *(uint4*)(BS[s]  + boff) = rb;
    };

    const int nch = 16;
    gload(0);
    sstore(0);
    gload(16);
    __syncthreads();

    for (int ch = 0; ch < nch; ++ch) {
        if (ch + 1 < nch) sstore((ch + 1) & 1);
        if (ch + 2 < nch) gload((ch + 2) << 4);
        int s = ch & 1;
        mma_step<false>(smem_u32(AhS[s]), 0, smem_u32(BS[s]), wm, wn, lane, acc);
        __syncthreads();
    }

    int g = lane >> 2, tig = lane & 3;
#pragma unroll
    for (int mt = 0; mt < 4; ++mt) {
        int r0 = m0 + wm + mt * 16 + g;
#pragma unroll
        for (int j = 0; j < 4; ++j) {
            int col = p0 + wn + j * 8 + tig * 2;
            int pc = perm_px(col);
            size_t i0 = ((size_t)(b * M + r0) << 16) + pc;
            size_t i1 = ((size_t)(b * M + r0 + 8) << 16) + pc;
            *(uint32_t*)&g_qkvh[i0] = h2bits(acc[mt][j][0], acc[mt][j][1]);
            *(uint32_t*)&g_qkvh[i1] = h2bits(acc[mt][j][2], acc[mt][j][3]);
        }
    }
}

// ---------------------------------------------------------------------------
// pw GEMM (2-pass, output-facing): A = wpw hi/lo (M=256,K=256), B = dw
// grid = (2, 1024)
// ---------------------------------------------------------------------------
__global__ __launch_bounds__(256, 2) void gemm_pw(float* __restrict__ C)
{
    __shared__ __align__(16) char AhS[2][ABYTES];
    __shared__ __align__(16) char AlS[2][ABYTES];
    __shared__ __align__(16) char BS [2][BBYTES];

    const int M = 256, K = 256;
    int tid = threadIdx.x;
    int m0  = blockIdx.x * 128;
    int pg0 = blockIdx.y * 128;
    int b   = pg0 >> 16;
    int p0  = pg0 & 65535;
    int lane = tid & 31, warp = tid >> 5;
    int wm = (warp >> 2) * 64, wn = (warp & 3) * 32;

    int am = tid >> 1, ak = (tid & 1) * 8;
    const u16* Abh = g_wph + (size_t)(m0 + am) * K + ak;
    const u16* Abl = g_wpl + (size_t)(m0 + am) * K + ak;
    int bk = tid >> 4, bn = (tid & 15) * 8;
    size_t bbase = ((size_t)(b * K + bk) << 16) + p0 + bn;

    int aoff = am * ASTRIDE + ak * 2;
    int boff = bk * BSTRIDE + bn * 2;

    float acc[4][4][4];
#pragma unroll
    for (int i = 0; i < 4; ++i)
#pragma unroll
        for (int j = 0; j < 4; ++j)
#pragma unroll
            for (int r = 0; r < 4; ++r) acc[i][j][r] = 0.f;

    uint4 rah, ral, rb;
    auto gload = [&](int k0) {
        rah = *(const uint4*)(Abh + k0);
        ral = *(const uint4*)(Abl + k0);
        rb  = *(const uint4*)(g_dwh + bbase + ((size_t)k0 << 16));
    };
    auto sstore = [&](int s) {
        *(uint4*)(AhS[s] + aoff) = rah;
        *(uint4*)(AlS[s] + aoff) = ral;
        *(uint4*)(BS[s]  + boff) = rb;
    };

    const int nch = 16;
    gload(0);
    sstore(0);
    gload(16);
    __syncthreads();

    for (int ch = 0; ch < nch; ++ch) {
        if (ch + 1 < nch) sstore((ch + 1) & 1);
        if (ch + 2 < nch) gload((ch + 2) << 4);
        int s = ch & 1;
        mma_step<true>(smem_u32(AhS[s]), smem_u32(AlS[s]), smem_u32(BS[s]),
                       wm, wn, lane, acc);
        __syncthreads();
    }

    int g = lane >> 2, tig = lane & 3;
#pragma unroll
    for (int mt = 0; mt < 4; ++mt) {
        int r0 = m0 + wm + mt * 16 + g;
#pragma unroll
        for (int j = 0; j < 4; ++j) {
            int col = p0 + wn + j * 8 + tig * 2;
            size_t i0 = ((size_t)(b * M + r0) << 16) + col;
            size_t i1 = ((size_t)(b * M + r0 + 8) << 16) + col;
            *(float2*)&C[i0] = make_float2(acc[mt][j][0], acc[mt][j][1]);
            *(float2*)&C[i1] = make_float2(acc[mt][j][2], acc[mt][j][3]);
        }
    }
}

// ---------------------------------------------------------------------------
// Fused local branch GEMM (1-pass fp16), K=2560, B gathered from g_yh.
// grid = (2, 1024)
// ---------------------------------------------------------------------------
__global__ __launch_bounds__(256, 2) void gemm_local_f16(void)
{
    __shared__ __align__(16) char AhS[2][ABYTES];
    __shared__ __align__(16) char BS [2][BBYTES];

    int tid = threadIdx.x;
    int m0  = blockIdx.x * 128;
    int pg0 = blockIdx.y * 128;
    int b   = pg0 >> 16;
    int p0  = pg0 & 65535;
    int h   = p0 >> 8;
    int w0  = p0 & 255;
    int lane = tid & 31, warp = tid >> 5;
    int wm = (warp >> 2) * 64, wn = (warp & 3) * 32;

    int am = tid >> 1, ak = (tid & 1) * 8;
    int mg = m0 + am;
    int bk = tid >> 4, bn = (tid & 15) * 8;

    int aoff = am * ASTRIDE + ak * 2;
    int boff = bk * BSTRIDE + bn * 2;

    const u16* Abh = g_wlh + (size_t)mg * 2560 + ak;

    float acc[4][4][4];
#pragma unroll
    for (int i = 0; i < 4; ++i)
#pragma unroll
        for (int j = 0; j < 4; ++j)
#pragma unroll
            for (int r = 0; r < 4; ++r) acc[i][j][r] = 0.f;

    uint4 rah, rb;
    auto gload = [&](int k0) {
        rah = *(const uint4*)(Abh + k0);
        int k = k0 + bk;
        int ci, dy, dx;
        if (k < 2304) {
            ci = k / 9;
            int tap = k - ci * 9;
            int r = tap / 3;
            dy = r - 1;
            dx = tap - r * 3 - 1;
        } else { ci = k - 2304; dy = 0; dx = 0; }
        int hh = h + dy;
        bool hok = (hh >= 0) && (hh < 256);
        const u16* row = g_yh + ((size_t)(b * 256 + ci) << 16) + hh * 256;
        uint32_t v[8];
#pragma unroll
        for (int j = 0; j < 8; ++j) {
            int ww = w0 + bn + j + dx;
            v[j] = (hok && ww >= 0 && ww < 256) ? (uint32_t)row[ww] : 0u;
        }
        uint32_t* pb = (uint32_t*)&rb;
#pragma unroll
        for (int j = 0; j < 4; ++j) pb[j] = v[2 * j] | (v[2 * j + 1] << 16);
    };
    auto sstore = [&](int s) {
        *(uint4*)(AhS[s] + aoff) = rah;
        *(uint4*)(BS[s]  + boff) = rb;
    };

    const int nch = 160;
    gload(0);
    sstore(0);
    gload(16);
    __syncthreads();

    for (int ch = 0; ch < nch; ++ch) {
        if (ch + 1 < nch) sstore((ch + 1) & 1);
        if (ch + 2 < nch) gload((ch + 2) << 4);
        int s = ch & 1;
        mma_step<false>(smem_u32(AhS[s]), 0, smem_u32(BS[s]), wm, wn, lane, acc);
        __syncthreads();
    }

    int g = lane >> 2, tig = lane & 3;
#pragma unroll
    for (int mt = 0; mt < 4; ++mt) {
        int r0 = m0 + wm + mt * 16 + g;
        float bi0 = g_biasc[r0];
        float bi1 = g_biasc[r0 + 8];
#pragma unroll
        for (int j = 0; j < 4; ++j) {
            int col = p0 + wn + j * 8 + tig * 2;
            size_t i0 = ((size_t)(b * 256 + r0) << 16) + col;
            size_t i1 = ((size_t)(b * 256 + r0 + 8) << 16) + col;
            *(float2*)&g_local[i0] = make_float2(acc[mt][j][0] + bi0, acc[mt][j][1] + bi0);
            *(float2*)&g_local[i1] = make_float2(acc[mt][j][2] + bi1, acc[mt][j][3] + bi1);
        }
    }
}

// ---------------------------------------------------------------------------
// Tensor-core windowed attention: 1 warp = 1 (window, head).
// Q/K/V in dim-major smem fp16; QK^T 4x8 m16n8k16 tiles; full-row softmax
// (shfl over 4-lane groups); P fed as fp16 A-frags into PV (C->A layout trick).
// ---------------------------------------------------------------------------
#define QSTR 72    // smem row stride (u16) for 64 tokens + pad

__global__ __launch_bounds__(128) void attn_mma(const float* __restrict__ rpb)
{
    __shared__ u16 qkvS[4][48][QSTR];
    __shared__ float rpbs[225];

    int tid  = threadIdx.x;
    int warp = tid >> 5, lane = tid & 31;
    int head = blockIdx.y;
    int win  = blockIdx.x * 4 + warp;
    int b    = win >> 10;
    int wloc = win & 1023;

    for (int t = tid; t < 225; t += 128) rpbs[t] = rpb[t * 16 + head];

    // load 48 rows (q:0-15, k:16-31, v:32-47) x 64 tokens, uint2 = 4 tokens
    {
        int ppb = wloc * 64;
        for (int f = lane; f < 768; f += 32) {
            int row = f >> 4;
            int c4  = (f & 15) * 4;
            int ch  = b * 768 + head * 16 + (row & 15) + (row >> 4) * 256;
            uint2 v = *(const uint2*)(g_qkvh + (((size_t)ch) << 16) + ppb + c4);
            *(uint2*)&qkvS[warp][row][c4] = v;
        }
    }
    __syncthreads();

    uint32_t sQ = smem_u32(&qkvS[warp][0][0]);
    uint32_t sK = smem_u32(&qkvS[warp][16][0]);
    uint32_t sV = smem_u32(&qkvS[warp][32][0]);

    int t = lane >> 3, r8 = lane & 7;
    int g = lane >> 2, tig = lane & 3;

    // K fragments: 8 n-tiles (col-major B from [dim][token] smem)
    uint32_t bqk[8][2];
#pragma unroll
    for (int ng = 0; ng < 4; ++ng) {
        uint32_t addr = sK + (((t >> 1) * 8 + r8) * QSTR + ng * 16 + (t & 1) * 8) * 2;
        uint32_t tb[4];
        ldsm4t(tb, addr);
        bqk[2 * ng + 0][0] = tb[0]; bqk[2 * ng + 0][1] = tb[2];
        bqk[2 * ng + 1][0] = tb[1]; bqk[2 * ng + 1][1] = tb[3];
    }
    // V fragments: bv[kt][nd][2] (col-major B from [dim][token] via non-trans)
    uint32_t bv[4][2][2];
#pragma unroll
    for (int kt = 0; kt < 4; ++kt) {
        uint32_t addr = sV + (((t & 1) * 8 + r8) * QSTR + kt * 16 + (t >> 1) * 8) * 2;
        uint32_t tb[4];
        ldsm4(tb, addr);
        bv[kt][0][0] = tb[0]; bv[kt][0][1] = tb[2];
        bv[kt][1][0] = tb[1]; bv[kt][1][1] = tb[3];
    }

    int wy = wloc >> 5, wx = wloc & 31;

#pragma unroll
    for (int mt = 0; mt < 4; ++mt) {
        // Q A-fragment via trans-ldmatrix from [dim][token]
        uint32_t aQ[4];
        ldsm4t(aQ, sQ + (((t >> 1) * 8 + r8) * QSTR + mt * 16 + (t & 1) * 8) * 2);

        float s[8][4];
#pragma unroll
        for (int nt = 0; nt < 8; ++nt) {
            s[nt][0] = s[nt][1] = s[nt][2] = s[nt][3] = 0.f;
            mma16(s[nt], aQ, bqk[nt]);
        }

        int row0 = mt * 16 + g, row1 = row0 + 8;
        int yi0 = row0 >> 3, xi0 = row0 & 7;
        int yi1 = row1 >> 3, xi1 = row1 & 7;
        float mx0 = -1e30f, mx1 = -1e30f;
#pragma unroll
        for (int nt = 0; nt < 8; ++nt) {
            int col = nt * 8 + tig * 2;
            int yj = col >> 3, xj = col & 7;
            s[nt][0] += rpbs[(yi0 - yj + 7) * 15 + (xi0 - xj + 7)];
            s[nt][1] += rpbs[(yi0 - yj + 7) * 15 + (xi0 - xj + 6)];
            s[nt][2] += rpbs[(yi1 - yj + 7) * 15 + (xi1 - xj + 7)];
            s[nt][3] += rpbs[(yi1 - yj + 7) * 15 + (xi1 - xj + 6)];
            mx0 = fmaxf(mx0, fmaxf(s[nt][0], s[nt][1]));
            mx1 = fmaxf(mx1, fmaxf(s[nt][2], s[nt][3]));
        }
        mx0 = fmaxf(mx0, __shfl_xor_sync(0xffffffffu, mx0, 1));
        mx0 = fmaxf(mx0, __shfl_xor_sync(0xffffffffu, mx0, 2));
        mx1 = fmaxf(mx1, __shfl_xor_sync(0xffffffffu, mx1, 1));
        mx1 = fmaxf(mx1, __shfl_xor_sync(0xffffffffu, mx1, 2));

        float sum0 = 0.f, sum1 = 0.f;
#pragma unroll
        for (int nt = 0; nt < 8; ++nt) {
            s[nt][0] = __expf(s[nt][0] - mx0);
            s[nt][1] = __expf(s[nt][1] - mx0);
            s[nt][2] = __expf(s[nt][2] - mx1);
            s[nt][3] = __expf(s[nt][3] - mx1);
            sum0 += s[nt][0] + s[nt][1];
            sum1 += s[nt][2] + s[nt][3];
        }
        sum0 += __shfl_xor_sync(0xffffffffu, sum0, 1);
        sum0 += __shfl_xor_sync(0xffffffffu, sum0, 2);
        sum1 += __shfl_xor_sync(0xffffffffu, sum1, 1);
        sum1 += __shfl_xor_sync(0xffffffffu, sum1, 2);
        float inv0 = 1.f / sum0, inv1 = 1.f / sum1;

        // PV: P (unnormalized exp) as fp16 A-frags, accumulate O
        float o[2][4];
        o[0][0]=o[0][1]=o[0][2]=o[0][3]=0.f;
        o[1][0]=o[1][1]=o[1][2]=o[1][3]=0.f;
#pragma unroll
        for (int kt = 0; kt < 4; ++kt) {
            uint32_t aP[4];
            aP[0] = h2bits(s[2 * kt][0],     s[2 * kt][1]);
            aP[1] = h2bits(s[2 * kt][2],     s[2 * kt][3]);
            aP[2] = h2bits(s[2 * kt + 1][0], s[2 * kt + 1][1]);
            aP[3] = h2bits(s[2 * kt + 1][2], s[2 * kt + 1][3]);
            mma16(o[0], aP, bv[kt][0]);
            mma16(o[1], aP, bv[kt][1]);
        }

        int p0 = ((wy * 8 + yi0) << 8) + wx * 8 + xi0;
        int p1 = ((wy * 8 + yi1) << 8) + wx * 8 + xi1;
#pragma unroll
        for (int nd = 0; nd < 2; ++nd) {
            int ch0 = b * 256 + head * 16 + nd * 8 + tig * 2;
            g_attn[(((size_t)ch0)     << 16) + p0] = o[nd][0] * inv0;
            g_attn[(((size_t)ch0 + 1) << 16) + p0] = o[nd][1] * inv0;
            g_attn[(((size_t)ch0)     << 16) + p1] = o[nd][2] * inv1;
            g_attn[(((size_t)ch0 + 1) << 16) + p1] = o[nd][3] * inv1;
        }
    }
}

// ---------------------------------------------------------------------------
// Fused pool + depthwise 8x8 conv + BN -> single fp16 output g_dwh.
// ---------------------------------------------------------------------------
__global__ __launch_bounds__(256) void dwpool_kernel(const float* __restrict__ w_dw)
{
    __shared__ float attnS[46][48];
    __shared__ float midS[39][40];
    __shared__ float ws[64];

    int tix = blockIdx.x;
    int bc  = blockIdx.y;
    int c   = bc & 255;
    int ty0 = (tix >> 3) * 32;
    int tx0 = (tix & 7) * 32;
    int tid = threadIdx.x;

    const float* aplane = g_attn + ((size_t)bc << 16);
    const float* lplane = g_local + ((size_t)bc << 16);

    for (int idx = tid; idx < 46 * 46; idx += 256) {
        int r  = idx / 46;
        int cc = idx - r * 46;
        int gh = ty0 - 6 + r;
        int gw = tx0 - 6 + cc;
        float v = 0.f;
        if (gh >= 0 && gh < 256 && gw >= 0 && gw < 256) v = aplane[gh * 256 + gw];
        attnS[r][cc] = v;
    }
    if (tid < 64) ws[tid] = w_dw[c * 64 + tid];
    __syncthreads();

    for (int idx = tid; idx < 39 * 39; idx += 256) {
        int r  = idx / 39;
        int cc = idx - r * 39;
        int gh = ty0 - 3 + r;
        int gw = tx0 - 3 + cc;
        float v = 0.f;
        if (gh >= 0 && gh <= 256 && gw >= 0 && gw <= 256) {
            int gh2 = (gh == 256) ? 254 : gh;
            int gw2 = (gw == 256) ? 254 : gw;
            int co = gw2 - (tx0 - 6);
            float vs = 0.f;
#pragma unroll
            for (int tt2 = gh2 - 3; tt2 <= gh2 + 4; ++tt2) {
                if (tt2 >= 0 && tt2 <= 256) {
                    int tt = (tt2 == 256) ? 254 : tt2;
                    vs += attnS[tt - (ty0 - 6)][co];
                }
            }
            int ro = gh2 - (ty0 - 6);
            float hs = 0.f;
#pragma unroll
            for (int ss2 = gw2 - 3; ss2 <= gw2 + 4; ++ss2) {
                if (ss2 >= 0 && ss2 <= 256) {
                    int ss = (ss2 == 256) ? 254 : ss2;
                    hs += attnS[ro][ss - (tx0 - 6)];
                }
            }
            v = (vs + hs) * 0.125f + lplane[gh2 * 256 + gw2];
        }
        midS[r][cc] = v;
    }
    __syncthreads();

    int lw  = tid & 31;
    int lh0 = (tid >> 5) * 4;
    float acc[4] = {0.f, 0.f, 0.f, 0.f};
#pragma unroll
    for (int j = 0; j < 8; ++j) {
        float wcol[8];
#pragma unroll
        for (int i = 0; i < 8; ++i) wcol[i] = ws[i * 8 + j];
#pragma unroll
        for (int r = 0; r < 11; ++r) {
            float v = midS[lh0 + r][lw + j];
#pragma unroll
            for (int a = 0; a < 4; ++a) {
                int i = r - a;
                if (i >= 0 && i < 8) acc[a] += v * wcol[i];
            }
        }
    }
    float ip = g_invp[c];
    float bb = g_biasp[c];
#pragma unroll
    for (int a = 0; a < 4; ++a) {
        int h = ty0 + lh0 + a;
        float r = acc[a] * ip + bb;
        size_t idx = ((size_t)bc << 16) + h * 256 + tx0 + lw;
        g_dwh[idx] = h16(r);
    }
}

// ---------------------------------------------------------------------------
// Launch
// ---------------------------------------------------------------------------
extern "C" void kernel_launch(void* const* d_in, const int* in_sizes, int n_in,
                              void* d_out, int out_size)
{
    const float* x    = (const float*)d_in[0];
    const float* y    = (const float*)d_in[1];
    const float* wqkv = (const float*)d_in[2];
    const float* wl1  = (const float*)d_in[3];
    const float* g1   = (const float*)d_in[4];
    const float* b1   = (const float*)d_in[5];
    const float* m1   = (const float*)d_in[6];
    const float* v1   = (const float*)d_in[7];
    const float* wl2  = (const float*)d_in[8];
    const float* g2   = (const float*)d_in[9];
    const float* b2   = (const float*)d_in[10];
    const float* m2   = (const float*)d_in[11];
    const float* v2   = (const float*)d_in[12];
    const float* wdw  = (const float*)d_in[13];
    const float* gp   = (const float*)d_in[14];
    const float* bp   = (const float*)d_in[15];
    const float* mp   = (const float*)d_in[16];
    const float* vp   = (const float*)d_in[17];
    const float* wpw  = (const float*)d_in[18];
    const float* rpb  = (const float*)d_in[19];
    float* out = (float*)d_out;

    prep_kernel<<<1, 256>>>(g1, b1, m1, v1, g2, b2, m2, v2, gp, bp, mp, vp);
    cvt_wqkv<<<768, 256>>>(wqkv);
    split_wpw<<<256, 256>>>(wpw);
    cvt_wlocal<<<2560, 256>>>(wl1, wl2);
    cvt_x<<<32768, 256>>>(x);
    cvt_y<<<32768, 256>>>(y);

    // local branch (K=2560, 1-pass fp16) -> g_local
    gemm_local_f16<<<dim3(2, 1024), 256>>>();

    // qkv (M=768, K=256, 1-pass fp16) -> g_qkvh (fp16, window-major)
    gemm_qkv<<<dim3(6, 1024), 256>>>();

    // tensor-core attention (4 window-heads per block)
    attn_mma<<<dim3(512, 16), 128>>>(rpb);

    // fused pools + depthwise conv + BN -> g_dwh (fp16)
    dwpool_kernel<<<dim3(64, 512), 256>>>(wdw);

    // pointwise (M=256, K=256, 2-pass) -> out
    gemm_pw<<<dim3(2, 1024), 256>>>(out);
}

// round 13
// speedup vs baseline: 3.2974x; 1.0172x over previous
#include <cuda_runtime.h>
#include <cuda_fp16.h>
#include <math.h>
#include <stdint.h>

// ---------------------------------------------------------------------------
// Problem constants: B=2, C=256, H=W=256, SSM=256, NH=16, HD=16, WS=8
// ---------------------------------------------------------------------------
#define PPLANE 65536
#define NBATCH 2

typedef unsigned long long u64;
typedef unsigned short u16;

__device__ float g_local[NBATCH * 256 * PPLANE];
__device__ u16   g_qkvh [NBATCH * 768 * PPLANE];   // fp16, window-major pixels
__device__ u16   g_attnh[NBATCH * 256 * PPLANE];   // fp16 attention output

// pre-converted fp16 operands
__device__ u16 g_xh [NBATCH * 256 * PPLANE];
__device__ u16 g_yh [NBATCH * 256 * PPLANE];
__device__ u16 g_dwh[NBATCH * 256 * PPLANE];
__device__ u16 g_wqh [768 * 256];                  // single-pass fp16
__device__ u16 g_wph [256 * 256];                  // single-pass fp16
__device__ u16 g_wlh [256 * 2560];                 // single-pass fp16

__device__ float g_inv1[256], g_inv2[256], g_biasc[256], g_invp[256], g_biasp[256];

// ---------------------------------------------------------------------------
// helpers
// ---------------------------------------------------------------------------
__device__ __forceinline__ uint32_t smem_u32(const void* p) {
    uint32_t a;
    asm("{ .reg .u64 t; cvta.to.shared.u64 t, %1; cvt.u32.u64 %0, t; }"
        : "=r"(a) : "l"(p));
    return a;
}
__device__ __forceinline__ u16 h16(float v) {
    __half h = __float2half_rn(v);
    return *reinterpret_cast<u16*>(&h);
}
__device__ __forceinline__ float f16f(u16 v) {
    __half h = *reinterpret_cast<__half*>(&v);
    return __half2float(h);
}
__device__ __forceinline__ uint32_t h2bits(float a, float b) {
    __half2 h = __floats2half2_rn(a, b);
    return *reinterpret_cast<uint32_t*>(&h);
}
__device__ __forceinline__ void ldsm4(uint32_t* r, uint32_t a) {
    asm volatile("ldmatrix.sync.aligned.m8n8.x4.shared.b16 {%0,%1,%2,%3},[%4];"
                 : "=r"(r[0]), "=r"(r[1]), "=r"(r[2]), "=r"(r[3]) : "r"(a));
}
__device__ __forceinline__ void ldsm4t(uint32_t* r, uint32_t a) {
    asm volatile("ldmatrix.sync.aligned.m8n8.x4.trans.shared.b16 {%0,%1,%2,%3},[%4];"
                 : "=r"(r[0]), "=r"(r[1]), "=r"(r[2]), "=r"(r[3]) : "r"(a));
}
__device__ __forceinline__ void mma16(float* c, const uint32_t* a, const uint32_t* b) {
    asm volatile(
        "mma.sync.aligned.m16n8k16.row.col.f32.f16.f16.f32 "
        "{%0,%1,%2,%3},{%4,%5,%6,%7},{%8,%9},{%0,%1,%2,%3};"
        : "+f"(c[0]), "+f"(c[1]), "+f"(c[2]), "+f"(c[3])
        : "r"(a[0]), "r"(a[1]), "r"(a[2]), "r"(a[3]), "r"(b[0]), "r"(b[1]));
}

#define ASTRIDE 48
#define BSTRIDE 272
#define ABYTES (128 * ASTRIDE)
#define BBYTES (16 * BSTRIDE)

__device__ __forceinline__ int perm_px(int p) {
    int h = p >> 8, w = p & 255;
    return (((h >> 3) * 32 + (w >> 3)) << 6) + ((h & 7) << 3) + (w & 7);
}

// ---------------------------------------------------------------------------
// Prep kernels
// ---------------------------------------------------------------------------
__global__ void prep_kernel(const float* __restrict__ g1, const float* __restrict__ b1,
                            const float* __restrict__ m1, const float* __restrict__ v1,
                            const float* __restrict__ g2, const float* __restrict__ b2,
                            const float* __restrict__ m2, const float* __restrict__ v2,
                            const float* __restrict__ gp, const float* __restrict__ bp,
                            const float* __restrict__ mp, const float* __restrict__ vp)
{
    int c = threadIdx.x;
    float i1 = g1[c] * rsqrtf(v1[c] + 1e-5f);
    float i2 = g2[c] * rsqrtf(v2[c] + 1e-5f);
    g_inv1[c] = i1;
    g_inv2[c] = i2;
    g_biasc[c] = (b1[c] - m1[c] * i1) + (b2[c] - m2[c] * i2);
    float ip = gp[c] * rsqrtf(vp[c] + 1e-5f);
    g_invp[c] = ip;
    g_biasp[c] = bp[c] - mp[c] * ip;
}

__global__ void cvt_wqkv(const float* __restrict__ w)
{
    int i = blockIdx.x * 256 + threadIdx.x;
    if (i >= 768 * 256) return;
    float sc = (i < 256 * 256) ? 0.25f : 1.0f;
    g_wqh[i] = h16(w[i] * sc);
}
__global__ void cvt_wpw(const float* __restrict__ w)
{
    int i = blockIdx.x * 256 + threadIdx.x;
    g_wph[i] = h16(w[i]);
}
__global__ void cvt_wlocal(const float* __restrict__ w1, const float* __restrict__ w2)
{
    int i = blockIdx.x * 256 + threadIdx.x;
    if (i >= 256 * 2560) return;
    int m = i / 2560, k = i - m * 2560;
    float v = (k < 2304) ? w1[m * 2304 + k] * g_inv1[m]
                         : w2[m * 256 + (k - 2304)] * g_inv2[m];
    g_wlh[i] = h16(v);
}
__global__ void cvt_x(const float* __restrict__ x)
{
    size_t base = ((size_t)blockIdx.x * 256 + threadIdx.x) * 4;
    float4 v = *(const float4*)(x + base);
    u16 h[4] = { h16(v.x), h16(v.y), h16(v.z), h16(v.w) };
    *(uint2*)(g_xh + base) = *(uint2*)h;
}
__global__ void cvt_y(const float* __restrict__ y)
{
    size_t base = ((size_t)blockIdx.x * 256 + threadIdx.x) * 4;
    float4 v = *(const float4*)(y + base);
    u16 h[4] = { h16(v.x), h16(v.y), h16(v.z), h16(v.w) };
    *(uint2*)(g_yh + base) = *(uint2*)h;
}

// ---------------------------------------------------------------------------
// Consumer: one K=16 step, 1-pass fp16.
// ---------------------------------------------------------------------------
__device__ __forceinline__ void mma_step(
    uint32_t sAh, uint32_t sB,
    int wm, int wn, int lane, float acc[4][4][4])
{
    int t  = lane >> 3;
    int r8 = lane & 7;
    uint32_t bh[4][2];
#pragma unroll
    for (int ng = 0; ng < 2; ++ng) {
        uint32_t addr = ((t >> 1) * 8 + r8) * BSTRIDE + (wn + ng * 16 + (t & 1) * 8) * 2;
        uint32_t tb[4];
        ldsm4t(tb, sB + addr);
        bh[ng * 2 + 0][0] = tb[0]; bh[ng * 2 + 0][1] = tb[2];
        bh[ng * 2 + 1][0] = tb[1]; bh[ng * 2 + 1][1] = tb[3];
    }
    uint32_t abase = ((t & 1) * 8 + r8) * ASTRIDE + (t >> 1) * 16;
#pragma unroll
    for (int mt = 0; mt < 4; ++mt) {
        uint32_t arow = abase + (wm + mt * 16) * ASTRIDE;
        uint32_t ah[4];
        ldsm4(ah, sAh + arow);
#pragma unroll
        for (int j = 0; j < 4; ++j) mma16(acc[mt][j], ah, bh[j]);
    }
}

// ---------------------------------------------------------------------------
// Aligned GEMM, 1-pass fp16, operands device-side.
//   which==0: A = wqkv (M=768,K=256), B = x,  C = g_qkvh (fp16, permuted)
//   which==1: A = wpw  (M=256,K=256), B = dw, C = extC (fp32)
// grid = (M/128, 1024)
// ---------------------------------------------------------------------------
__global__ __launch_bounds__(256, 2) void gemm_aligned(float* extC, int M, int K, int which)
{
    __shared__ __align__(16) char AhS[2][ABYTES];
    __shared__ __align__(16) char BS [2][BBYTES];

    const u16 *Ah_g, *B_g;
    if (which == 0) { Ah_g = g_wqh; B_g = g_xh; }
    else            { Ah_g = g_wph; B_g = g_dwh; }

    int tid = threadIdx.x;
    int m0  = blockIdx.x * 128;
    int pg0 = blockIdx.y * 128;
    int b   = pg0 >> 16;
    int p0  = pg0 & 65535;
    int lane = tid & 31, warp = tid >> 5;
    int wm = (warp >> 2) * 64, wn = (warp & 3) * 32;

    int am = tid >> 1, ak = (tid & 1) * 8;
    const u16* Abh = Ah_g + (size_t)(m0 + am) * K + ak;
    int bk = tid >> 4, bn = (tid & 15) * 8;
    size_t bbase = ((size_t)(b * K + bk) << 16) + p0 + bn;

    int aoff = am * ASTRIDE + ak * 2;
    int boff = bk * BSTRIDE + bn * 2;

    float acc[4][4][4];
#pragma unroll
    for (int i = 0; i < 4; ++i)
#pragma unroll
        for (int j = 0; j < 4; ++j)
#pragma unroll
            for (int r = 0; r < 4; ++r) acc[i][j][r] = 0.f;

    uint4 rah, rb;
    auto gload = [&](int k0) {
        rah = *(const uint4*)(Abh + k0);
        rb  = *(const uint4*)(B_g + bbase + ((size_t)k0 << 16));
    };
    auto sstore = [&](int s) {
        *(uint4*)(AhS[s] + aoff) = rah;
        *(uint4*)(BS[s]  + boff) = rb;
    };

    int nch = K >> 4;
    gload(0);
    sstore(0);
    if (nch > 1) gload(16);
    __syncthreads();

    for (int ch = 0; ch < nch; ++ch) {
        if (ch + 1 < nch) sstore((ch + 1) & 1);
        if (ch + 2 < nch) gload((ch + 2) << 4);
        int s = ch & 1;
        mma_step(smem_u32(AhS[s]), smem_u32(BS[s]), wm, wn, lane, acc);
        __syncthreads();
    }

    int g = lane >> 2, tig = lane & 3;
#pragma unroll
    for (int mt = 0; mt < 4; ++mt) {
        int r0 = m0 + wm + mt * 16 + g;
#pragma unroll
        for (int j = 0; j < 4; ++j) {
            int col = p0 + wn + j * 8 + tig * 2;
            if (which == 0) {
                int pc = perm_px(col);
                size_t i0 = ((size_t)(b * M + r0) << 16) + pc;
                size_t i1 = ((size_t)(b * M + r0 + 8) << 16) + pc;
                *(uint32_t*)&g_qkvh[i0] = h2bits(acc[mt][j][0], acc[mt][j][1]);
                *(uint32_t*)&g_qkvh[i1] = h2bits(acc[mt][j][2], acc[mt][j][3]);
            } else {
                size_t i0 = ((size_t)(b * M + r0) << 16) + col;
                size_t i1 = ((size_t)(b * M + r0 + 8) << 16) + col;
                *(float2*)&extC[i0] = make_float2(acc[mt][j][0], acc[mt][j][1]);
                *(float2*)&extC[i1] = make_float2(acc[mt][j][2], acc[mt][j][3]);
            }
        }
    }
}

// ---------------------------------------------------------------------------
// Fused local branch GEMM (1-pass fp16), K=2560, B gathered from g_yh.
// grid = (2, 1024)
// ---------------------------------------------------------------------------
__global__ __launch_bounds__(256, 2) void gemm_local_f16(void)
{
    __shared__ __align__(16) char AhS[2][ABYTES];
    __shared__ __align__(16) char BS [2][BBYTES];

    int tid = threadIdx.x;
    int m0  = blockIdx.x * 128;
    int pg0 = blockIdx.y * 128;
    int b   = pg0 >> 16;
    int p0  = pg0 & 65535;
    int h   = p0 >> 8;
    int w0  = p0 & 255;
    int lane = tid & 31, warp = tid >> 5;
    int wm = (warp >> 2) * 64, wn = (warp & 3) * 32;

    int am = tid >> 1, ak = (tid & 1) * 8;
    int mg = m0 + am;
    int bk = tid >> 4, bn = (tid & 15) * 8;

    int aoff = am * ASTRIDE + ak * 2;
    int boff = bk * BSTRIDE + bn * 2;

    const u16* Abh = g_wlh + (size_t)mg * 2560 + ak;

    float acc[4][4][4];
#pragma unroll
    for (int i = 0; i < 4; ++i)
#pragma unroll
        for (int j = 0; j < 4; ++j)
#pragma unroll
            for (int r = 0; r < 4; ++r) acc[i][j][r] = 0.f;

    uint4 rah, rb;
    auto gload = [&](int k0) {
        rah = *(const uint4*)(Abh + k0);
        int k = k0 + bk;
        int ci, dy, dx;
        if (k < 2304) {
            ci = k / 9;
            int tap = k - ci * 9;
            int r = tap / 3;
            dy = r - 1;
            dx = tap - r * 3 - 1;
        } else { ci = k - 2304; dy = 0; dx = 0; }
        int hh = h + dy;
        bool hok = (hh >= 0) && (hh < 256);
        const u16* row = g_yh + ((size_t)(b * 256 + ci) << 16) + hh * 256;
        uint32_t v[8];
#pragma unroll
        for (int j = 0; j < 8; ++j) {
            int ww = w0 + bn + j + dx;
            v[j] = (hok && ww >= 0 && ww < 256) ? (uint32_t)row[ww] : 0u;
        }
        uint32_t* pb = (uint32_t*)&rb;
#pragma unroll
        for (int j = 0; j < 4; ++j) pb[j] = v[2 * j] | (v[2 * j + 1] << 16);
    };
    auto sstore = [&](int s) {
        *(uint4*)(AhS[s] + aoff) = rah;
        *(uint4*)(BS[s]  + boff) = rb;
    };

    const int nch = 160;
    gload(0);
    sstore(0);
    gload(16);
    __syncthreads();

    for (int ch = 0; ch < nch; ++ch) {
        if (ch + 1 < nch) sstore((ch + 1) & 1);
        if (ch + 2 < nch) gload((ch + 2) << 4);
        int s = ch & 1;
        mma_step(smem_u32(AhS[s]), smem_u32(BS[s]), wm, wn, lane, acc);
        __syncthreads();
    }

    int g = lane >> 2, tig = lane & 3;
#pragma unroll
    for (int mt = 0; mt < 4; ++mt) {
        int r0 = m0 + wm + mt * 16 + g;
        float bi0 = g_biasc[r0];
        float bi1 = g_biasc[r0 + 8];
#pragma unroll
        for (int j = 0; j < 4; ++j) {
            int col = p0 + wn + j * 8 + tig * 2;
            size_t i0 = ((size_t)(b * 256 + r0) << 16) + col;
            size_t i1 = ((size_t)(b * 256 + r0 + 8) << 16) + col;
            *(float2*)&g_local[i0] = make_float2(acc[mt][j][0] + bi0, acc[mt][j][1] + bi0);
            *(float2*)&g_local[i1] = make_float2(acc[mt][j][2] + bi1, acc[mt][j][3] + bi1);
        }
    }
}

// ---------------------------------------------------------------------------
// Tensor-core windowed attention: 1 warp = 1 (window, head). fp16 output.
// ---------------------------------------------------------------------------
#define QSTR 72

__global__ __launch_bounds__(128) void attn_mma(const float* __restrict__ rpb)
{
    __shared__ u16 qkvS[4][48][QSTR];
    __shared__ float rpbs[225];

    int tid  = threadIdx.x;
    int warp = tid >> 5, lane = tid & 31;
    int head = blockIdx.y;
    int win  = blockIdx.x * 4 + warp;
    int b    = win >> 10;
    int wloc = win & 1023;

    for (int t = tid; t < 225; t += 128) rpbs[t] = rpb[t * 16 + head];

    {
        int ppb = wloc * 64;
        for (int f = lane; f < 768; f += 32) {
            int row = f >> 4;
            int c4  = (f & 15) * 4;
            int ch  = b * 768 + head * 16 + (row & 15) + (row >> 4) * 256;
            uint2 v = *(const uint2*)(g_qkvh + (((size_t)ch) << 16) + ppb + c4);
            *(uint2*)&qkvS[warp][row][c4] = v;
        }
    }
    __syncthreads();

    uint32_t sQ = smem_u32(&qkvS[warp][0][0]);
    uint32_t sK = smem_u32(&qkvS[warp][16][0]);
    uint32_t sV = smem_u32(&qkvS[warp][32][0]);

    int t = lane >> 3, r8 = lane & 7;
    int g = lane >> 2, tig = lane & 3;

    uint32_t bqk[8][2];
#pragma unroll
    for (int ng = 0; ng < 4; ++ng) {
        uint32_t addr = sK + (((t >> 1) * 8 + r8) * QSTR + ng * 16 + (t & 1) * 8) * 2;
        uint32_t tb[4];
        ldsm4t(tb, addr);
        bqk[2 * ng + 0][0] = tb[0]; bqk[2 * ng + 0][1] = tb[2];
        bqk[2 * ng + 1][0] = tb[1]; bqk[2 * ng + 1][1] = tb[3];
    }
    uint32_t bv[4][2][2];
#pragma unroll
    for (int kt = 0; kt < 4; ++kt) {
        uint32_t addr = sV + (((t & 1) * 8 + r8) * QSTR + kt * 16 + (t >> 1) * 8) * 2;
        uint32_t tb[4];
        ldsm4(tb, addr);
        bv[kt][0][0] = tb[0]; bv[kt][0][1] = tb[2];
        bv[kt][1][0] = tb[1]; bv[kt][1][1] = tb[3];
    }

    int wy = wloc >> 5, wx = wloc & 31;

#pragma unroll
    for (int mt = 0; mt < 4; ++mt) {
        uint32_t aQ[4];
        ldsm4t(aQ, sQ + (((t >> 1) * 8 + r8) * QSTR + mt * 16 + (t & 1) * 8) * 2);

        float s[8][4];
#pragma unroll
        for (int nt = 0; nt < 8; ++nt) {
            s[nt][0] = s[nt][1] = s[nt][2] = s[nt][3] = 0.f;
            mma16(s[nt], aQ, bqk[nt]);
        }

        int row0 = mt * 16 + g, row1 = row0 + 8;
        int yi0 = row0 >> 3, xi0 = row0 & 7;
        int yi1 = row1 >> 3, xi1 = row1 & 7;
        float mx0 = -1e30f, mx1 = -1e30f;
#pragma unroll
        for (int nt = 0; nt < 8; ++nt) {
            int col = nt * 8 + tig * 2;
            int yj = col >> 3, xj = col & 7;
            s[nt][0] += rpbs[(yi0 - yj + 7) * 15 + (xi0 - xj + 7)];
            s[nt][1] += rpbs[(yi0 - yj + 7) * 15 + (xi0 - xj + 6)];
            s[nt][2] += rpbs[(yi1 - yj + 7) * 15 + (xi1 - xj + 7)];
            s[nt][3] += rpbs[(yi1 - yj + 7) * 15 + (xi1 - xj + 6)];
            mx0 = fmaxf(mx0, fmaxf(s[nt][0], s[nt][1]));
            mx1 = fmaxf(mx1, fmaxf(s[nt][2], s[nt][3]));
        }
        mx0 = fmaxf(mx0, __shfl_xor_sync(0xffffffffu, mx0, 1));
        mx0 = fmaxf(mx0, __shfl_xor_sync(0xffffffffu, mx0, 2));
        mx1 = fmaxf(mx1, __shfl_xor_sync(0xffffffffu, mx1, 1));
        mx1 = fmaxf(mx1, __shfl_xor_sync(0xffffffffu, mx1, 2));

        float sum0 = 0.f, sum1 = 0.f;
#pragma unroll
        for (int nt = 0; nt < 8; ++nt) {
            s[nt][0] = __expf(s[nt][0] - mx0);
            s[nt][1] = __expf(s[nt][1] - mx0);
            s[nt][2] = __expf(s[nt][2] - mx1);
            s[nt][3] = __expf(s[nt][3] - mx1);
            sum0 += s[nt][0] + s[nt][1];
            sum1 += s[nt][2] + s[nt][3];
        }
        sum0 += __shfl_xor_sync(0xffffffffu, sum0, 1);
        sum0 += __shfl_xor_sync(0xffffffffu, sum0, 2);
        sum1 += __shfl_xor_sync(0xffffffffu, sum1, 1);
        sum1 += __shfl_xor_sync(0xffffffffu, sum1, 2);
        float inv0 = 1.f / sum0, inv1 = 1.f / sum1;

        float o[2][4];
        o[0][0]=o[0][1]=o[0][2]=o[0][3]=0.f;
        o[1][0]=o[1][1]=o[1][2]=o[1][3]=0.f;
#pragma unroll
        for (int kt = 0; kt < 4; ++kt) {
            uint32_t aP[4];
            aP[0] = h2bits(s[2 * kt][0],     s[2 * kt][1]);
            aP[1] = h2bits(s[2 * kt][2],     s[2 * kt][3]);
            aP[2] = h2bits(s[2 * kt + 1][0], s[2 * kt + 1][1]);
            aP[3] = h2bits(s[2 * kt + 1][2], s[2 * kt + 1][3]);
            mma16(o[0], aP, bv[kt][0]);
            mma16(o[1], aP, bv[kt][1]);
        }

        int p0 = ((wy * 8 + yi0) << 8) + wx * 8 + xi0;
        int p1 = ((wy * 8 + yi1) << 8) + wx * 8 + xi1;
#pragma unroll
        for (int nd = 0; nd < 2; ++nd) {
            int ch0 = b * 256 + head * 16 + nd * 8 + tig * 2;
            g_attnh[(((size_t)ch0)     << 16) + p0] = h16(o[nd][0] * inv0);
            g_attnh[(((size_t)ch0 + 1) << 16) + p0] = h16(o[nd][1] * inv0);
            g_attnh[(((size_t)ch0)     << 16) + p1] = h16(o[nd][2] * inv1);
            g_attnh[(((size_t)ch0 + 1) << 16) + p1] = h16(o[nd][3] * inv1);
        }
    }
}

// ---------------------------------------------------------------------------
// Fused pool + depthwise 8x8 conv + BN -> single fp16 output g_dwh.
// ---------------------------------------------------------------------------
__global__ __launch_bounds__(256) void dwpool_kernel(const float* __restrict__ w_dw)
{
    __shared__ float attnS[46][48];
    __shared__ float midS[39][40];
    __shared__ float ws[64];

    int tix = blockIdx.x;
    int bc  = blockIdx.y;
    int c   = bc & 255;
    int ty0 = (tix >> 3) * 32;
    int tx0 = (tix & 7) * 32;
    int tid = threadIdx.x;

    const u16*   aplane = g_attnh + ((size_t)bc << 16);
    const float* lplane = g_local + ((size_t)bc << 16);

    for (int idx = tid; idx < 46 * 46; idx += 256) {
        int r  = idx / 46;
        int cc = idx - r * 46;
        int gh = ty0 - 6 + r;
        int gw = tx0 - 6 + cc;
        float v = 0.f;
        if (gh >= 0 && gh < 256 && gw >= 0 && gw < 256) v = f16f(aplane[gh * 256 + gw]);
        attnS[r][cc] = v;
    }
    if (tid < 64) ws[tid] = w_dw[c * 64 + tid];
    __syncthreads();

    for (int idx = tid; idx < 39 * 39; idx += 256) {
        int r  = idx / 39;
        int cc = idx - r * 39;
        int gh = ty0 - 3 + r;
        int gw = tx0 - 3 + cc;
        float v = 0.f;
        if (gh >= 0 && gh <= 256 && gw >= 0 && gw <= 256) {
            int gh2 = (gh == 256) ? 254 : gh;
            int gw2 = (gw == 256) ? 254 : gw;
            int co = gw2 - (tx0 - 6);
            float vs = 0.f;
#pragma unroll
            for (int tt2 = gh2 - 3; tt2 <= gh2 + 4; ++tt2) {
                if (tt2 >= 0 && tt2 <= 256) {
                    int tt = (tt2 == 256) ? 254 : tt2;
                    vs += attnS[tt - (ty0 - 6)][co];
                }
            }
            int ro = gh2 - (ty0 - 6);
            float hs = 0.f;
#pragma unroll
            for (int ss2 = gw2 - 3; ss2 <= gw2 + 4; ++ss2) {
                if (ss2 >= 0 && ss2 <= 256) {
                    int ss = (ss2 == 256) ? 254 : ss2;
                    hs += attnS[ro][ss - (tx0 - 6)];
                }
            }
            v = (vs + hs) * 0.125f + lplane[gh2 * 256 + gw2];
        }
        midS[r][cc] = v;
    }
    __syncthreads();

    int lw  = tid & 31;
    int lh0 = (tid >> 5) * 4;
    float acc[4] = {0.f, 0.f, 0.f, 0.f};
#pragma unroll
    for (int j = 0; j < 8; ++j) {
        float wcol[8];
#pragma unroll
        for (int i = 0; i < 8; ++i) wcol[i] = ws[i * 8 + j];
#pragma unroll
        for (int r = 0; r < 11; ++r) {
            float v = midS[lh0 + r][lw + j];
#pragma unroll
            for (int a = 0; a < 4; ++a) {
                int i = r - a;
                if (i >= 0 && i < 8) acc[a] += v * wcol[i];
            }
        }
    }
    float ip = g_invp[c];
    float bb = g_biasp[c];
#pragma unroll
    for (int a = 0; a < 4; ++a) {
        int h = ty0 + lh0 + a;
        float r = acc[a] * ip + bb;
        size_t idx = ((size_t)bc << 16) + h * 256 + tx0 + lw;
        g_dwh[idx] = h16(r);
    }
}

// ---------------------------------------------------------------------------
// Launch
// ---------------------------------------------------------------------------
extern "C" void kernel_launch(void* const* d_in, const int* in_sizes, int n_in,
                              void* d_out, int out_size)
{
    const float* x    = (const float*)d_in[0];
    const float* y    = (const float*)d_in[1];
    const float* wqkv = (const float*)d_in[2];
    const float* wl1  = (const float*)d_in[3];
    const float* g1   = (const float*)d_in[4];
    const float* b1   = (const float*)d_in[5];
    const float* m1   = (const float*)d_in[6];
    const float* v1   = (const float*)d_in[7];
    const float* wl2  = (const float*)d_in[8];
    const float* g2   = (const float*)d_in[9];
    const float* b2   = (const float*)d_in[10];
    const float* m2   = (const float*)d_in[11];
    const float* v2   = (const float*)d_in[12];
    const float* wdw  = (const float*)d_in[13];
    const float* gp   = (const float*)d_in[14];
    const float* bp   = (const float*)d_in[15];
    const float* mp   = (const float*)d_in[16];
    const float* vp   = (const float*)d_in[17];
    const float* wpw  = (const float*)d_in[18];
    const float* rpb  = (const float*)d_in[19];
    float* out = (float*)d_out;

    prep_kernel<<<1, 256>>>(g1, b1, m1, v1, g2, b2, m2, v2, gp, bp, mp, vp);
    cvt_wqkv<<<768, 256>>>(wqkv);
    cvt_wpw<<<256, 256>>>(wpw);
    cvt_wlocal<<<2560, 256>>>(wl1, wl2);
    cvt_x<<<32768, 256>>>(x);
    cvt_y<<<32768, 256>>>(y);

    // local branch (K=2560, 1-pass fp16) -> g_local
    gemm_local_f16<<<dim3(2, 1024), 256>>>();

    // qkv (M=768, K=256, 1-pass fp16) -> g_qkvh (fp16, window-major)
    gemm_aligned<<<dim3(6, 1024), 256>>>(nullptr, 768, 256, 0);

    // tensor-core attention (4 window-heads per block) -> g_attnh (fp16)
    attn_mma<<<dim3(512, 16), 128>>>(rpb);

    // fused pools + depthwise conv + BN -> g_dwh (fp16)
    dwpool_kernel<<<dim3(64, 512), 256>>>(wdw);

    // pointwise (M=256, K=256, 1-pass fp16) -> out
    gemm_aligned<<<dim3(2, 1024), 256>>>(out, 256, 256, 1);
}